// round 6
// baseline (speedup 1.0000x reference)
#include <cuda_runtime.h>
#include <cuda_fp16.h>
#include <math.h>
#include <stdint.h>

#define NT   8192
#define DD   256
#define FF   8
#define DFE  64
#define DIN  320
#define DR   256
#define EE   8
#define DH   512

// ---------------- device-global scratch ----------------
__device__ __align__(16) float g_x[NT * DIN];
__device__ int                 g_cnt[EE];
__device__ int                 g_tok[EE * NT];
__device__ float               g_w[EE * NT];
__device__ __align__(16) float g_part[2 * NT * DD];
__device__ __align__(16) __half g_xh[NT * DIN];     // fp16 hi of x
__device__ __align__(16) __half g_xl[NT * DIN];     // fp16 lo of x
__device__ __align__(16) __half g_heh[2 * NT * DH]; // fp16 hi of he
__device__ __align__(16) __half g_hel[2 * NT * DH]; // fp16 lo of he
// pre-transposed n-major fp16 weights: B1 [e][kc=5][n=512][k=64], B2 [e][kc=8][n=256][k=64]
__device__ __align__(16) __half g_B1[EE * 5 * 512 * 64];
__device__ __align__(16) __half g_B2[EE * 8 * 256 * 64];

// ---------------- helpers ----------------
__device__ __forceinline__ float gelu_tanh(float v) {
    float u = 0.7978845608028654f * (v + 0.044715f * v * v * v);
    return 0.5f * v * (1.0f + tanhf(u));
}
__device__ __forceinline__ float gelu_fast(float v) {
    float u = 0.7978845608028654f * (v + 0.044715f * v * v * v);
    return v / (1.0f + __expf(-2.0f * u));
}
__device__ __forceinline__ uint32_t smem_u32(const void* p) {
    uint32_t a;
    asm("{ .reg .u64 t; cvta.to.shared.u64 t, %1; cvt.u32.u64 %0, t; }" : "=r"(a) : "l"(p));
    return a;
}
__device__ __forceinline__ void mma_f16(float* d, const uint32_t* a, const uint32_t* b) {
    asm volatile(
        "mma.sync.aligned.m16n8k16.row.col.f32.f16.f16.f32 "
        "{%0,%1,%2,%3}, {%4,%5,%6,%7}, {%8,%9}, {%0,%1,%2,%3};"
        : "+f"(d[0]), "+f"(d[1]), "+f"(d[2]), "+f"(d[3])
        : "r"(a[0]), "r"(a[1]), "r"(a[2]), "r"(a[3]), "r"(b[0]), "r"(b[1]));
}
__device__ __forceinline__ void ldsm_x4(uint32_t* r, uint32_t a) {
    asm volatile("ldmatrix.sync.aligned.m8n8.x4.shared.b16 {%0,%1,%2,%3}, [%4];"
        : "=r"(r[0]), "=r"(r[1]), "=r"(r[2]), "=r"(r[3]) : "r"(a));
}
__device__ __forceinline__ void cp16(uint32_t dst, const void* src) {
    asm volatile("cp.async.cg.shared.global [%0], [%1], 16;" :: "r"(dst), "l"(src));
}
__device__ __forceinline__ void cp_commit() {
    asm volatile("cp.async.commit_group;" ::: "memory");
}
__device__ __forceinline__ void cp_wait1() {
    asm volatile("cp.async.wait_group 1;" ::: "memory");
}
__device__ __forceinline__ void cp_wait0() {
    asm volatile("cp.async.wait_group 0;" ::: "memory");
}

// ---------------- K0: reset counters ----------------
__global__ void k_init() {
    if (threadIdx.x < EE) g_cnt[threadIdx.x] = 0;
}

// ---------------- K1: x = concat(hidden, feat @ W_feat + b_feat) + fp16 splits ------
__global__ void k_build_x(const float* __restrict__ hidden,
                          const float* __restrict__ feat,
                          const float* __restrict__ Wf,
                          const float* __restrict__ bf) {
    int tok = blockIdx.x;
    int t = threadIdx.x;
    float v;
    if (t < DD) {
        v = hidden[tok * DD + t];
    } else {
        int j = t - DD;
        float acc = bf[j];
#pragma unroll
        for (int k = 0; k < FF; k++) acc += feat[tok * FF + k] * Wf[k * DFE + j];
        v = acc;
    }
    g_x[tok * DIN + t] = v;
    __half h = __float2half_rn(v);
    g_xh[tok * DIN + t] = h;
    g_xl[tok * DIN + t] = __float2half_rn(v - __half2float(h));
}

// ---------------- prep: transpose expert weights to n-major fp16 ----------------
__global__ void k_prep_w1(const float* __restrict__ We1) {
    __shared__ float tile[64][65];
    int e = blockIdx.z, kc = blockIdx.y, hb = blockIdx.x;
    int tid = threadIdx.x;
#pragma unroll
    for (int i = 0; i < 16; i++) {
        int li = i * 256 + tid;
        int ki = li >> 6, hi = li & 63;
        tile[ki][hi] = We1[((size_t)e * DIN + kc * 64 + ki) * DH + hb * 64 + hi];
    }
    __syncthreads();
#pragma unroll
    for (int i = 0; i < 16; i++) {
        int li = i * 256 + tid;
        int kk = li & 63, hr = li >> 6;
        size_t dst = (((size_t)(e * 5 + kc) * 512) + hb * 64 + hr) * 64 + kk;
        g_B1[dst] = __float2half_rn(tile[kk][hr]);
    }
}

__global__ void k_prep_w2(const float* __restrict__ We2) {
    __shared__ float tile[64][65];
    int e = blockIdx.z, kc = blockIdx.y, ob = blockIdx.x;
    int tid = threadIdx.x;
#pragma unroll
    for (int i = 0; i < 16; i++) {
        int li = i * 256 + tid;
        int ki = li >> 6, oi = li & 63;
        tile[ki][oi] = We2[((size_t)e * DH + kc * 64 + ki) * DD + ob * 64 + oi];
    }
    __syncthreads();
#pragma unroll
    for (int i = 0; i < 16; i++) {
        int li = i * 256 + tid;
        int kk = li & 63, orr = li >> 6;
        size_t dst = (((size_t)(e * 8 + kc) * 256) + ob * 64 + orr) * 64 + kk;
        g_B2[dst] = __float2half_rn(tile[kk][orr]);
    }
}

// ---------------- K2: router (logit-exact fp32 SIMT) ----------------
#define R_SMEM_FLOATS (320 * 33 + 32 * 256)
__global__ __launch_bounds__(256, 2) void k_router(
    const float* __restrict__ Wr1, const float* __restrict__ br1,
    const float* __restrict__ Wr2, const float* __restrict__ br2,
    float* __restrict__ out) {
    extern __shared__ float sm[];
    float* xT  = sm;
    float* wch = sm + 320 * 33;
    float* hrT = sm;
    float* ws2 = wch;
    float* lg  = wch + 2048;

    int tid  = threadIdx.x;
    int base = blockIdx.x * 32;

    for (int idx = tid; idx < 32 * DIN; idx += 256) {
        int r = idx / DIN;
        int k = idx - r * DIN;
        xT[k * 33 + r] = g_x[(base + r) * DIN + k];
    }

    int tg = tid >> 5;
    int cg = tid & 31;

    float acc[2][4][4];
#pragma unroll
    for (int m = 0; m < 2; m++)
#pragma unroll
        for (int tt = 0; tt < 4; tt++)
#pragma unroll
            for (int j = 0; j < 4; j++) acc[m][tt][j] = 0.f;

    for (int kc = 0; kc < DIN; kc += 32) {
#pragma unroll
        for (int i = 0; i < 32; i++) {
            int idx = tid + i * 256;
            int kk = idx >> 8;
            int c  = idx & 255;
            wch[kk * 256 + c] = Wr1[(kc + kk) * DR + c];
        }
        __syncthreads();
#pragma unroll 2
        for (int k = 0; k < 32; k++) {
            float xv[4];
#pragma unroll
            for (int tt = 0; tt < 4; tt++) xv[tt] = xT[(kc + k) * 33 + 4 * tg + tt];
#pragma unroll
            for (int m = 0; m < 2; m++) {
                float4 wq = *(const float4*)&wch[k * 256 + 128 * m + 4 * cg];
#pragma unroll
                for (int tt = 0; tt < 4; tt++) {
                    acc[m][tt][0] += xv[tt] * wq.x;
                    acc[m][tt][1] += xv[tt] * wq.y;
                    acc[m][tt][2] += xv[tt] * wq.z;
                    acc[m][tt][3] += xv[tt] * wq.w;
                }
            }
        }
        __syncthreads();
    }

#pragma unroll
    for (int m = 0; m < 2; m++)
#pragma unroll
        for (int j = 0; j < 4; j++) {
            int col = 4 * cg + 128 * m + j;
            float b = br1[col];
#pragma unroll
            for (int tt = 0; tt < 4; tt++)
                hrT[col * 33 + 4 * tg + tt] = gelu_tanh(acc[m][tt][j] + b);
        }
    for (int idx = tid; idx < DR * EE; idx += 256) ws2[idx] = Wr2[idx];
    __syncthreads();

    {
        int e = tid >> 5;
        int r = tid & 31;
        float lacc = br2[e];
#pragma unroll 4
        for (int k = 0; k < DR; k++) lacc += hrT[k * 33 + r] * ws2[k * EE + e];
        lg[r * EE + e] = lacc;
        out[(size_t)NT * DD + (size_t)NT * EE + (size_t)(base + r) * EE + e] = lacc;
    }
    __syncthreads();

    if (tid < 32) {
        int r = tid;
        int gtok = base + r;
        float v[EE];
#pragma unroll
        for (int e = 0; e < EE; e++) v[e] = lg[r * EE + e];
        int i0 = 0;
#pragma unroll
        for (int e = 1; e < EE; e++)
            if (v[e] > v[i0]) i0 = e;
        int i1 = (i0 == 0) ? 1 : 0;
#pragma unroll
        for (int e = 0; e < EE; e++) {
            if (e == i0) continue;
            if (v[e] > v[i1]) i1 = e;
        }
        float t  = expf(v[i1] - v[i0]);
        float s  = 1.0f + t;
        float w0 = 1.0f / s;
        float w1 = t / s;
        float* gw = out + (size_t)NT * DD + (size_t)gtok * EE;
#pragma unroll
        for (int e = 0; e < EE; e++)
            gw[e] = (e == i0) ? w0 : ((e == i1) ? w1 : 0.0f);
        int p0 = atomicAdd(&g_cnt[i0], 1);
        g_tok[i0 * NT + p0] = gtok;
        g_w[i0 * NT + p0]   = w0;
        int p1 = atomicAdd(&g_cnt[i1], 1);
        g_tok[i1 * NT + p1] = gtok | (1 << 31);
        g_w[i1 * NT + p1]   = w1;
    }
}

// ---------------- HMMA expert kernels: fp16 2-term, cp.async double-buffer ----------------
// Per stage (55296 B): Ah[128x72h] Al[128x72h] B[128x72h], row stride 144 B.
#define BUF_BYTES 55296
#define EXP_SMEM  (2 * BUF_BYTES)

// layer 1: he = gelu(x @ We1 + b1), 20 chunks = nc(4) x kc(5)
__global__ __launch_bounds__(256, 2) void k_expert1(const float* __restrict__ be1) {
    int e = blockIdx.y;
    int cnt = g_cnt[e];
    int base = blockIdx.x * 128;
    if (base >= cnt) return;
    int nrows = min(128, cnt - base);

    extern __shared__ char smraw[];
    uint32_t smb = smem_u32(smraw);

    __shared__ int s_tok[128];
    __shared__ int s_dst[128];

    int tid = threadIdx.x, wid = tid >> 5, lane = tid & 31;
    for (int r = tid; r < 128; r += 256) {
        int rr = (r < nrows) ? r : 0;
        int ent = g_tok[e * NT + base + rr];
        int tok = ent & 0x7FFFFFFF;
        s_tok[r] = tok;
        s_dst[r] = (r < nrows) ? (int)((((unsigned)ent) >> 31) * NT + tok) : -1;
    }
    __syncthreads();

    int wm = wid & 3, wn = wid >> 2, lq = lane >> 2, lr = lane & 3;
    int srow = tid >> 3, su = tid & 7;
    uint32_t aoff = (uint32_t)((wm * 32 + (lane & 15)) * 144 + ((lane >> 4) << 4));
    uint32_t boff = (uint32_t)((wn * 64 + (lane & 15)) * 144 + ((lane >> 4) << 4));

    float acc[2][8][4];

    auto stage = [&](int c) {
        int nc = c / 5, kc = c - nc * 5;
        uint32_t b = smb + (uint32_t)(c & 1) * BUF_BYTES;
        const char* B1 = (const char*)(g_B1 + (((size_t)(e * 5 + kc) * 512) + nc * 128) * 64);
#pragma unroll
        for (int i4 = 0; i4 < 4; i4++) {
            int r = srow + i4 * 32;
            uint32_t d = b + (uint32_t)(r * 144 + su * 16);
            size_t sb = (size_t)s_tok[r] * DIN + kc * 64;
            cp16(d,         (const char*)(g_xh + sb) + su * 16);
            cp16(d + 18432, (const char*)(g_xl + sb) + su * 16);
            cp16(d + 36864, B1 + r * 128 + su * 16);
        }
        cp_commit();
    };

    stage(0);
    for (int c = 0; c < 20; c++) {
        int nc = c / 5, kc = c - nc * 5;
        if (c + 1 < 20) { stage(c + 1); cp_wait1(); } else { cp_wait0(); }
        __syncthreads();
        uint32_t b = smb + (uint32_t)(c & 1) * BUF_BYTES;

        if (kc == 0) {
#pragma unroll
            for (int mt = 0; mt < 2; mt++)
#pragma unroll
                for (int nt = 0; nt < 8; nt++)
#pragma unroll
                    for (int j = 0; j < 4; j++) acc[mt][nt][j] = 0.f;
        }
#pragma unroll
        for (int s = 0; s < 4; s++) {
            uint32_t ah[2][4], al[2][4];
#pragma unroll
            for (int mt = 0; mt < 2; mt++) {
                uint32_t a = b + aoff + (uint32_t)(mt * 2304 + s * 32);
                ldsm_x4(ah[mt], a);
                ldsm_x4(al[mt], a + 18432);
            }
#pragma unroll
            for (int g = 0; g < 4; g++) {
                uint32_t bh[4];
                ldsm_x4(bh, b + 36864 + boff + (uint32_t)(g * 2304 + s * 32));
                uint32_t bhe[2] = {bh[0], bh[2]}, bho[2] = {bh[1], bh[3]};
#pragma unroll
                for (int mt = 0; mt < 2; mt++) {
                    mma_f16(acc[mt][2 * g],     ah[mt], bhe);
                    mma_f16(acc[mt][2 * g],     al[mt], bhe);
                    mma_f16(acc[mt][2 * g + 1], ah[mt], bho);
                    mma_f16(acc[mt][2 * g + 1], al[mt], bho);
                }
            }
        }

        if (kc == 4) {
            const float* b1 = be1 + e * DH + nc * 128;
#pragma unroll
            for (int mt = 0; mt < 2; mt++)
#pragma unroll
                for (int nt = 0; nt < 8; nt++) {
                    int col = wn * 64 + nt * 8 + lr * 2;
                    float bb0 = b1[col], bb1 = b1[col + 1];
#pragma unroll
                    for (int h = 0; h < 2; h++) {
                        int row = wm * 32 + mt * 16 + lq + h * 8;
                        int dst = s_dst[row];
                        if (dst >= 0) {
                            float v0 = gelu_fast(acc[mt][nt][2 * h]     + bb0);
                            float v1 = gelu_fast(acc[mt][nt][2 * h + 1] + bb1);
                            __half h0 = __float2half_rn(v0), h1 = __float2half_rn(v1);
                            __half l0 = __float2half_rn(v0 - __half2float(h0));
                            __half l1 = __float2half_rn(v1 - __half2float(h1));
                            uint32_t ph = (uint32_t)__half_as_ushort(h0) | ((uint32_t)__half_as_ushort(h1) << 16);
                            uint32_t pl = (uint32_t)__half_as_ushort(l0) | ((uint32_t)__half_as_ushort(l1) << 16);
                            size_t widx = ((size_t)dst * DH + nc * 128 + col) >> 1;
                            ((uint32_t*)g_heh)[widx] = ph;
                            ((uint32_t*)g_hel)[widx] = pl;
                        }
                    }
                }
        }
        __syncthreads();
    }
}

// layer 2: eo = he @ We2 + b2, gate-scaled; 16 chunks = nc(2) x kc(8)
__global__ __launch_bounds__(256, 2) void k_expert2(const float* __restrict__ be2) {
    int e = blockIdx.y;
    int cnt = g_cnt[e];
    int base = blockIdx.x * 128;
    if (base >= cnt) return;
    int nrows = min(128, cnt - base);

    extern __shared__ char smraw[];
    uint32_t smb = smem_u32(smraw);

    __shared__ int   s_row[128];
    __shared__ int   s_dst[128];
    __shared__ float s_w[128];

    int tid = threadIdx.x, wid = tid >> 5, lane = tid & 31;
    for (int r = tid; r < 128; r += 256) {
        int rr = (r < nrows) ? r : 0;
        int ent = g_tok[e * NT + base + rr];
        int tok = ent & 0x7FFFFFFF;
        int herow = (int)((((unsigned)ent) >> 31) * NT + tok);
        s_row[r] = herow;
        s_dst[r] = (r < nrows) ? herow : -1;
        s_w[r]   = g_w[e * NT + base + rr];
    }
    __syncthreads();

    int wm = wid & 3, wn = wid >> 2, lq = lane >> 2, lr = lane & 3;
    int srow = tid >> 3, su = tid & 7;
    uint32_t aoff = (uint32_t)((wm * 32 + (lane & 15)) * 144 + ((lane >> 4) << 4));
    uint32_t boff = (uint32_t)((wn * 64 + (lane & 15)) * 144 + ((lane >> 4) << 4));

    float acc[2][8][4];

    auto stage = [&](int c) {
        int nc = c >> 3, kc = c & 7;
        uint32_t b = smb + (uint32_t)(c & 1) * BUF_BYTES;
        const char* B2 = (const char*)(g_B2 + (((size_t)(e * 8 + kc) * 256) + nc * 128) * 64);
#pragma unroll
        for (int i4 = 0; i4 < 4; i4++) {
            int r = srow + i4 * 32;
            uint32_t d = b + (uint32_t)(r * 144 + su * 16);
            size_t sb = (size_t)s_row[r] * DH + kc * 64;
            cp16(d,         (const char*)(g_heh + sb) + su * 16);
            cp16(d + 18432, (const char*)(g_hel + sb) + su * 16);
            cp16(d + 36864, B2 + r * 128 + su * 16);
        }
        cp_commit();
    };

    stage(0);
    for (int c = 0; c < 16; c++) {
        int nc = c >> 3, kc = c & 7;
        if (c + 1 < 16) { stage(c + 1); cp_wait1(); } else { cp_wait0(); }
        __syncthreads();
        uint32_t b = smb + (uint32_t)(c & 1) * BUF_BYTES;

        if (kc == 0) {
#pragma unroll
            for (int mt = 0; mt < 2; mt++)
#pragma unroll
                for (int nt = 0; nt < 8; nt++)
#pragma unroll
                    for (int j = 0; j < 4; j++) acc[mt][nt][j] = 0.f;
        }
#pragma unroll
        for (int s = 0; s < 4; s++) {
            uint32_t ah[2][4], al[2][4];
#pragma unroll
            for (int mt = 0; mt < 2; mt++) {
                uint32_t a = b + aoff + (uint32_t)(mt * 2304 + s * 32);
                ldsm_x4(ah[mt], a);
                ldsm_x4(al[mt], a + 18432);
            }
#pragma unroll
            for (int g = 0; g < 4; g++) {
                uint32_t bh[4];
                ldsm_x4(bh, b + 36864 + boff + (uint32_t)(g * 2304 + s * 32));
                uint32_t bhe[2] = {bh[0], bh[2]}, bho[2] = {bh[1], bh[3]};
#pragma unroll
                for (int mt = 0; mt < 2; mt++) {
                    mma_f16(acc[mt][2 * g],     ah[mt], bhe);
                    mma_f16(acc[mt][2 * g],     al[mt], bhe);
                    mma_f16(acc[mt][2 * g + 1], ah[mt], bho);
                    mma_f16(acc[mt][2 * g + 1], al[mt], bho);
                }
            }
        }

        if (kc == 7) {
            const float* b2 = be2 + e * DD + nc * 128;
#pragma unroll
            for (int mt = 0; mt < 2; mt++)
#pragma unroll
                for (int nt = 0; nt < 8; nt++) {
                    int col = wn * 64 + nt * 8 + lr * 2;
                    float bb0 = b2[col], bb1 = b2[col + 1];
#pragma unroll
                    for (int h = 0; h < 2; h++) {
                        int row = wm * 32 + mt * 16 + lq + h * 8;
                        int dst = s_dst[row];
                        if (dst >= 0) {
                            float wgt = s_w[row];
                            float2 o;
                            o.x = wgt * (acc[mt][nt][2 * h]     + bb0);
                            o.y = wgt * (acc[mt][nt][2 * h + 1] + bb1);
                            *(float2*)&g_part[(size_t)dst * DD + nc * 128 + col] = o;
                        }
                    }
                }
        }
        __syncthreads();
    }
}

// ---------------- K4: combine slot partials ----------------
__global__ void k_combine(float* __restrict__ out) {
    int i = blockIdx.x * blockDim.x + threadIdx.x;
    const float4* p0 = (const float4*)g_part;
    const float4* p1 = (const float4*)(g_part + (size_t)NT * DD);
    float4 a = p0[i], b = p1[i];
    float4 r;
    r.x = a.x + b.x; r.y = a.y + b.y; r.z = a.z + b.z; r.w = a.w + b.w;
    ((float4*)out)[i] = r;
}

// ---------------- launch ----------------
extern "C" void kernel_launch(void* const* d_in, const int* in_sizes, int n_in,
                              void* d_out, int out_size) {
    const float* hidden = (const float*)d_in[0];
    const float* feat   = (const float*)d_in[1];
    const float* Wf     = (const float*)d_in[2];
    const float* bf     = (const float*)d_in[3];
    const float* Wr1    = (const float*)d_in[4];
    const float* br1    = (const float*)d_in[5];
    const float* Wr2    = (const float*)d_in[6];
    const float* br2    = (const float*)d_in[7];
    const float* We1    = (const float*)d_in[8];
    const float* be1    = (const float*)d_in[9];
    const float* We2    = (const float*)d_in[10];
    const float* be2    = (const float*)d_in[11];
    float* out = (float*)d_out;

    const int r_smem = R_SMEM_FLOATS * 4;
    cudaFuncSetAttribute(k_router,  cudaFuncAttributeMaxDynamicSharedMemorySize, r_smem);
    cudaFuncSetAttribute(k_expert1, cudaFuncAttributeMaxDynamicSharedMemorySize, EXP_SMEM);
    cudaFuncSetAttribute(k_expert2, cudaFuncAttributeMaxDynamicSharedMemorySize, EXP_SMEM);

    k_init<<<1, 32>>>();
    k_build_x<<<NT, DIN>>>(hidden, feat, Wf, bf);
    k_prep_w1<<<dim3(8, 5, EE), 256>>>(We1);
    k_prep_w2<<<dim3(4, 8, EE), 256>>>(We2);
    k_router<<<NT / 32, 256, r_smem>>>(Wr1, br1, Wr2, br2, out);
    k_expert1<<<dim3(64, EE), 256, EXP_SMEM>>>(be1);
    k_expert2<<<dim3(64, EE), 256, EXP_SMEM>>>(be2);
    k_combine<<<(NT * DD / 4) / 256, 256>>>(out);
}

// round 7
// speedup vs baseline: 1.1110x; 1.1110x over previous
#include <cuda_runtime.h>
#include <cuda_fp16.h>
#include <math.h>
#include <stdint.h>

#define NT   8192
#define DD   256
#define FF   8
#define DFE  64
#define DIN  320
#define DR   256
#define EE   8
#define DH   512

// ---------------- device-global scratch ----------------
__device__ __align__(16) float g_x[NT * DIN];
__device__ int                 g_cnt[EE];
__device__ int                 g_tok[EE * NT];
__device__ float               g_w[EE * NT];
__device__ __align__(16) float g_part[2 * NT * DD];
__device__ __align__(16) __half g_xh[NT * DIN];     // fp16 hi of x
__device__ __align__(16) __half g_xl[NT * DIN];     // fp16 lo of x
__device__ __align__(16) __half g_heh[2 * NT * DH]; // fp16 hi of he
__device__ __align__(16) __half g_hel[2 * NT * DH]; // fp16 lo of he
// pre-transposed n-major fp16 weights: B1 [e][kc=5][n=512][k=64], B2 [e][kc=8][n=256][k=64]
__device__ __align__(16) __half g_B1[EE * 5 * 512 * 64];
__device__ __align__(16) __half g_B2[EE * 8 * 256 * 64];

// ---------------- helpers ----------------
__device__ __forceinline__ float gelu_tanh(float v) {
    float u = 0.7978845608028654f * (v + 0.044715f * v * v * v);
    return 0.5f * v * (1.0f + tanhf(u));
}
__device__ __forceinline__ float gelu_fast(float v) {
    float u = 0.7978845608028654f * (v + 0.044715f * v * v * v);
    return v / (1.0f + __expf(-2.0f * u));
}
__device__ __forceinline__ uint32_t smem_u32(const void* p) {
    uint32_t a;
    asm("{ .reg .u64 t; cvta.to.shared.u64 t, %1; cvt.u32.u64 %0, t; }" : "=r"(a) : "l"(p));
    return a;
}
__device__ __forceinline__ void mma_f16(float* d, const uint32_t* a, const uint32_t* b) {
    asm volatile(
        "mma.sync.aligned.m16n8k16.row.col.f32.f16.f16.f32 "
        "{%0,%1,%2,%3}, {%4,%5,%6,%7}, {%8,%9}, {%0,%1,%2,%3};"
        : "+f"(d[0]), "+f"(d[1]), "+f"(d[2]), "+f"(d[3])
        : "r"(a[0]), "r"(a[1]), "r"(a[2]), "r"(a[3]), "r"(b[0]), "r"(b[1]));
}
__device__ __forceinline__ void ldsm_x4(uint32_t* r, uint32_t a) {
    asm volatile("ldmatrix.sync.aligned.m8n8.x4.shared.b16 {%0,%1,%2,%3}, [%4];"
        : "=r"(r[0]), "=r"(r[1]), "=r"(r[2]), "=r"(r[3]) : "r"(a));
}
__device__ __forceinline__ void cp16(uint32_t dst, const void* src) {
    asm volatile("cp.async.cg.shared.global [%0], [%1], 16;" :: "r"(dst), "l"(src));
}
__device__ __forceinline__ void cp_commit() {
    asm volatile("cp.async.commit_group;" ::: "memory");
}
__device__ __forceinline__ void cp_wait1() {
    asm volatile("cp.async.wait_group 1;" ::: "memory");
}
__device__ __forceinline__ void cp_wait0() {
    asm volatile("cp.async.wait_group 0;" ::: "memory");
}

// ---------------- K0: reset counters ----------------
__global__ void k_init() {
    if (threadIdx.x < EE) g_cnt[threadIdx.x] = 0;
}

// ---------------- K1: x = concat(hidden, feat @ W_feat + b_feat) + fp16 splits ------
__global__ void k_build_x(const float* __restrict__ hidden,
                          const float* __restrict__ feat,
                          const float* __restrict__ Wf,
                          const float* __restrict__ bf) {
    int tok = blockIdx.x;
    int t = threadIdx.x;
    float v;
    if (t < DD) {
        v = hidden[tok * DD + t];
    } else {
        int j = t - DD;
        float acc = bf[j];
#pragma unroll
        for (int k = 0; k < FF; k++) acc += feat[tok * FF + k] * Wf[k * DFE + j];
        v = acc;
    }
    g_x[tok * DIN + t] = v;
    __half h = __float2half_rn(v);
    g_xh[tok * DIN + t] = h;
    g_xl[tok * DIN + t] = __float2half_rn(v - __half2float(h));
}

// ---------------- prep: transpose expert weights to n-major fp16 ----------------
__global__ void k_prep_w1(const float* __restrict__ We1) {
    __shared__ float tile[64][65];
    int e = blockIdx.z, kc = blockIdx.y, hb = blockIdx.x;
    int tid = threadIdx.x;
#pragma unroll
    for (int i = 0; i < 16; i++) {
        int li = i * 256 + tid;
        int ki = li >> 6, hi = li & 63;
        tile[ki][hi] = We1[((size_t)e * DIN + kc * 64 + ki) * DH + hb * 64 + hi];
    }
    __syncthreads();
#pragma unroll
    for (int i = 0; i < 16; i++) {
        int li = i * 256 + tid;
        int kk = li & 63, hr = li >> 6;
        size_t dst = (((size_t)(e * 5 + kc) * 512) + hb * 64 + hr) * 64 + kk;
        g_B1[dst] = __float2half_rn(tile[kk][hr]);
    }
}

__global__ void k_prep_w2(const float* __restrict__ We2) {
    __shared__ float tile[64][65];
    int e = blockIdx.z, kc = blockIdx.y, ob = blockIdx.x;
    int tid = threadIdx.x;
#pragma unroll
    for (int i = 0; i < 16; i++) {
        int li = i * 256 + tid;
        int ki = li >> 6, oi = li & 63;
        tile[ki][oi] = We2[((size_t)e * DH + kc * 64 + ki) * DD + ob * 64 + oi];
    }
    __syncthreads();
#pragma unroll
    for (int i = 0; i < 16; i++) {
        int li = i * 256 + tid;
        int kk = li & 63, orr = li >> 6;
        size_t dst = (((size_t)(e * 8 + kc) * 256) + ob * 64 + orr) * 64 + kk;
        g_B2[dst] = __float2half_rn(tile[kk][orr]);
    }
}

// ---------------- K2: router (logit-exact fp32 SIMT) ----------------
#define R_SMEM_FLOATS (320 * 33 + 32 * 256)
__global__ __launch_bounds__(256, 2) void k_router(
    const float* __restrict__ Wr1, const float* __restrict__ br1,
    const float* __restrict__ Wr2, const float* __restrict__ br2,
    float* __restrict__ out) {
    extern __shared__ float sm[];
    float* xT  = sm;
    float* wch = sm + 320 * 33;
    float* hrT = sm;
    float* ws2 = wch;
    float* lg  = wch + 2048;

    int tid  = threadIdx.x;
    int base = blockIdx.x * 32;

    for (int idx = tid; idx < 32 * DIN; idx += 256) {
        int r = idx / DIN;
        int k = idx - r * DIN;
        xT[k * 33 + r] = g_x[(base + r) * DIN + k];
    }

    int tg = tid >> 5;
    int cg = tid & 31;

    float acc[2][4][4];
#pragma unroll
    for (int m = 0; m < 2; m++)
#pragma unroll
        for (int tt = 0; tt < 4; tt++)
#pragma unroll
            for (int j = 0; j < 4; j++) acc[m][tt][j] = 0.f;

    for (int kc = 0; kc < DIN; kc += 32) {
#pragma unroll
        for (int i = 0; i < 32; i++) {
            int idx = tid + i * 256;
            int kk = idx >> 8;
            int c  = idx & 255;
            wch[kk * 256 + c] = Wr1[(kc + kk) * DR + c];
        }
        __syncthreads();
#pragma unroll 2
        for (int k = 0; k < 32; k++) {
            float xv[4];
#pragma unroll
            for (int tt = 0; tt < 4; tt++) xv[tt] = xT[(kc + k) * 33 + 4 * tg + tt];
#pragma unroll
            for (int m = 0; m < 2; m++) {
                float4 wq = *(const float4*)&wch[k * 256 + 128 * m + 4 * cg];
#pragma unroll
                for (int tt = 0; tt < 4; tt++) {
                    acc[m][tt][0] += xv[tt] * wq.x;
                    acc[m][tt][1] += xv[tt] * wq.y;
                    acc[m][tt][2] += xv[tt] * wq.z;
                    acc[m][tt][3] += xv[tt] * wq.w;
                }
            }
        }
        __syncthreads();
    }

#pragma unroll
    for (int m = 0; m < 2; m++)
#pragma unroll
        for (int j = 0; j < 4; j++) {
            int col = 4 * cg + 128 * m + j;
            float b = br1[col];
#pragma unroll
            for (int tt = 0; tt < 4; tt++)
                hrT[col * 33 + 4 * tg + tt] = gelu_tanh(acc[m][tt][j] + b);
        }
    for (int idx = tid; idx < DR * EE; idx += 256) ws2[idx] = Wr2[idx];
    __syncthreads();

    {
        int e = tid >> 5;
        int r = tid & 31;
        float lacc = br2[e];
#pragma unroll 4
        for (int k = 0; k < DR; k++) lacc += hrT[k * 33 + r] * ws2[k * EE + e];
        lg[r * EE + e] = lacc;
        out[(size_t)NT * DD + (size_t)NT * EE + (size_t)(base + r) * EE + e] = lacc;
    }
    __syncthreads();

    if (tid < 32) {
        int r = tid;
        int gtok = base + r;
        float v[EE];
#pragma unroll
        for (int e = 0; e < EE; e++) v[e] = lg[r * EE + e];
        int i0 = 0;
#pragma unroll
        for (int e = 1; e < EE; e++)
            if (v[e] > v[i0]) i0 = e;
        int i1 = (i0 == 0) ? 1 : 0;
#pragma unroll
        for (int e = 0; e < EE; e++) {
            if (e == i0) continue;
            if (v[e] > v[i1]) i1 = e;
        }
        float t  = expf(v[i1] - v[i0]);
        float s  = 1.0f + t;
        float w0 = 1.0f / s;
        float w1 = t / s;
        float* gw = out + (size_t)NT * DD + (size_t)gtok * EE;
#pragma unroll
        for (int e = 0; e < EE; e++)
            gw[e] = (e == i0) ? w0 : ((e == i1) ? w1 : 0.0f);
        int p0 = atomicAdd(&g_cnt[i0], 1);
        g_tok[i0 * NT + p0] = gtok;
        g_w[i0 * NT + p0]   = w0;
        int p1 = atomicAdd(&g_cnt[i1], 1);
        g_tok[i1 * NT + p1] = gtok | (1 << 31);
        g_w[i1 * NT + p1]   = w1;
    }
}

// ---------------- HMMA expert kernels: fp16 2-term, cp.async double-buffer ----------------
// Per stage (55296 B): Ah[128x72h] Al[128x72h] B[128x72h], row stride 144 B.
#define BUF_BYTES 55296
#define EXP_SMEM  (2 * BUF_BYTES)

// layer 1: he = gelu(x @ We1 + b1), 20 chunks = nc(4) x kc(5)
__global__ __launch_bounds__(256, 1) void k_expert1(const float* __restrict__ be1) {
    int e = blockIdx.y;
    int cnt = g_cnt[e];
    int base = blockIdx.x * 128;
    if (base >= cnt) return;
    int nrows = min(128, cnt - base);

    extern __shared__ char smraw[];
    uint32_t smb = smem_u32(smraw);

    __shared__ int s_tok[128];
    __shared__ int s_dst[128];

    int tid = threadIdx.x, wid = tid >> 5, lane = tid & 31;
    for (int r = tid; r < 128; r += 256) {
        int rr = (r < nrows) ? r : 0;
        int ent = g_tok[e * NT + base + rr];
        int tok = ent & 0x7FFFFFFF;
        s_tok[r] = tok;
        s_dst[r] = (r < nrows) ? (int)((((unsigned)ent) >> 31) * NT + tok) : -1;
    }
    __syncthreads();

    int wm = wid & 3, wn = wid >> 2, lq = lane >> 2, lr = lane & 3;
    int srow = tid >> 3, su = tid & 7;
    uint32_t aoff = (uint32_t)((wm * 32 + (lane & 15)) * 144 + ((lane >> 4) << 4));
    uint32_t boff = (uint32_t)((wn * 64 + (lane & 15)) * 144 + ((lane >> 4) << 4));

    float acc[2][8][4];

    auto stage = [&](int c) {
        int nc = c / 5, kc = c - nc * 5;
        uint32_t b = smb + (uint32_t)(c & 1) * BUF_BYTES;
        const char* B1 = (const char*)(g_B1 + (((size_t)(e * 5 + kc) * 512) + nc * 128) * 64);
#pragma unroll
        for (int i4 = 0; i4 < 4; i4++) {
            int r = srow + i4 * 32;
            uint32_t d = b + (uint32_t)(r * 144 + su * 16);
            size_t sb = (size_t)s_tok[r] * DIN + kc * 64;
            cp16(d,         (const char*)(g_xh + sb) + su * 16);
            cp16(d + 18432, (const char*)(g_xl + sb) + su * 16);
            cp16(d + 36864, B1 + r * 128 + su * 16);
        }
        cp_commit();
    };

    stage(0);
    for (int c = 0; c < 20; c++) {
        int nc = c / 5, kc = c - nc * 5;
        if (c + 1 < 20) { stage(c + 1); cp_wait1(); } else { cp_wait0(); }
        __syncthreads();
        uint32_t b = smb + (uint32_t)(c & 1) * BUF_BYTES;

        if (kc == 0) {
#pragma unroll
            for (int mt = 0; mt < 2; mt++)
#pragma unroll
                for (int nt = 0; nt < 8; nt++)
#pragma unroll
                    for (int j = 0; j < 4; j++) acc[mt][nt][j] = 0.f;
        }
#pragma unroll
        for (int s = 0; s < 4; s++) {
            uint32_t ah[2][4], al[2][4];
#pragma unroll
            for (int mt = 0; mt < 2; mt++) {
                uint32_t a = b + aoff + (uint32_t)(mt * 2304 + s * 32);
                ldsm_x4(ah[mt], a);
                ldsm_x4(al[mt], a + 18432);
            }
#pragma unroll
            for (int g = 0; g < 4; g++) {
                uint32_t bh[4];
                ldsm_x4(bh, b + 36864 + boff + (uint32_t)(g * 2304 + s * 32));
                uint32_t bhe[2] = {bh[0], bh[2]}, bho[2] = {bh[1], bh[3]};
#pragma unroll
                for (int mt = 0; mt < 2; mt++) {
                    mma_f16(acc[mt][2 * g],     ah[mt], bhe);
                    mma_f16(acc[mt][2 * g],     al[mt], bhe);
                    mma_f16(acc[mt][2 * g + 1], ah[mt], bho);
                    mma_f16(acc[mt][2 * g + 1], al[mt], bho);
                }
            }
        }

        if (kc == 4) {
            const float* b1 = be1 + e * DH + nc * 128;
#pragma unroll
            for (int mt = 0; mt < 2; mt++)
#pragma unroll
                for (int nt = 0; nt < 8; nt++) {
                    int col = wn * 64 + nt * 8 + lr * 2;
                    float bb0 = b1[col], bb1 = b1[col + 1];
#pragma unroll
                    for (int h = 0; h < 2; h++) {
                        int row = wm * 32 + mt * 16 + lq + h * 8;
                        int dst = s_dst[row];
                        if (dst >= 0) {
                            float v0 = gelu_fast(acc[mt][nt][2 * h]     + bb0);
                            float v1 = gelu_fast(acc[mt][nt][2 * h + 1] + bb1);
                            __half h0 = __float2half_rn(v0), h1 = __float2half_rn(v1);
                            __half l0 = __float2half_rn(v0 - __half2float(h0));
                            __half l1 = __float2half_rn(v1 - __half2float(h1));
                            uint32_t ph = (uint32_t)__half_as_ushort(h0) | ((uint32_t)__half_as_ushort(h1) << 16);
                            uint32_t pl = (uint32_t)__half_as_ushort(l0) | ((uint32_t)__half_as_ushort(l1) << 16);
                            size_t widx = ((size_t)dst * DH + nc * 128 + col) >> 1;
                            ((uint32_t*)g_heh)[widx] = ph;
                            ((uint32_t*)g_hel)[widx] = pl;
                        }
                    }
                }
        }
        __syncthreads();
    }
}

// layer 2: eo = he @ We2 + b2, gate-scaled; 16 chunks = nc(2) x kc(8)
__global__ __launch_bounds__(256, 1) void k_expert2(const float* __restrict__ be2) {
    int e = blockIdx.y;
    int cnt = g_cnt[e];
    int base = blockIdx.x * 128;
    if (base >= cnt) return;
    int nrows = min(128, cnt - base);

    extern __shared__ char smraw[];
    uint32_t smb = smem_u32(smraw);

    __shared__ int   s_row[128];
    __shared__ int   s_dst[128];
    __shared__ float s_w[128];

    int tid = threadIdx.x, wid = tid >> 5, lane = tid & 31;
    for (int r = tid; r < 128; r += 256) {
        int rr = (r < nrows) ? r : 0;
        int ent = g_tok[e * NT + base + rr];
        int tok = ent & 0x7FFFFFFF;
        int herow = (int)((((unsigned)ent) >> 31) * NT + tok);
        s_row[r] = herow;
        s_dst[r] = (r < nrows) ? herow : -1;
        s_w[r]   = g_w[e * NT + base + rr];
    }
    __syncthreads();

    int wm = wid & 3, wn = wid >> 2, lq = lane >> 2, lr = lane & 3;
    int srow = tid >> 3, su = tid & 7;
    uint32_t aoff = (uint32_t)((wm * 32 + (lane & 15)) * 144 + ((lane >> 4) << 4));
    uint32_t boff = (uint32_t)((wn * 64 + (lane & 15)) * 144 + ((lane >> 4) << 4));

    float acc[2][8][4];

    auto stage = [&](int c) {
        int nc = c >> 3, kc = c & 7;
        uint32_t b = smb + (uint32_t)(c & 1) * BUF_BYTES;
        const char* B2 = (const char*)(g_B2 + (((size_t)(e * 8 + kc) * 256) + nc * 128) * 64);
#pragma unroll
        for (int i4 = 0; i4 < 4; i4++) {
            int r = srow + i4 * 32;
            uint32_t d = b + (uint32_t)(r * 144 + su * 16);
            size_t sb = (size_t)s_row[r] * DH + kc * 64;
            cp16(d,         (const char*)(g_heh + sb) + su * 16);
            cp16(d + 18432, (const char*)(g_hel + sb) + su * 16);
            cp16(d + 36864, B2 + r * 128 + su * 16);
        }
        cp_commit();
    };

    stage(0);
    for (int c = 0; c < 16; c++) {
        int nc = c >> 3, kc = c & 7;
        if (c + 1 < 16) { stage(c + 1); cp_wait1(); } else { cp_wait0(); }
        __syncthreads();
        uint32_t b = smb + (uint32_t)(c & 1) * BUF_BYTES;

        if (kc == 0) {
#pragma unroll
            for (int mt = 0; mt < 2; mt++)
#pragma unroll
                for (int nt = 0; nt < 8; nt++)
#pragma unroll
                    for (int j = 0; j < 4; j++) acc[mt][nt][j] = 0.f;
        }
#pragma unroll
        for (int s = 0; s < 4; s++) {
            uint32_t ah[2][4], al[2][4];
#pragma unroll
            for (int mt = 0; mt < 2; mt++) {
                uint32_t a = b + aoff + (uint32_t)(mt * 2304 + s * 32);
                ldsm_x4(ah[mt], a);
                ldsm_x4(al[mt], a + 18432);
            }
#pragma unroll
            for (int g = 0; g < 4; g++) {
                uint32_t bh[4];
                ldsm_x4(bh, b + 36864 + boff + (uint32_t)(g * 2304 + s * 32));
                uint32_t bhe[2] = {bh[0], bh[2]}, bho[2] = {bh[1], bh[3]};
#pragma unroll
                for (int mt = 0; mt < 2; mt++) {
                    mma_f16(acc[mt][2 * g],     ah[mt], bhe);
                    mma_f16(acc[mt][2 * g],     al[mt], bhe);
                    mma_f16(acc[mt][2 * g + 1], ah[mt], bho);
                    mma_f16(acc[mt][2 * g + 1], al[mt], bho);
                }
            }
        }

        if (kc == 7) {
            const float* b2 = be2 + e * DD + nc * 128;
#pragma unroll
            for (int mt = 0; mt < 2; mt++)
#pragma unroll
                for (int nt = 0; nt < 8; nt++) {
                    int col = wn * 64 + nt * 8 + lr * 2;
                    float bb0 = b2[col], bb1 = b2[col + 1];
#pragma unroll
                    for (int h = 0; h < 2; h++) {
                        int row = wm * 32 + mt * 16 + lq + h * 8;
                        int dst = s_dst[row];
                        if (dst >= 0) {
                            float wgt = s_w[row];
                            float2 o;
                            o.x = wgt * (acc[mt][nt][2 * h]     + bb0);
                            o.y = wgt * (acc[mt][nt][2 * h + 1] + bb1);
                            *(float2*)&g_part[(size_t)dst * DD + nc * 128 + col] = o;
                        }
                    }
                }
        }
        __syncthreads();
    }
}

// ---------------- K4: combine slot partials ----------------
__global__ void k_combine(float* __restrict__ out) {
    int i = blockIdx.x * blockDim.x + threadIdx.x;
    const float4* p0 = (const float4*)g_part;
    const float4* p1 = (const float4*)(g_part + (size_t)NT * DD);
    float4 a = p0[i], b = p1[i];
    float4 r;
    r.x = a.x + b.x; r.y = a.y + b.y; r.z = a.z + b.z; r.w = a.w + b.w;
    ((float4*)out)[i] = r;
}

// ---------------- launch ----------------
extern "C" void kernel_launch(void* const* d_in, const int* in_sizes, int n_in,
                              void* d_out, int out_size) {
    const float* hidden = (const float*)d_in[0];
    const float* feat   = (const float*)d_in[1];
    const float* Wf     = (const float*)d_in[2];
    const float* bf     = (const float*)d_in[3];
    const float* Wr1    = (const float*)d_in[4];
    const float* br1    = (const float*)d_in[5];
    const float* Wr2    = (const float*)d_in[6];
    const float* br2    = (const float*)d_in[7];
    const float* We1    = (const float*)d_in[8];
    const float* be1    = (const float*)d_in[9];
    const float* We2    = (const float*)d_in[10];
    const float* be2    = (const float*)d_in[11];
    float* out = (float*)d_out;

    const int r_smem = R_SMEM_FLOATS * 4;
    cudaFuncSetAttribute(k_router,  cudaFuncAttributeMaxDynamicSharedMemorySize, r_smem);
    cudaFuncSetAttribute(k_expert1, cudaFuncAttributeMaxDynamicSharedMemorySize, EXP_SMEM);
    cudaFuncSetAttribute(k_expert2, cudaFuncAttributeMaxDynamicSharedMemorySize, EXP_SMEM);

    k_init<<<1, 32>>>();
    k_build_x<<<NT, DIN>>>(hidden, feat, Wf, bf);
    k_prep_w1<<<dim3(8, 5, EE), 256>>>(We1);
    k_prep_w2<<<dim3(4, 8, EE), 256>>>(We2);
    k_router<<<NT / 32, 256, r_smem>>>(Wr1, br1, Wr2, br2, out);
    k_expert1<<<dim3(64, EE), 256, EXP_SMEM>>>(be1);
    k_expert2<<<dim3(64, EE), 256, EXP_SMEM>>>(be2);
    k_combine<<<(NT * DD / 4) / 256, 256>>>(out);
}

// round 8
// speedup vs baseline: 1.3151x; 1.1837x over previous
#include <cuda_runtime.h>
#include <cuda_fp16.h>
#include <math.h>
#include <stdint.h>

#define NT   8192
#define DD   256
#define FF   8
#define DFE  64
#define DIN  320
#define DR   256
#define EE   8
#define DH   512

// ---------------- device-global scratch ----------------
__device__ __align__(16) float g_x[NT * DIN];
__device__ int                 g_cnt[EE];
__device__ int                 g_tok[EE * NT];
__device__ float               g_w[EE * NT];
__device__ __align__(16) float g_part[2 * NT * DD];
__device__ __align__(16) __half g_xh[NT * DIN];
__device__ __align__(16) __half g_xl[NT * DIN];
__device__ __align__(16) __half g_heh[2 * NT * DH];
__device__ __align__(16) __half g_hel[2 * NT * DH];
// pre-transposed n-major fp16 weights: B1 [e][kc=5][n=512][k=64], B2 [e][kc=8][n=256][k=64]
__device__ __align__(16) __half g_B1[EE * 5 * 512 * 64];
__device__ __align__(16) __half g_B2[EE * 8 * 256 * 64];

// ---------------- helpers ----------------
__device__ __forceinline__ float gelu_tanh(float v) {
    float u = 0.7978845608028654f * (v + 0.044715f * v * v * v);
    return 0.5f * v * (1.0f + tanhf(u));
}
__device__ __forceinline__ float gelu_fast(float v) {
    float u = 0.7978845608028654f * (v + 0.044715f * v * v * v);
    return v / (1.0f + __expf(-2.0f * u));
}
__device__ __forceinline__ uint32_t smem_u32(const void* p) {
    uint32_t a;
    asm("{ .reg .u64 t; cvta.to.shared.u64 t, %1; cvt.u32.u64 %0, t; }" : "=r"(a) : "l"(p));
    return a;
}
__device__ __forceinline__ void mma_f16(float* d, const uint32_t* a, const uint32_t* b) {
    asm volatile(
        "mma.sync.aligned.m16n8k16.row.col.f32.f16.f16.f32 "
        "{%0,%1,%2,%3}, {%4,%5,%6,%7}, {%8,%9}, {%0,%1,%2,%3};"
        : "+f"(d[0]), "+f"(d[1]), "+f"(d[2]), "+f"(d[3])
        : "r"(a[0]), "r"(a[1]), "r"(a[2]), "r"(a[3]), "r"(b[0]), "r"(b[1]));
}
__device__ __forceinline__ void ldsm_x4(uint32_t* r, uint32_t a) {
    asm volatile("ldmatrix.sync.aligned.m8n8.x4.shared.b16 {%0,%1,%2,%3}, [%4];"
        : "=r"(r[0]), "=r"(r[1]), "=r"(r[2]), "=r"(r[3]) : "r"(a));
}
__device__ __forceinline__ void cp16(uint32_t dst, const void* src) {
    asm volatile("cp.async.cg.shared.global [%0], [%1], 16;" :: "r"(dst), "l"(src));
}
__device__ __forceinline__ void cp_commit() {
    asm volatile("cp.async.commit_group;" ::: "memory");
}
__device__ __forceinline__ void cp_wait1() {
    asm volatile("cp.async.wait_group 1;" ::: "memory");
}

// ---------------- K1: build x + splits (+ counter reset in block 0) ----------------
__global__ void k_build_x(const float* __restrict__ hidden,
                          const float* __restrict__ feat,
                          const float* __restrict__ Wf,
                          const float* __restrict__ bf) {
    int tok = blockIdx.x;
    int t = threadIdx.x;
    if (blockIdx.x == 0 && t < EE) g_cnt[t] = 0;
    float v;
    if (t < DD) {
        v = hidden[tok * DD + t];
    } else {
        int j = t - DD;
        float acc = bf[j];
#pragma unroll
        for (int k = 0; k < FF; k++) acc += feat[tok * FF + k] * Wf[k * DFE + j];
        v = acc;
    }
    g_x[tok * DIN + t] = v;
    __half h = __float2half_rn(v);
    g_xh[tok * DIN + t] = h;
    g_xl[tok * DIN + t] = __float2half_rn(v - __half2float(h));
}

// ---------------- K2: merged weight prep (transpose to n-major fp16) ----------------
__global__ void k_prep(const float* __restrict__ We1, const float* __restrict__ We2) {
    __shared__ float tile[64][65];
    int bx = blockIdx.x;
    int tid = threadIdx.x;
    if (bx < 320) {
        int hb = bx & 7, kc = (bx >> 3) % 5, e = bx / 40;
#pragma unroll
        for (int i = 0; i < 16; i++) {
            int li = i * 256 + tid;
            int ki = li >> 6, hi = li & 63;
            tile[ki][hi] = We1[((size_t)e * DIN + kc * 64 + ki) * DH + hb * 64 + hi];
        }
        __syncthreads();
#pragma unroll
        for (int i = 0; i < 16; i++) {
            int li = i * 256 + tid;
            int kk = li & 63, hr = li >> 6;
            size_t dst = (((size_t)(e * 5 + kc) * 512) + hb * 64 + hr) * 64 + kk;
            g_B1[dst] = __float2half_rn(tile[kk][hr]);
        }
    } else {
        int b2 = bx - 320;
        int ob = b2 & 3, kc = (b2 >> 2) & 7, e = b2 >> 5;
#pragma unroll
        for (int i = 0; i < 16; i++) {
            int li = i * 256 + tid;
            int ki = li >> 6, oi = li & 63;
            tile[ki][oi] = We2[((size_t)e * DH + kc * 64 + ki) * DD + ob * 64 + oi];
        }
        __syncthreads();
#pragma unroll
        for (int i = 0; i < 16; i++) {
            int li = i * 256 + tid;
            int kk = li & 63, orr = li >> 6;
            size_t dst = (((size_t)(e * 8 + kc) * 256) + ob * 64 + orr) * 64 + kk;
            g_B2[dst] = __float2half_rn(tile[kk][orr]);
        }
    }
}

// ---------------- K3: router (logit-exact fp32 SIMT) ----------------
#define R_SMEM_FLOATS (320 * 33 + 32 * 256)
__global__ __launch_bounds__(256, 2) void k_router(
    const float* __restrict__ Wr1, const float* __restrict__ br1,
    const float* __restrict__ Wr2, const float* __restrict__ br2,
    float* __restrict__ out) {
    extern __shared__ float sm[];
    float* xT  = sm;
    float* wch = sm + 320 * 33;
    float* hrT = sm;
    float* ws2 = wch;
    float* lg  = wch + 2048;

    int tid  = threadIdx.x;
    int base = blockIdx.x * 32;

    for (int idx = tid; idx < 32 * DIN; idx += 256) {
        int r = idx / DIN;
        int k = idx - r * DIN;
        xT[k * 33 + r] = g_x[(base + r) * DIN + k];
    }

    int tg = tid >> 5;
    int cg = tid & 31;

    float acc[2][4][4];
#pragma unroll
    for (int m = 0; m < 2; m++)
#pragma unroll
        for (int tt = 0; tt < 4; tt++)
#pragma unroll
            for (int j = 0; j < 4; j++) acc[m][tt][j] = 0.f;

    for (int kc = 0; kc < DIN; kc += 32) {
#pragma unroll
        for (int i = 0; i < 32; i++) {
            int idx = tid + i * 256;
            int kk = idx >> 8;
            int c  = idx & 255;
            wch[kk * 256 + c] = Wr1[(kc + kk) * DR + c];
        }
        __syncthreads();
#pragma unroll 2
        for (int k = 0; k < 32; k++) {
            float xv[4];
#pragma unroll
            for (int tt = 0; tt < 4; tt++) xv[tt] = xT[(kc + k) * 33 + 4 * tg + tt];
#pragma unroll
            for (int m = 0; m < 2; m++) {
                float4 wq = *(const float4*)&wch[k * 256 + 128 * m + 4 * cg];
#pragma unroll
                for (int tt = 0; tt < 4; tt++) {
                    acc[m][tt][0] += xv[tt] * wq.x;
                    acc[m][tt][1] += xv[tt] * wq.y;
                    acc[m][tt][2] += xv[tt] * wq.z;
                    acc[m][tt][3] += xv[tt] * wq.w;
                }
            }
        }
        __syncthreads();
    }

#pragma unroll
    for (int m = 0; m < 2; m++)
#pragma unroll
        for (int j = 0; j < 4; j++) {
            int col = 4 * cg + 128 * m + j;
            float b = br1[col];
#pragma unroll
            for (int tt = 0; tt < 4; tt++)
                hrT[col * 33 + 4 * tg + tt] = gelu_tanh(acc[m][tt][j] + b);
        }
    for (int idx = tid; idx < DR * EE; idx += 256) ws2[idx] = Wr2[idx];
    __syncthreads();

    {
        int e = tid >> 5;
        int r = tid & 31;
        float lacc = br2[e];
#pragma unroll 4
        for (int k = 0; k < DR; k++) lacc += hrT[k * 33 + r] * ws2[k * EE + e];
        lg[r * EE + e] = lacc;
        out[(size_t)NT * DD + (size_t)NT * EE + (size_t)(base + r) * EE + e] = lacc;
    }
    __syncthreads();

    if (tid < 32) {
        int r = tid;
        int gtok = base + r;
        float v[EE];
#pragma unroll
        for (int e = 0; e < EE; e++) v[e] = lg[r * EE + e];
        int i0 = 0;
#pragma unroll
        for (int e = 1; e < EE; e++)
            if (v[e] > v[i0]) i0 = e;
        int i1 = (i0 == 0) ? 1 : 0;
#pragma unroll
        for (int e = 0; e < EE; e++) {
            if (e == i0) continue;
            if (v[e] > v[i1]) i1 = e;
        }
        float t  = expf(v[i1] - v[i0]);
        float s  = 1.0f + t;
        float w0 = 1.0f / s;
        float w1 = t / s;
        float* gw = out + (size_t)NT * DD + (size_t)gtok * EE;
#pragma unroll
        for (int e = 0; e < EE; e++)
            gw[e] = (e == i0) ? w0 : ((e == i1) ? w1 : 0.0f);
        int p0 = atomicAdd(&g_cnt[i0], 1);
        g_tok[i0 * NT + p0] = gtok;
        g_w[i0 * NT + p0]   = w0;
        int p1 = atomicAdd(&g_cnt[i1], 1);
        g_tok[i1 * NT + p1] = gtok | (1 << 31);
        g_w[i1 * NT + p1]   = w1;
    }
}

// ---------------- expert layer 1: A resident, 3-stage B pipeline ----------------
// smem: A1h [0,83968) 128 rows x 656B (328 halves, 320 data + 8 pad)
//       A1l [83968,167936)
//       B   3 x 18432 at 167936 (128 n x 144B)
#define E1_AH   0
#define E1_AL   83968
#define E1_B    167936
#define E1_SMEM 223232

__global__ __launch_bounds__(256, 1) void k_expert1(const float* __restrict__ be1) {
    int e = blockIdx.y;
    int cnt = g_cnt[e];
    int base = blockIdx.x * 128;
    if (base >= cnt) return;
    int nrows = min(128, cnt - base);

    extern __shared__ char smraw[];
    uint32_t smb = smem_u32(smraw);

    __shared__ int s_tok[128];
    __shared__ int s_dst[128];

    int tid = threadIdx.x, wid = tid >> 5, lane = tid & 31;
    for (int r = tid; r < 128; r += 256) {
        int rr = (r < nrows) ? r : 0;
        int ent = g_tok[e * NT + base + rr];
        int tok = ent & 0x7FFFFFFF;
        s_tok[r] = tok;
        s_dst[r] = (r < nrows) ? (int)((((unsigned)ent) >> 31) * NT + tok) : -1;
    }
    __syncthreads();

    int wm = wid & 3, wn = wid >> 2, lq = lane >> 2, lr = lane & 3;

    // ---- prologue: stage full A (group 0), B0 (group 1), B1 (group 2) ----
    {
        int row = tid >> 1, half = tid & 1;
        const char* srch = (const char*)(g_xh + (size_t)s_tok[row] * DIN);
        const char* srcl = (const char*)(g_xl + (size_t)s_tok[row] * DIN);
        uint32_t dh = smb + E1_AH + (uint32_t)(row * 656 + half * 320);
        uint32_t dl = smb + E1_AL + (uint32_t)(row * 656 + half * 320);
#pragma unroll
        for (int j = 0; j < 20; j++) {
            int g = half * 20 + j;
            cp16(dh + j * 16, srch + g * 16);
            cp16(dl + j * 16, srcl + g * 16);
        }
        cp_commit();
    }
    int srow = tid >> 3, su = tid & 7;
    auto stageB = [&](int c) {
        int nc = c / 5, kc = c - nc * 5;
        uint32_t b = smb + E1_B + (uint32_t)(c % 3) * 18432;
        const char* B1 = (const char*)(g_B1 + (((size_t)(e * 5 + kc) * 512) + nc * 128) * 64);
#pragma unroll
        for (int i4 = 0; i4 < 4; i4++) {
            int r = srow + i4 * 32;
            cp16(b + (uint32_t)(r * 144 + su * 16), B1 + r * 128 + su * 16);
        }
        cp_commit();
    };
    stageB(0);
    stageB(1);

    uint32_t abase = smb + (uint32_t)((wm * 32 + (lane & 15)) * 656 + ((lane >> 4) << 4));
    uint32_t bbase = (uint32_t)((wn * 64 + (lane & 15)) * 144 + ((lane >> 4) << 4));

    float acc[2][8][4];
    for (int c = 0; c < 20; c++) {
        int nc = c / 5, kc = c - nc * 5;
        cp_wait1();
        __syncthreads();
        if (c + 2 < 20) stageB(c + 2); else cp_commit();

        if (kc == 0) {
#pragma unroll
            for (int mt = 0; mt < 2; mt++)
#pragma unroll
                for (int nt = 0; nt < 8; nt++)
#pragma unroll
                    for (int j = 0; j < 4; j++) acc[mt][nt][j] = 0.f;
        }
        uint32_t bb = smb + E1_B + (uint32_t)(c % 3) * 18432 + bbase;
        uint32_t ab = abase + (uint32_t)(kc * 128);
#pragma unroll
        for (int s = 0; s < 4; s++) {
            uint32_t ah[2][4], al[2][4];
#pragma unroll
            for (int mt = 0; mt < 2; mt++) {
                uint32_t a = ab + (uint32_t)(mt * 10496 + s * 32);
                ldsm_x4(ah[mt], a + E1_AH);
                ldsm_x4(al[mt], a + E1_AL);
            }
#pragma unroll
            for (int g = 0; g < 4; g++) {
                uint32_t bh[4];
                ldsm_x4(bh, bb + (uint32_t)(g * 2304 + s * 32));
                uint32_t bhe[2] = {bh[0], bh[2]}, bho[2] = {bh[1], bh[3]};
#pragma unroll
                for (int mt = 0; mt < 2; mt++) {
                    mma_f16(acc[mt][2 * g],     ah[mt], bhe);
                    mma_f16(acc[mt][2 * g],     al[mt], bhe);
                    mma_f16(acc[mt][2 * g + 1], ah[mt], bho);
                    mma_f16(acc[mt][2 * g + 1], al[mt], bho);
                }
            }
        }

        if (kc == 4) {
            const float* b1 = be1 + e * DH + nc * 128;
#pragma unroll
            for (int mt = 0; mt < 2; mt++)
#pragma unroll
                for (int nt = 0; nt < 8; nt++) {
                    int col = wn * 64 + nt * 8 + lr * 2;
                    float bb0 = b1[col], bb1 = b1[col + 1];
#pragma unroll
                    for (int h = 0; h < 2; h++) {
                        int row = wm * 32 + mt * 16 + lq + h * 8;
                        int dst = s_dst[row];
                        if (dst >= 0) {
                            float v0 = gelu_fast(acc[mt][nt][2 * h]     + bb0);
                            float v1 = gelu_fast(acc[mt][nt][2 * h + 1] + bb1);
                            __half h0 = __float2half_rn(v0), h1 = __float2half_rn(v1);
                            __half l0 = __float2half_rn(v0 - __half2float(h0));
                            __half l1 = __float2half_rn(v1 - __half2float(h1));
                            uint32_t ph = (uint32_t)__half_as_ushort(h0) | ((uint32_t)__half_as_ushort(h1) << 16);
                            uint32_t pl = (uint32_t)__half_as_ushort(l0) | ((uint32_t)__half_as_ushort(l1) << 16);
                            size_t widx = ((size_t)dst * DH + nc * 128 + col) >> 1;
                            ((uint32_t*)g_heh)[widx] = ph;
                            ((uint32_t*)g_hel)[widx] = pl;
                        }
                    }
                }
        }
    }
}

// ---------------- expert layer 2: A in K-halves, 3-stage B pipeline, dual-nc acc ----
// smem: A2h [0,67584) 128 rows x 528B (264 halves: 256 data + 8 pad)
//       A2l [67584,135168)
//       B   3 x 18432 at 135168
#define E2_AH   0
#define E2_AL   67584
#define E2_B    135168
#define E2_SMEM 190464

__global__ __launch_bounds__(256, 1) void k_expert2(const float* __restrict__ be2) {
    int e = blockIdx.y;
    int cnt = g_cnt[e];
    int base = blockIdx.x * 128;
    if (base >= cnt) return;
    int nrows = min(128, cnt - base);

    extern __shared__ char smraw[];
    uint32_t smb = smem_u32(smraw);

    __shared__ int   s_row[128];
    __shared__ int   s_dst[128];
    __shared__ float s_w[128];

    int tid = threadIdx.x, wid = tid >> 5, lane = tid & 31;
    for (int r = tid; r < 128; r += 256) {
        int rr = (r < nrows) ? r : 0;
        int ent = g_tok[e * NT + base + rr];
        int tok = ent & 0x7FFFFFFF;
        int herow = (int)((((unsigned)ent) >> 31) * NT + tok);
        s_row[r] = herow;
        s_dst[r] = (r < nrows) ? herow : -1;
        s_w[r]   = g_w[e * NT + base + rr];
    }
    __syncthreads();

    int wm = wid & 3, wn = wid >> 2, lq = lane >> 2, lr = lane & 3;
    int srow = tid >> 3, su = tid & 7;

    uint32_t abase = smb + (uint32_t)((wm * 32 + (lane & 15)) * 528 + ((lane >> 4) << 4));
    uint32_t bbase = (uint32_t)((wn * 64 + (lane & 15)) * 144 + ((lane >> 4) << 4));

    auto stageB = [&](int cgl) {       // cgl = kh*8 + j ; j: nc = j>>2, kcl = j&3
        int j = cgl & 7, kh = cgl >> 3;
        int nc = j >> 2, kcl = j & 3;
        int kc = kh * 4 + kcl;
        uint32_t b = smb + E2_B + (uint32_t)(cgl % 3) * 18432;
        const char* B2 = (const char*)(g_B2 + (((size_t)(e * 8 + kc) * 256) + nc * 128) * 64);
#pragma unroll
        for (int i4 = 0; i4 < 4; i4++) {
            int r = srow + i4 * 32;
            cp16(b + (uint32_t)(r * 144 + su * 16), B2 + r * 128 + su * 16);
        }
        cp_commit();
    };

    float acc[2][2][8][4];
#pragma unroll
    for (int nc = 0; nc < 2; nc++)
#pragma unroll
        for (int mt = 0; mt < 2; mt++)
#pragma unroll
            for (int nt = 0; nt < 8; nt++)
#pragma unroll
                for (int j = 0; j < 4; j++) acc[nc][mt][nt][j] = 0.f;

    for (int kh = 0; kh < 2; kh++) {
        // prologue: all warps done reading previous A half
        __syncthreads();
        {
            int row = tid >> 1, half = tid & 1;
            const char* srch = (const char*)(g_heh + (size_t)s_row[row] * DH + kh * 256);
            const char* srcl = (const char*)(g_hel + (size_t)s_row[row] * DH + kh * 256);
            uint32_t dh = smb + E2_AH + (uint32_t)(row * 528 + half * 256);
            uint32_t dl = smb + E2_AL + (uint32_t)(row * 528 + half * 256);
#pragma unroll
            for (int j = 0; j < 16; j++) {
                int g = half * 16 + j;
                cp16(dh + j * 16, srch + g * 16);
                cp16(dl + j * 16, srcl + g * 16);
            }
            cp_commit();
        }
        stageB(kh * 8);
        stageB(kh * 8 + 1);

        for (int j = 0; j < 8; j++) {
            int cgl = kh * 8 + j;
            int nc = j >> 2, kcl = j & 3;
            cp_wait1();
            __syncthreads();
            if (j + 2 < 8) stageB(cgl + 2); else cp_commit();

            uint32_t bb = smb + E2_B + (uint32_t)(cgl % 3) * 18432 + bbase;
            uint32_t ab = abase + (uint32_t)(kcl * 128);
#pragma unroll
            for (int s = 0; s < 4; s++) {
                uint32_t ah[2][4], al[2][4];
#pragma unroll
                for (int mt = 0; mt < 2; mt++) {
                    uint32_t a = ab + (uint32_t)(mt * 8448 + s * 32);
                    ldsm_x4(ah[mt], a + E2_AH);
                    ldsm_x4(al[mt], a + E2_AL);
                }
#pragma unroll
                for (int g = 0; g < 4; g++) {
                    uint32_t bh[4];
                    ldsm_x4(bh, bb + (uint32_t)(g * 2304 + s * 32));
                    uint32_t bhe[2] = {bh[0], bh[2]}, bho[2] = {bh[1], bh[3]};
#pragma unroll
                    for (int mt = 0; mt < 2; mt++) {
                        mma_f16(acc[nc][mt][2 * g],     ah[mt], bhe);
                        mma_f16(acc[nc][mt][2 * g],     al[mt], bhe);
                        mma_f16(acc[nc][mt][2 * g + 1], ah[mt], bho);
                        mma_f16(acc[nc][mt][2 * g + 1], al[mt], bho);
                    }
                }
            }
        }
    }

    // epilogue: gate-scaled bias add -> g_part
#pragma unroll
    for (int nc = 0; nc < 2; nc++) {
        const float* b2 = be2 + e * DD + nc * 128;
#pragma unroll
        for (int mt = 0; mt < 2; mt++)
#pragma unroll
            for (int nt = 0; nt < 8; nt++) {
                int col = wn * 64 + nt * 8 + lr * 2;
                float bb0 = b2[col], bb1 = b2[col + 1];
#pragma unroll
                for (int h = 0; h < 2; h++) {
                    int row = wm * 32 + mt * 16 + lq + h * 8;
                    int dst = s_dst[row];
                    if (dst >= 0) {
                        float wgt = s_w[row];
                        float2 o;
                        o.x = wgt * (acc[nc][mt][nt][2 * h]     + bb0);
                        o.y = wgt * (acc[nc][mt][nt][2 * h + 1] + bb1);
                        *(float2*)&g_part[(size_t)dst * DD + nc * 128 + col] = o;
                    }
                }
            }
    }
}

// ---------------- K4: combine slot partials ----------------
__global__ void k_combine(float* __restrict__ out) {
    int i = blockIdx.x * blockDim.x + threadIdx.x;
    const float4* p0 = (const float4*)g_part;
    const float4* p1 = (const float4*)(g_part + (size_t)NT * DD);
    float4 a = p0[i], b = p1[i];
    float4 r;
    r.x = a.x + b.x; r.y = a.y + b.y; r.z = a.z + b.z; r.w = a.w + b.w;
    ((float4*)out)[i] = r;
}

// ---------------- launch ----------------
extern "C" void kernel_launch(void* const* d_in, const int* in_sizes, int n_in,
                              void* d_out, int out_size) {
    const float* hidden = (const float*)d_in[0];
    const float* feat   = (const float*)d_in[1];
    const float* Wf     = (const float*)d_in[2];
    const float* bf     = (const float*)d_in[3];
    const float* Wr1    = (const float*)d_in[4];
    const float* br1    = (const float*)d_in[5];
    const float* Wr2    = (const float*)d_in[6];
    const float* br2    = (const float*)d_in[7];
    const float* We1    = (const float*)d_in[8];
    const float* be1    = (const float*)d_in[9];
    const float* We2    = (const float*)d_in[10];
    const float* be2    = (const float*)d_in[11];
    float* out = (float*)d_out;

    const int r_smem = R_SMEM_FLOATS * 4;
    cudaFuncSetAttribute(k_router,  cudaFuncAttributeMaxDynamicSharedMemorySize, r_smem);
    cudaFuncSetAttribute(k_expert1, cudaFuncAttributeMaxDynamicSharedMemorySize, E1_SMEM);
    cudaFuncSetAttribute(k_expert2, cudaFuncAttributeMaxDynamicSharedMemorySize, E2_SMEM);

    k_build_x<<<NT, DIN>>>(hidden, feat, Wf, bf);
    k_prep<<<576, 256>>>(We1, We2);
    k_router<<<NT / 32, 256, r_smem>>>(Wr1, br1, Wr2, br2, out);
    k_expert1<<<dim3(64, EE), 256, E1_SMEM>>>(be1);
    k_expert2<<<dim3(64, EE), 256, E2_SMEM>>>(be2);
    k_combine<<<(NT * DD / 4) / 256, 256>>>(out);
}

// round 9
// speedup vs baseline: 1.3176x; 1.0019x over previous
#include <cuda_runtime.h>
#include <cuda_fp16.h>
#include <math.h>
#include <stdint.h>

#define NT   8192
#define DD   256
#define FF   8
#define DFE  64
#define DIN  320
#define DR   256
#define EE   8
#define DH   512

// ---------------- device-global scratch ----------------
__device__ __align__(16) float g_x[NT * DIN];
__device__ int                 g_cnt[EE];
__device__ int                 g_tok[EE * NT];
__device__ float               g_w[EE * NT];
__device__ __align__(16) float g_part[2 * NT * DD];
__device__ __align__(16) __half g_xh[NT * DIN];
__device__ __align__(16) __half g_xl[NT * DIN];
__device__ __align__(16) __half g_heh[2 * NT * DH];
__device__ __align__(16) __half g_hel[2 * NT * DH];
// pre-transposed n-major fp16 weights: B1 [e][kc=5][n=512][k=64], B2 [e][kc=8][n=256][k=64]
__device__ __align__(16) __half g_B1[EE * 5 * 512 * 64];
__device__ __align__(16) __half g_B2[EE * 8 * 256 * 64];

// ---------------- helpers ----------------
__device__ __forceinline__ float gelu_tanh(float v) {
    float u = 0.7978845608028654f * (v + 0.044715f * v * v * v);
    return 0.5f * v * (1.0f + tanhf(u));
}
__device__ __forceinline__ float gelu_fast(float v) {
    float u = 0.7978845608028654f * (v + 0.044715f * v * v * v);
    return v / (1.0f + __expf(-2.0f * u));
}
__device__ __forceinline__ uint32_t smem_u32(const void* p) {
    uint32_t a;
    asm("{ .reg .u64 t; cvta.to.shared.u64 t, %1; cvt.u32.u64 %0, t; }" : "=r"(a) : "l"(p));
    return a;
}
__device__ __forceinline__ void mma_f16(float* d, const uint32_t* a, const uint32_t* b) {
    asm volatile(
        "mma.sync.aligned.m16n8k16.row.col.f32.f16.f16.f32 "
        "{%0,%1,%2,%3}, {%4,%5,%6,%7}, {%8,%9}, {%0,%1,%2,%3};"
        : "+f"(d[0]), "+f"(d[1]), "+f"(d[2]), "+f"(d[3])
        : "r"(a[0]), "r"(a[1]), "r"(a[2]), "r"(a[3]), "r"(b[0]), "r"(b[1]));
}
__device__ __forceinline__ void ldsm_x4(uint32_t* r, uint32_t a) {
    asm volatile("ldmatrix.sync.aligned.m8n8.x4.shared.b16 {%0,%1,%2,%3}, [%4];"
        : "=r"(r[0]), "=r"(r[1]), "=r"(r[2]), "=r"(r[3]) : "r"(a));
}
__device__ __forceinline__ void cp16(uint32_t dst, const void* src) {
    asm volatile("cp.async.cg.shared.global [%0], [%1], 16;" :: "r"(dst), "l"(src));
}
__device__ __forceinline__ void cp_commit() {
    asm volatile("cp.async.commit_group;" ::: "memory");
}
__device__ __forceinline__ void cp_wait1() {
    asm volatile("cp.async.wait_group 1;" ::: "memory");
}

// ---------------- K1: build x + splits (+ counter reset in block 0) ----------------
__global__ void k_build_x(const float* __restrict__ hidden,
                          const float* __restrict__ feat,
                          const float* __restrict__ Wf,
                          const float* __restrict__ bf) {
    int tok = blockIdx.x;
    int t = threadIdx.x;
    if (blockIdx.x == 0 && t < EE) g_cnt[t] = 0;
    float v;
    if (t < DD) {
        v = hidden[tok * DD + t];
    } else {
        int j = t - DD;
        float acc = bf[j];
#pragma unroll
        for (int k = 0; k < FF; k++) acc += feat[tok * FF + k] * Wf[k * DFE + j];
        v = acc;
    }
    g_x[tok * DIN + t] = v;
    __half h = __float2half_rn(v);
    g_xh[tok * DIN + t] = h;
    g_xl[tok * DIN + t] = __float2half_rn(v - __half2float(h));
}

// ---------------- K2: merged weight prep (transpose to n-major fp16) ----------------
__global__ void k_prep(const float* __restrict__ We1, const float* __restrict__ We2) {
    __shared__ float tile[64][65];
    int bx = blockIdx.x;
    int tid = threadIdx.x;
    if (bx < 320) {
        int hb = bx & 7, kc = (bx >> 3) % 5, e = bx / 40;
#pragma unroll
        for (int i = 0; i < 16; i++) {
            int li = i * 256 + tid;
            int ki = li >> 6, hi = li & 63;
            tile[ki][hi] = We1[((size_t)e * DIN + kc * 64 + ki) * DH + hb * 64 + hi];
        }
        __syncthreads();
#pragma unroll
        for (int i = 0; i < 16; i++) {
            int li = i * 256 + tid;
            int kk = li & 63, hr = li >> 6;
            size_t dst = (((size_t)(e * 5 + kc) * 512) + hb * 64 + hr) * 64 + kk;
            g_B1[dst] = __float2half_rn(tile[kk][hr]);
        }
    } else {
        int b2 = bx - 320;
        int ob = b2 & 3, kc = (b2 >> 2) & 7, e = b2 >> 5;
#pragma unroll
        for (int i = 0; i < 16; i++) {
            int li = i * 256 + tid;
            int ki = li >> 6, oi = li & 63;
            tile[ki][oi] = We2[((size_t)e * DH + kc * 64 + ki) * DD + ob * 64 + oi];
        }
        __syncthreads();
#pragma unroll
        for (int i = 0; i < 16; i++) {
            int li = i * 256 + tid;
            int kk = li & 63, orr = li >> 6;
            size_t dst = (((size_t)(e * 8 + kc) * 256) + ob * 64 + orr) * 64 + kk;
            g_B2[dst] = __float2half_rn(tile[kk][orr]);
        }
    }
}

// ---------------- K3: router (logit-exact fp32 SIMT) ----------------
#define R_SMEM_FLOATS (320 * 33 + 32 * 256)
__global__ __launch_bounds__(256, 2) void k_router(
    const float* __restrict__ Wr1, const float* __restrict__ br1,
    const float* __restrict__ Wr2, const float* __restrict__ br2,
    float* __restrict__ out) {
    extern __shared__ float sm[];
    float* xT  = sm;
    float* wch = sm + 320 * 33;
    float* hrT = sm;
    float* ws2 = wch;
    float* lg  = wch + 2048;

    int tid  = threadIdx.x;
    int base = blockIdx.x * 32;

    for (int idx = tid; idx < 32 * DIN; idx += 256) {
        int r = idx / DIN;
        int k = idx - r * DIN;
        xT[k * 33 + r] = g_x[(base + r) * DIN + k];
    }

    int tg = tid >> 5;
    int cg = tid & 31;

    float acc[2][4][4];
#pragma unroll
    for (int m = 0; m < 2; m++)
#pragma unroll
        for (int tt = 0; tt < 4; tt++)
#pragma unroll
            for (int j = 0; j < 4; j++) acc[m][tt][j] = 0.f;

    for (int kc = 0; kc < DIN; kc += 32) {
#pragma unroll
        for (int i = 0; i < 32; i++) {
            int idx = tid + i * 256;
            int kk = idx >> 8;
            int c  = idx & 255;
            wch[kk * 256 + c] = Wr1[(kc + kk) * DR + c];
        }
        __syncthreads();
#pragma unroll 2
        for (int k = 0; k < 32; k++) {
            float xv[4];
#pragma unroll
            for (int tt = 0; tt < 4; tt++) xv[tt] = xT[(kc + k) * 33 + 4 * tg + tt];
#pragma unroll
            for (int m = 0; m < 2; m++) {
                float4 wq = *(const float4*)&wch[k * 256 + 128 * m + 4 * cg];
#pragma unroll
                for (int tt = 0; tt < 4; tt++) {
                    acc[m][tt][0] += xv[tt] * wq.x;
                    acc[m][tt][1] += xv[tt] * wq.y;
                    acc[m][tt][2] += xv[tt] * wq.z;
                    acc[m][tt][3] += xv[tt] * wq.w;
                }
            }
        }
        __syncthreads();
    }

#pragma unroll
    for (int m = 0; m < 2; m++)
#pragma unroll
        for (int j = 0; j < 4; j++) {
            int col = 4 * cg + 128 * m + j;
            float b = br1[col];
#pragma unroll
            for (int tt = 0; tt < 4; tt++)
                hrT[col * 33 + 4 * tg + tt] = gelu_tanh(acc[m][tt][j] + b);
        }
    for (int idx = tid; idx < DR * EE; idx += 256) ws2[idx] = Wr2[idx];
    __syncthreads();

    {
        int e = tid >> 5;
        int r = tid & 31;
        float lacc = br2[e];
#pragma unroll 4
        for (int k = 0; k < DR; k++) lacc += hrT[k * 33 + r] * ws2[k * EE + e];
        lg[r * EE + e] = lacc;
        out[(size_t)NT * DD + (size_t)NT * EE + (size_t)(base + r) * EE + e] = lacc;
    }
    __syncthreads();

    if (tid < 32) {
        int r = tid;
        int gtok = base + r;
        float v[EE];
#pragma unroll
        for (int e = 0; e < EE; e++) v[e] = lg[r * EE + e];
        int i0 = 0;
#pragma unroll
        for (int e = 1; e < EE; e++)
            if (v[e] > v[i0]) i0 = e;
        int i1 = (i0 == 0) ? 1 : 0;
#pragma unroll
        for (int e = 0; e < EE; e++) {
            if (e == i0) continue;
            if (v[e] > v[i1]) i1 = e;
        }
        float t  = expf(v[i1] - v[i0]);
        float s  = 1.0f + t;
        float w0 = 1.0f / s;
        float w1 = t / s;
        float* gw = out + (size_t)NT * DD + (size_t)gtok * EE;
#pragma unroll
        for (int e = 0; e < EE; e++)
            gw[e] = (e == i0) ? w0 : ((e == i1) ? w1 : 0.0f);
        int p0 = atomicAdd(&g_cnt[i0], 1);
        g_tok[i0 * NT + p0] = gtok;
        g_w[i0 * NT + p0]   = w0;
        int p1 = atomicAdd(&g_cnt[i1], 1);
        g_tok[i1 * NT + p1] = gtok | (1 << 31);
        g_w[i1 * NT + p1]   = w1;
    }
}

// ---------------- expert layer 1: A resident, 3-stage B pipeline ----------------
#define E1_AH   0
#define E1_AL   83968
#define E1_B    167936
#define E1_SMEM 223232

__global__ __launch_bounds__(256, 1) void k_expert1(const float* __restrict__ be1) {
    int e = blockIdx.y;
    int cnt = g_cnt[e];
    int base = blockIdx.x * 128;
    if (base >= cnt) return;
    int nrows = min(128, cnt - base);

    extern __shared__ char smraw[];
    uint32_t smb = smem_u32(smraw);

    __shared__ int s_tok[128];
    __shared__ int s_dst[128];

    int tid = threadIdx.x, wid = tid >> 5, lane = tid & 31;
    for (int r = tid; r < 128; r += 256) {
        int rr = (r < nrows) ? r : 0;
        int ent = g_tok[e * NT + base + rr];
        int tok = ent & 0x7FFFFFFF;
        s_tok[r] = tok;
        s_dst[r] = (r < nrows) ? (int)((((unsigned)ent) >> 31) * NT + tok) : -1;
    }
    __syncthreads();

    int wm = wid & 3, wn = wid >> 2, lq = lane >> 2, lr = lane & 3;

    // prologue: stage full A, then B0, B1
    {
        int row = tid >> 1, half = tid & 1;
        const char* srch = (const char*)(g_xh + (size_t)s_tok[row] * DIN);
        const char* srcl = (const char*)(g_xl + (size_t)s_tok[row] * DIN);
        uint32_t dh = smb + E1_AH + (uint32_t)(row * 656 + half * 320);
        uint32_t dl = smb + E1_AL + (uint32_t)(row * 656 + half * 320);
#pragma unroll
        for (int j = 0; j < 20; j++) {
            int g = half * 20 + j;
            cp16(dh + j * 16, srch + g * 16);
            cp16(dl + j * 16, srcl + g * 16);
        }
        cp_commit();
    }
    int srow = tid >> 3, su = tid & 7;
    auto stageB = [&](int c) {
        int nc = c / 5, kc = c - nc * 5;
        uint32_t b = smb + E1_B + (uint32_t)(c % 3) * 18432;
        const char* B1 = (const char*)(g_B1 + (((size_t)(e * 5 + kc) * 512) + nc * 128) * 64);
#pragma unroll
        for (int i4 = 0; i4 < 4; i4++) {
            int r = srow + i4 * 32;
            cp16(b + (uint32_t)(r * 144 + su * 16), B1 + r * 128 + su * 16);
        }
        cp_commit();
    };
    stageB(0);
    stageB(1);

    uint32_t abase = smb + (uint32_t)((wm * 32 + (lane & 15)) * 656 + ((lane >> 4) << 4));
    uint32_t bbase = (uint32_t)((wn * 64 + (lane & 15)) * 144 + ((lane >> 4) << 4));

    float acc[2][8][4];
    for (int c = 0; c < 20; c++) {
        int nc = c / 5, kc = c - nc * 5;
        cp_wait1();
        __syncthreads();
        if (c + 2 < 20) stageB(c + 2); else cp_commit();

        if (kc == 0) {
#pragma unroll
            for (int mt = 0; mt < 2; mt++)
#pragma unroll
                for (int nt = 0; nt < 8; nt++)
#pragma unroll
                    for (int j = 0; j < 4; j++) acc[mt][nt][j] = 0.f;
        }
        uint32_t bb = smb + E1_B + (uint32_t)(c % 3) * 18432 + bbase;
        uint32_t ab = abase + (uint32_t)(kc * 128);
#pragma unroll
        for (int s = 0; s < 4; s++) {
            uint32_t ah[2][4], al[2][4], bq[4][4];
#pragma unroll
            for (int mt = 0; mt < 2; mt++) {
                uint32_t a = ab + (uint32_t)(mt * 10496 + s * 32);
                ldsm_x4(ah[mt], a + E1_AH);
                ldsm_x4(al[mt], a + E1_AL);
            }
#pragma unroll
            for (int g = 0; g < 4; g++)
                ldsm_x4(bq[g], bb + (uint32_t)(g * 2304 + s * 32));
            // ah pass: 16 independent MMAs (all distinct accumulators)
#pragma unroll
            for (int g = 0; g < 4; g++) {
                uint32_t bhe[2] = {bq[g][0], bq[g][2]}, bho[2] = {bq[g][1], bq[g][3]};
#pragma unroll
                for (int mt = 0; mt < 2; mt++) {
                    mma_f16(acc[mt][2 * g],     ah[mt], bhe);
                    mma_f16(acc[mt][2 * g + 1], ah[mt], bho);
                }
            }
            // al pass: reuse distance 16
#pragma unroll
            for (int g = 0; g < 4; g++) {
                uint32_t bhe[2] = {bq[g][0], bq[g][2]}, bho[2] = {bq[g][1], bq[g][3]};
#pragma unroll
                for (int mt = 0; mt < 2; mt++) {
                    mma_f16(acc[mt][2 * g],     al[mt], bhe);
                    mma_f16(acc[mt][2 * g + 1], al[mt], bho);
                }
            }
        }

        if (kc == 4) {
            const float* b1 = be1 + e * DH + nc * 128;
#pragma unroll
            for (int mt = 0; mt < 2; mt++)
#pragma unroll
                for (int nt = 0; nt < 8; nt++) {
                    int col = wn * 64 + nt * 8 + lr * 2;
                    float bb0 = b1[col], bb1 = b1[col + 1];
#pragma unroll
                    for (int h = 0; h < 2; h++) {
                        int row = wm * 32 + mt * 16 + lq + h * 8;
                        int dst = s_dst[row];
                        if (dst >= 0) {
                            float v0 = gelu_fast(acc[mt][nt][2 * h]     + bb0);
                            float v1 = gelu_fast(acc[mt][nt][2 * h + 1] + bb1);
                            __half h0 = __float2half_rn(v0), h1 = __float2half_rn(v1);
                            __half l0 = __float2half_rn(v0 - __half2float(h0));
                            __half l1 = __float2half_rn(v1 - __half2float(h1));
                            uint32_t ph = (uint32_t)__half_as_ushort(h0) | ((uint32_t)__half_as_ushort(h1) << 16);
                            uint32_t pl = (uint32_t)__half_as_ushort(l0) | ((uint32_t)__half_as_ushort(l1) << 16);
                            size_t widx = ((size_t)dst * DH + nc * 128 + col) >> 1;
                            ((uint32_t*)g_heh)[widx] = ph;
                            ((uint32_t*)g_hel)[widx] = pl;
                        }
                    }
                }
        }
    }
}

// ---------------- expert layer 2: A in K-halves, 3-stage B pipeline, dual-nc acc ----
#define E2_AH   0
#define E2_AL   67584
#define E2_B    135168
#define E2_SMEM 190464

__global__ __launch_bounds__(256, 1) void k_expert2(const float* __restrict__ be2) {
    int e = blockIdx.y;
    int cnt = g_cnt[e];
    int base = blockIdx.x * 128;
    if (base >= cnt) return;
    int nrows = min(128, cnt - base);

    extern __shared__ char smraw[];
    uint32_t smb = smem_u32(smraw);

    __shared__ int   s_row[128];
    __shared__ int   s_dst[128];
    __shared__ float s_w[128];

    int tid = threadIdx.x, wid = tid >> 5, lane = tid & 31;
    for (int r = tid; r < 128; r += 256) {
        int rr = (r < nrows) ? r : 0;
        int ent = g_tok[e * NT + base + rr];
        int tok = ent & 0x7FFFFFFF;
        int herow = (int)((((unsigned)ent) >> 31) * NT + tok);
        s_row[r] = herow;
        s_dst[r] = (r < nrows) ? herow : -1;
        s_w[r]   = g_w[e * NT + base + rr];
    }
    __syncthreads();

    int wm = wid & 3, wn = wid >> 2, lq = lane >> 2, lr = lane & 3;
    int srow = tid >> 3, su = tid & 7;

    uint32_t abase = smb + (uint32_t)((wm * 32 + (lane & 15)) * 528 + ((lane >> 4) << 4));
    uint32_t bbase = (uint32_t)((wn * 64 + (lane & 15)) * 144 + ((lane >> 4) << 4));

    auto stageB = [&](int cgl) {
        int j = cgl & 7, kh = cgl >> 3;
        int nc = j >> 2, kcl = j & 3;
        int kc = kh * 4 + kcl;
        uint32_t b = smb + E2_B + (uint32_t)(cgl % 3) * 18432;
        const char* B2 = (const char*)(g_B2 + (((size_t)(e * 8 + kc) * 256) + nc * 128) * 64);
#pragma unroll
        for (int i4 = 0; i4 < 4; i4++) {
            int r = srow + i4 * 32;
            cp16(b + (uint32_t)(r * 144 + su * 16), B2 + r * 128 + su * 16);
        }
        cp_commit();
    };

    float acc[2][2][8][4];
#pragma unroll
    for (int nc = 0; nc < 2; nc++)
#pragma unroll
        for (int mt = 0; mt < 2; mt++)
#pragma unroll
            for (int nt = 0; nt < 8; nt++)
#pragma unroll
                for (int j = 0; j < 4; j++) acc[nc][mt][nt][j] = 0.f;

    for (int kh = 0; kh < 2; kh++) {
        __syncthreads();
        {
            int row = tid >> 1, half = tid & 1;
            const char* srch = (const char*)(g_heh + (size_t)s_row[row] * DH + kh * 256);
            const char* srcl = (const char*)(g_hel + (size_t)s_row[row] * DH + kh * 256);
            uint32_t dh = smb + E2_AH + (uint32_t)(row * 528 + half * 256);
            uint32_t dl = smb + E2_AL + (uint32_t)(row * 528 + half * 256);
#pragma unroll
            for (int j = 0; j < 16; j++) {
                int g = half * 16 + j;
                cp16(dh + j * 16, srch + g * 16);
                cp16(dl + j * 16, srcl + g * 16);
            }
            cp_commit();
        }
        stageB(kh * 8);
        stageB(kh * 8 + 1);

        for (int j = 0; j < 8; j++) {
            int cgl = kh * 8 + j;
            int nc = j >> 2, kcl = j & 3;
            cp_wait1();
            __syncthreads();
            if (j + 2 < 8) stageB(cgl + 2); else cp_commit();

            uint32_t bb = smb + E2_B + (uint32_t)(cgl % 3) * 18432 + bbase;
            uint32_t ab = abase + (uint32_t)(kcl * 128);
#pragma unroll
            for (int s = 0; s < 4; s++) {
                uint32_t ah[2][4], al[2][4];
#pragma unroll
                for (int mt = 0; mt < 2; mt++) {
                    uint32_t a = ab + (uint32_t)(mt * 8448 + s * 32);
                    ldsm_x4(ah[mt], a + E2_AH);
                    ldsm_x4(al[mt], a + E2_AL);
                }
#pragma unroll
                for (int g = 0; g < 4; g++) {
                    uint32_t bh4[4];
                    ldsm_x4(bh4, bb + (uint32_t)(g * 2304 + s * 32));
                    uint32_t bhe[2] = {bh4[0], bh4[2]}, bho[2] = {bh4[1], bh4[3]};
                    // reuse distance 4 (ah group then al group)
                    mma_f16(acc[nc][0][2 * g],     ah[0], bhe);
                    mma_f16(acc[nc][1][2 * g],     ah[1], bhe);
                    mma_f16(acc[nc][0][2 * g + 1], ah[0], bho);
                    mma_f16(acc[nc][1][2 * g + 1], ah[1], bho);
                    mma_f16(acc[nc][0][2 * g],     al[0], bhe);
                    mma_f16(acc[nc][1][2 * g],     al[1], bhe);
                    mma_f16(acc[nc][0][2 * g + 1], al[0], bho);
                    mma_f16(acc[nc][1][2 * g + 1], al[1], bho);
                }
            }
        }
    }

    // epilogue: gate-scaled bias add -> g_part
#pragma unroll
    for (int nc = 0; nc < 2; nc++) {
        const float* b2 = be2 + e * DD + nc * 128;
#pragma unroll
        for (int mt = 0; mt < 2; mt++)
#pragma unroll
            for (int nt = 0; nt < 8; nt++) {
                int col = wn * 64 + nt * 8 + lr * 2;
                float bb0 = b2[col], bb1 = b2[col + 1];
#pragma unroll
                for (int h = 0; h < 2; h++) {
                    int row = wm * 32 + mt * 16 + lq + h * 8;
                    int dst = s_dst[row];
                    if (dst >= 0) {
                        float wgt = s_w[row];
                        float2 o;
                        o.x = wgt * (acc[nc][mt][nt][2 * h]     + bb0);
                        o.y = wgt * (acc[nc][mt][nt][2 * h + 1] + bb1);
                        *(float2*)&g_part[(size_t)dst * DD + nc * 128 + col] = o;
                    }
                }
            }
    }
}

// ---------------- K4: combine slot partials ----------------
__global__ void k_combine(float* __restrict__ out) {
    int i = blockIdx.x * blockDim.x + threadIdx.x;
    const float4* p0 = (const float4*)g_part;
    const float4* p1 = (const float4*)(g_part + (size_t)NT * DD);
    float4 a = p0[i], b = p1[i];
    float4 r;
    r.x = a.x + b.x; r.y = a.y + b.y; r.z = a.z + b.z; r.w = a.w + b.w;
    ((float4*)out)[i] = r;
}

// ---------------- launch ----------------
extern "C" void kernel_launch(void* const* d_in, const int* in_sizes, int n_in,
                              void* d_out, int out_size) {
    const float* hidden = (const float*)d_in[0];
    const float* feat   = (const float*)d_in[1];
    const float* Wf     = (const float*)d_in[2];
    const float* bf     = (const float*)d_in[3];
    const float* Wr1    = (const float*)d_in[4];
    const float* br1    = (const float*)d_in[5];
    const float* Wr2    = (const float*)d_in[6];
    const float* br2    = (const float*)d_in[7];
    const float* We1    = (const float*)d_in[8];
    const float* be1    = (const float*)d_in[9];
    const float* We2    = (const float*)d_in[10];
    const float* be2    = (const float*)d_in[11];
    float* out = (float*)d_out;

    const int r_smem = R_SMEM_FLOATS * 4;
    cudaFuncSetAttribute(k_router,  cudaFuncAttributeMaxDynamicSharedMemorySize, r_smem);
    cudaFuncSetAttribute(k_expert1, cudaFuncAttributeMaxDynamicSharedMemorySize, E1_SMEM);
    cudaFuncSetAttribute(k_expert2, cudaFuncAttributeMaxDynamicSharedMemorySize, E2_SMEM);

    k_build_x<<<NT, DIN>>>(hidden, feat, Wf, bf);
    k_prep<<<576, 256>>>(We1, We2);
    k_router<<<NT / 32, 256, r_smem>>>(Wr1, br1, Wr2, br2, out);
    k_expert1<<<dim3(64, EE), 256, E1_SMEM>>>(be1);
    k_expert2<<<dim3(64, EE), 256, E2_SMEM>>>(be2);
    k_combine<<<(NT * DD / 4) / 256, 256>>>(out);
}

// round 10
// speedup vs baseline: 1.3989x; 1.0617x over previous
#include <cuda_runtime.h>
#include <cuda_fp16.h>
#include <math.h>
#include <stdint.h>

#define NT   8192
#define DD   256
#define FF   8
#define DFE  64
#define DIN  320
#define DR   256
#define EE   8
#define DH   512

// ---------------- device-global scratch ----------------
__device__ __align__(16) float g_x[NT * DIN];
__device__ int                 g_cnt[EE];
__device__ int                 g_tok[EE * NT];
__device__ float               g_w[EE * NT];
__device__ __align__(16) float g_part[2 * NT * DD];
__device__ __align__(16) __half g_xh[NT * DIN];
__device__ __align__(16) __half g_xl[NT * DIN];
__device__ __align__(16) __half g_heh[2 * NT * DH];
__device__ __align__(16) __half g_hel[2 * NT * DH];
// pre-transposed n-major fp16 weights: B1 [e][kc=5][n=512][k=64], B2 [e][kc=8][n=256][k=64]
__device__ __align__(16) __half g_B1[EE * 5 * 512 * 64];
__device__ __align__(16) __half g_B2[EE * 8 * 256 * 64];

// ---------------- helpers ----------------
__device__ __forceinline__ float gelu_tanh(float v) {
    float u = 0.7978845608028654f * (v + 0.044715f * v * v * v);
    return 0.5f * v * (1.0f + tanhf(u));
}
__device__ __forceinline__ float gelu_fast(float v) {
    float u = 0.7978845608028654f * (v + 0.044715f * v * v * v);
    return v / (1.0f + __expf(-2.0f * u));
}
__device__ __forceinline__ uint32_t smem_u32(const void* p) {
    uint32_t a;
    asm("{ .reg .u64 t; cvta.to.shared.u64 t, %1; cvt.u32.u64 %0, t; }" : "=r"(a) : "l"(p));
    return a;
}
__device__ __forceinline__ void mma_f16(float* d, const uint32_t* a, const uint32_t* b) {
    asm volatile(
        "mma.sync.aligned.m16n8k16.row.col.f32.f16.f16.f32 "
        "{%0,%1,%2,%3}, {%4,%5,%6,%7}, {%8,%9}, {%0,%1,%2,%3};"
        : "+f"(d[0]), "+f"(d[1]), "+f"(d[2]), "+f"(d[3])
        : "r"(a[0]), "r"(a[1]), "r"(a[2]), "r"(a[3]), "r"(b[0]), "r"(b[1]));
}
__device__ __forceinline__ void ldsm_x4(uint32_t* r, uint32_t a) {
    asm volatile("ldmatrix.sync.aligned.m8n8.x4.shared.b16 {%0,%1,%2,%3}, [%4];"
        : "=r"(r[0]), "=r"(r[1]), "=r"(r[2]), "=r"(r[3]) : "r"(a));
}
__device__ __forceinline__ void cp16(uint32_t dst, const void* src) {
    asm volatile("cp.async.cg.shared.global [%0], [%1], 16;" :: "r"(dst), "l"(src));
}
__device__ __forceinline__ void cp_commit() {
    asm volatile("cp.async.commit_group;" ::: "memory");
}
__device__ __forceinline__ void cp_wait1() {
    asm volatile("cp.async.wait_group 1;" ::: "memory");
}

// ---------------- K1: build x + splits (+ counter reset in block 0) ----------------
__global__ void k_build_x(const float* __restrict__ hidden,
                          const float* __restrict__ feat,
                          const float* __restrict__ Wf,
                          const float* __restrict__ bf) {
    int tok = blockIdx.x;
    int t = threadIdx.x;
    if (blockIdx.x == 0 && t < EE) g_cnt[t] = 0;
    float v;
    if (t < DD) {
        v = hidden[tok * DD + t];
    } else {
        int j = t - DD;
        float acc = bf[j];
#pragma unroll
        for (int k = 0; k < FF; k++) acc += feat[tok * FF + k] * Wf[k * DFE + j];
        v = acc;
    }
    g_x[tok * DIN + t] = v;
    __half h = __float2half_rn(v);
    g_xh[tok * DIN + t] = h;
    g_xl[tok * DIN + t] = __float2half_rn(v - __half2float(h));
}

// ---------------- K2: merged weight prep (transpose to n-major fp16) ----------------
__global__ void k_prep(const float* __restrict__ We1, const float* __restrict__ We2) {
    __shared__ float tile[64][65];
    int bx = blockIdx.x;
    int tid = threadIdx.x;
    if (bx < 320) {
        int hb = bx & 7, kc = (bx >> 3) % 5, e = bx / 40;
#pragma unroll
        for (int i = 0; i < 16; i++) {
            int li = i * 256 + tid;
            int ki = li >> 6, hi = li & 63;
            tile[ki][hi] = We1[((size_t)e * DIN + kc * 64 + ki) * DH + hb * 64 + hi];
        }
        __syncthreads();
#pragma unroll
        for (int i = 0; i < 16; i++) {
            int li = i * 256 + tid;
            int kk = li & 63, hr = li >> 6;
            size_t dst = (((size_t)(e * 5 + kc) * 512) + hb * 64 + hr) * 64 + kk;
            g_B1[dst] = __float2half_rn(tile[kk][hr]);
        }
    } else {
        int b2 = bx - 320;
        int ob = b2 & 3, kc = (b2 >> 2) & 7, e = b2 >> 5;
#pragma unroll
        for (int i = 0; i < 16; i++) {
            int li = i * 256 + tid;
            int ki = li >> 6, oi = li & 63;
            tile[ki][oi] = We2[((size_t)e * DH + kc * 64 + ki) * DD + ob * 64 + oi];
        }
        __syncthreads();
#pragma unroll
        for (int i = 0; i < 16; i++) {
            int li = i * 256 + tid;
            int kk = li & 63, orr = li >> 6;
            size_t dst = (((size_t)(e * 8 + kc) * 256) + ob * 64 + orr) * 64 + kk;
            g_B2[dst] = __float2half_rn(tile[kk][orr]);
        }
    }
}

// ---------------- K3: router (logit-exact fp32 SIMT) ----------------
#define R_SMEM_FLOATS (320 * 33 + 32 * 256)
__global__ __launch_bounds__(256, 2) void k_router(
    const float* __restrict__ Wr1, const float* __restrict__ br1,
    const float* __restrict__ Wr2, const float* __restrict__ br2,
    float* __restrict__ out) {
    extern __shared__ float sm[];
    float* xT  = sm;
    float* wch = sm + 320 * 33;
    float* hrT = sm;
    float* ws2 = wch;
    float* lg  = wch + 2048;

    int tid  = threadIdx.x;
    int base = blockIdx.x * 32;

    for (int idx = tid; idx < 32 * DIN; idx += 256) {
        int r = idx / DIN;
        int k = idx - r * DIN;
        xT[k * 33 + r] = g_x[(base + r) * DIN + k];
    }

    int tg = tid >> 5;
    int cg = tid & 31;

    float acc[2][4][4];
#pragma unroll
    for (int m = 0; m < 2; m++)
#pragma unroll
        for (int tt = 0; tt < 4; tt++)
#pragma unroll
            for (int j = 0; j < 4; j++) acc[m][tt][j] = 0.f;

    for (int kc = 0; kc < DIN; kc += 32) {
#pragma unroll
        for (int i = 0; i < 32; i++) {
            int idx = tid + i * 256;
            int kk = idx >> 8;
            int c  = idx & 255;
            wch[kk * 256 + c] = Wr1[(kc + kk) * DR + c];
        }
        __syncthreads();
#pragma unroll 2
        for (int k = 0; k < 32; k++) {
            float xv[4];
#pragma unroll
            for (int tt = 0; tt < 4; tt++) xv[tt] = xT[(kc + k) * 33 + 4 * tg + tt];
#pragma unroll
            for (int m = 0; m < 2; m++) {
                float4 wq = *(const float4*)&wch[k * 256 + 128 * m + 4 * cg];
#pragma unroll
                for (int tt = 0; tt < 4; tt++) {
                    acc[m][tt][0] += xv[tt] * wq.x;
                    acc[m][tt][1] += xv[tt] * wq.y;
                    acc[m][tt][2] += xv[tt] * wq.z;
                    acc[m][tt][3] += xv[tt] * wq.w;
                }
            }
        }
        __syncthreads();
    }

#pragma unroll
    for (int m = 0; m < 2; m++)
#pragma unroll
        for (int j = 0; j < 4; j++) {
            int col = 4 * cg + 128 * m + j;
            float b = br1[col];
#pragma unroll
            for (int tt = 0; tt < 4; tt++)
                hrT[col * 33 + 4 * tg + tt] = gelu_tanh(acc[m][tt][j] + b);
        }
    for (int idx = tid; idx < DR * EE; idx += 256) ws2[idx] = Wr2[idx];
    __syncthreads();

    {
        int e = tid >> 5;
        int r = tid & 31;
        float lacc = br2[e];
#pragma unroll 4
        for (int k = 0; k < DR; k++) lacc += hrT[k * 33 + r] * ws2[k * EE + e];
        lg[r * EE + e] = lacc;
        out[(size_t)NT * DD + (size_t)NT * EE + (size_t)(base + r) * EE + e] = lacc;
    }
    __syncthreads();

    if (tid < 32) {
        int r = tid;
        int gtok = base + r;
        float v[EE];
#pragma unroll
        for (int e = 0; e < EE; e++) v[e] = lg[r * EE + e];
        int i0 = 0;
#pragma unroll
        for (int e = 1; e < EE; e++)
            if (v[e] > v[i0]) i0 = e;
        int i1 = (i0 == 0) ? 1 : 0;
#pragma unroll
        for (int e = 0; e < EE; e++) {
            if (e == i0) continue;
            if (v[e] > v[i1]) i1 = e;
        }
        float t  = expf(v[i1] - v[i0]);
        float s  = 1.0f + t;
        float w0 = 1.0f / s;
        float w1 = t / s;
        float* gw = out + (size_t)NT * DD + (size_t)gtok * EE;
#pragma unroll
        for (int e = 0; e < EE; e++)
            gw[e] = (e == i0) ? w0 : ((e == i1) ? w1 : 0.0f);
        int p0 = atomicAdd(&g_cnt[i0], 1);
        g_tok[i0 * NT + p0] = gtok;
        g_w[i0 * NT + p0]   = w0;
        int p1 = atomicAdd(&g_cnt[i1], 1);
        g_tok[i1 * NT + p1] = gtok | (1 << 31);
        g_w[i1 * NT + p1]   = w1;
    }
}

// ---------------- expert layer 1: 512 threads, warp tile 32x32, A resident ----------
#define E1_AH   0
#define E1_AL   83968
#define E1_B    167936
#define E1_SMEM 223232

__global__ __launch_bounds__(512, 1) void k_expert1(const float* __restrict__ be1) {
    int e = blockIdx.y;
    int cnt = g_cnt[e];
    int base = blockIdx.x * 128;
    if (base >= cnt) return;
    int nrows = min(128, cnt - base);

    extern __shared__ char smraw[];
    uint32_t smb = smem_u32(smraw);

    __shared__ int s_tok[128];
    __shared__ int s_dst[128];

    int tid = threadIdx.x, wid = tid >> 5, lane = tid & 31;
    if (tid < 128) {
        int r = tid;
        int rr = (r < nrows) ? r : 0;
        int ent = g_tok[e * NT + base + rr];
        int tok = ent & 0x7FFFFFFF;
        s_tok[r] = tok;
        s_dst[r] = (r < nrows) ? (int)((((unsigned)ent) >> 31) * NT + tok) : -1;
    }
    __syncthreads();

    int wm = wid & 3, wn = wid >> 2, lq = lane >> 2, lr = lane & 3;

    // prologue: stage full A (row = tid>>2, quarter = tid&3 -> 10 x 16B each array)
    {
        int row = tid >> 2, q = tid & 3;
        const char* srch = (const char*)(g_xh + (size_t)s_tok[row] * DIN);
        const char* srcl = (const char*)(g_xl + (size_t)s_tok[row] * DIN);
        uint32_t dh = smb + E1_AH + (uint32_t)(row * 656);
        uint32_t dl = smb + E1_AL + (uint32_t)(row * 656);
#pragma unroll
        for (int j = 0; j < 10; j++) {
            int g = q * 10 + j;
            cp16(dh + g * 16, srch + g * 16);
            cp16(dl + g * 16, srcl + g * 16);
        }
        cp_commit();
    }
    auto stageB = [&](int c) {
        int nc = c / 5, kc = c - nc * 5;
        uint32_t b = smb + E1_B + (uint32_t)(c % 3) * 18432;
        const char* B1 = (const char*)(g_B1 + (((size_t)(e * 5 + kc) * 512) + nc * 128) * 64);
#pragma unroll
        for (int i4 = 0; i4 < 2; i4++) {
            int idx = tid + i4 * 512;
            int r = idx >> 3, su = idx & 7;
            cp16(b + (uint32_t)(r * 144 + su * 16), B1 + r * 128 + su * 16);
        }
        cp_commit();
    };
    stageB(0);
    stageB(1);

    uint32_t abase = smb + (uint32_t)((wm * 32 + (lane & 15)) * 656 + ((lane >> 4) << 4));
    uint32_t bbase = (uint32_t)((wn * 32 + (lane & 15)) * 144 + ((lane >> 4) << 4));

    float acc[2][4][4];
    for (int c = 0; c < 20; c++) {
        int nc = c / 5, kc = c - nc * 5;
        cp_wait1();
        __syncthreads();
        if (c + 2 < 20) stageB(c + 2); else cp_commit();

        if (kc == 0) {
#pragma unroll
            for (int mt = 0; mt < 2; mt++)
#pragma unroll
                for (int nt = 0; nt < 4; nt++)
#pragma unroll
                    for (int j = 0; j < 4; j++) acc[mt][nt][j] = 0.f;
        }
        uint32_t bb = smb + E1_B + (uint32_t)(c % 3) * 18432 + bbase;
        uint32_t ab = abase + (uint32_t)(kc * 128);
#pragma unroll
        for (int s = 0; s < 4; s++) {
            uint32_t ah[2][4], al[2][4], bq[2][4];
#pragma unroll
            for (int mt = 0; mt < 2; mt++) {
                uint32_t a = ab + (uint32_t)(mt * 10496 + s * 32);
                ldsm_x4(ah[mt], a + E1_AH);
                ldsm_x4(al[mt], a + E1_AL);
            }
#pragma unroll
            for (int g = 0; g < 2; g++)
                ldsm_x4(bq[g], bb + (uint32_t)(g * 2304 + s * 32));
            // ah pass then al pass (accumulation order per register unchanged)
#pragma unroll
            for (int g = 0; g < 2; g++) {
                uint32_t bhe[2] = {bq[g][0], bq[g][2]}, bho[2] = {bq[g][1], bq[g][3]};
#pragma unroll
                for (int mt = 0; mt < 2; mt++) {
                    mma_f16(acc[mt][2 * g],     ah[mt], bhe);
                    mma_f16(acc[mt][2 * g + 1], ah[mt], bho);
                }
            }
#pragma unroll
            for (int g = 0; g < 2; g++) {
                uint32_t bhe[2] = {bq[g][0], bq[g][2]}, bho[2] = {bq[g][1], bq[g][3]};
#pragma unroll
                for (int mt = 0; mt < 2; mt++) {
                    mma_f16(acc[mt][2 * g],     al[mt], bhe);
                    mma_f16(acc[mt][2 * g + 1], al[mt], bho);
                }
            }
        }

        if (kc == 4) {
            const float* b1 = be1 + e * DH + nc * 128;
#pragma unroll
            for (int mt = 0; mt < 2; mt++)
#pragma unroll
                for (int nt = 0; nt < 4; nt++) {
                    int col = wn * 32 + nt * 8 + lr * 2;
                    float bb0 = b1[col], bb1 = b1[col + 1];
#pragma unroll
                    for (int h = 0; h < 2; h++) {
                        int row = wm * 32 + mt * 16 + lq + h * 8;
                        int dst = s_dst[row];
                        if (dst >= 0) {
                            float v0 = gelu_fast(acc[mt][nt][2 * h]     + bb0);
                            float v1 = gelu_fast(acc[mt][nt][2 * h + 1] + bb1);
                            __half h0 = __float2half_rn(v0), h1 = __float2half_rn(v1);
                            __half l0 = __float2half_rn(v0 - __half2float(h0));
                            __half l1 = __float2half_rn(v1 - __half2float(h1));
                            uint32_t ph = (uint32_t)__half_as_ushort(h0) | ((uint32_t)__half_as_ushort(h1) << 16);
                            uint32_t pl = (uint32_t)__half_as_ushort(l0) | ((uint32_t)__half_as_ushort(l1) << 16);
                            size_t widx = ((size_t)dst * DH + nc * 128 + col) >> 1;
                            ((uint32_t*)g_heh)[widx] = ph;
                            ((uint32_t*)g_hel)[widx] = pl;
                        }
                    }
                }
        }
    }
}

// ---------------- expert layer 2: 512 threads, warp tile 32x32, dual-nc acc -------
#define E2_AH   0
#define E2_AL   67584
#define E2_B    135168
#define E2_SMEM 190464

__global__ __launch_bounds__(512, 1) void k_expert2(const float* __restrict__ be2) {
    int e = blockIdx.y;
    int cnt = g_cnt[e];
    int base = blockIdx.x * 128;
    if (base >= cnt) return;
    int nrows = min(128, cnt - base);

    extern __shared__ char smraw[];
    uint32_t smb = smem_u32(smraw);

    __shared__ int   s_row[128];
    __shared__ int   s_dst[128];
    __shared__ float s_w[128];

    int tid = threadIdx.x, wid = tid >> 5, lane = tid & 31;
    if (tid < 128) {
        int r = tid;
        int rr = (r < nrows) ? r : 0;
        int ent = g_tok[e * NT + base + rr];
        int tok = ent & 0x7FFFFFFF;
        int herow = (int)((((unsigned)ent) >> 31) * NT + tok);
        s_row[r] = herow;
        s_dst[r] = (r < nrows) ? herow : -1;
        s_w[r]   = g_w[e * NT + base + rr];
    }
    __syncthreads();

    int wm = wid & 3, wn = wid >> 2, lq = lane >> 2, lr = lane & 3;

    uint32_t abase = smb + (uint32_t)((wm * 32 + (lane & 15)) * 528 + ((lane >> 4) << 4));
    uint32_t bbase = (uint32_t)((wn * 32 + (lane & 15)) * 144 + ((lane >> 4) << 4));

    auto stageB = [&](int cgl) {
        int j = cgl & 7, kh = cgl >> 3;
        int nc = j >> 2, kcl = j & 3;
        int kc = kh * 4 + kcl;
        uint32_t b = smb + E2_B + (uint32_t)(cgl % 3) * 18432;
        const char* B2 = (const char*)(g_B2 + (((size_t)(e * 8 + kc) * 256) + nc * 128) * 64);
#pragma unroll
        for (int i4 = 0; i4 < 2; i4++) {
            int idx = tid + i4 * 512;
            int r = idx >> 3, su = idx & 7;
            cp16(b + (uint32_t)(r * 144 + su * 16), B2 + r * 128 + su * 16);
        }
        cp_commit();
    };

    float acc[2][2][4][4];
#pragma unroll
    for (int nc = 0; nc < 2; nc++)
#pragma unroll
        for (int mt = 0; mt < 2; mt++)
#pragma unroll
            for (int nt = 0; nt < 4; nt++)
#pragma unroll
                for (int j = 0; j < 4; j++) acc[nc][mt][nt][j] = 0.f;

    for (int kh = 0; kh < 2; kh++) {
        __syncthreads();
        {
            int row = tid >> 2, q = tid & 3;
            const char* srch = (const char*)(g_heh + (size_t)s_row[row] * DH + kh * 256);
            const char* srcl = (const char*)(g_hel + (size_t)s_row[row] * DH + kh * 256);
            uint32_t dh = smb + E2_AH + (uint32_t)(row * 528);
            uint32_t dl = smb + E2_AL + (uint32_t)(row * 528);
#pragma unroll
            for (int j = 0; j < 8; j++) {
                int g = q * 8 + j;
                cp16(dh + g * 16, srch + g * 16);
                cp16(dl + g * 16, srcl + g * 16);
            }
            cp_commit();
        }
        stageB(kh * 8);
        stageB(kh * 8 + 1);

        for (int j = 0; j < 8; j++) {
            int cgl = kh * 8 + j;
            int nc = j >> 2, kcl = j & 3;
            cp_wait1();
            __syncthreads();
            if (j + 2 < 8) stageB(cgl + 2); else cp_commit();

            uint32_t bb = smb + E2_B + (uint32_t)(cgl % 3) * 18432 + bbase;
            uint32_t ab = abase + (uint32_t)(kcl * 128);
#pragma unroll
            for (int s = 0; s < 4; s++) {
                uint32_t ah[2][4], al[2][4], bq[2][4];
#pragma unroll
                for (int mt = 0; mt < 2; mt++) {
                    uint32_t a = ab + (uint32_t)(mt * 8448 + s * 32);
                    ldsm_x4(ah[mt], a + E2_AH);
                    ldsm_x4(al[mt], a + E2_AL);
                }
#pragma unroll
                for (int g = 0; g < 2; g++)
                    ldsm_x4(bq[g], bb + (uint32_t)(g * 2304 + s * 32));
#pragma unroll
                for (int g = 0; g < 2; g++) {
                    uint32_t bhe[2] = {bq[g][0], bq[g][2]}, bho[2] = {bq[g][1], bq[g][3]};
#pragma unroll
                    for (int mt = 0; mt < 2; mt++) {
                        mma_f16(acc[nc][mt][2 * g],     ah[mt], bhe);
                        mma_f16(acc[nc][mt][2 * g + 1], ah[mt], bho);
                    }
                }
#pragma unroll
                for (int g = 0; g < 2; g++) {
                    uint32_t bhe[2] = {bq[g][0], bq[g][2]}, bho[2] = {bq[g][1], bq[g][3]};
#pragma unroll
                    for (int mt = 0; mt < 2; mt++) {
                        mma_f16(acc[nc][mt][2 * g],     al[mt], bhe);
                        mma_f16(acc[nc][mt][2 * g + 1], al[mt], bho);
                    }
                }
            }
        }
    }

    // epilogue: gate-scaled bias add -> g_part
#pragma unroll
    for (int nc = 0; nc < 2; nc++) {
        const float* b2 = be2 + e * DD + nc * 128;
#pragma unroll
        for (int mt = 0; mt < 2; mt++)
#pragma unroll
            for (int nt = 0; nt < 4; nt++) {
                int col = wn * 32 + nt * 8 + lr * 2;
                float bb0 = b2[col], bb1 = b2[col + 1];
#pragma unroll
                for (int h = 0; h < 2; h++) {
                    int row = wm * 32 + mt * 16 + lq + h * 8;
                    int dst = s_dst[row];
                    if (dst >= 0) {
                        float wgt = s_w[row];
                        float2 o;
                        o.x = wgt * (acc[nc][mt][nt][2 * h]     + bb0);
                        o.y = wgt * (acc[nc][mt][nt][2 * h + 1] + bb1);
                        *(float2*)&g_part[(size_t)dst * DD + nc * 128 + col] = o;
                    }
                }
            }
    }
}

// ---------------- K4: combine slot partials ----------------
__global__ void k_combine(float* __restrict__ out) {
    int i = blockIdx.x * blockDim.x + threadIdx.x;
    const float4* p0 = (const float4*)g_part;
    const float4* p1 = (const float4*)(g_part + (size_t)NT * DD);
    float4 a = p0[i], b = p1[i];
    float4 r;
    r.x = a.x + b.x; r.y = a.y + b.y; r.z = a.z + b.z; r.w = a.w + b.w;
    ((float4*)out)[i] = r;
}

// ---------------- launch ----------------
extern "C" void kernel_launch(void* const* d_in, const int* in_sizes, int n_in,
                              void* d_out, int out_size) {
    const float* hidden = (const float*)d_in[0];
    const float* feat   = (const float*)d_in[1];
    const float* Wf     = (const float*)d_in[2];
    const float* bf     = (const float*)d_in[3];
    const float* Wr1    = (const float*)d_in[4];
    const float* br1    = (const float*)d_in[5];
    const float* Wr2    = (const float*)d_in[6];
    const float* br2    = (const float*)d_in[7];
    const float* We1    = (const float*)d_in[8];
    const float* be1    = (const float*)d_in[9];
    const float* We2    = (const float*)d_in[10];
    const float* be2    = (const float*)d_in[11];
    float* out = (float*)d_out;

    const int r_smem = R_SMEM_FLOATS * 4;
    cudaFuncSetAttribute(k_router,  cudaFuncAttributeMaxDynamicSharedMemorySize, r_smem);
    cudaFuncSetAttribute(k_expert1, cudaFuncAttributeMaxDynamicSharedMemorySize, E1_SMEM);
    cudaFuncSetAttribute(k_expert2, cudaFuncAttributeMaxDynamicSharedMemorySize, E2_SMEM);

    k_build_x<<<NT, DIN>>>(hidden, feat, Wf, bf);
    k_prep<<<576, 256>>>(We1, We2);
    k_router<<<NT / 32, 256, r_smem>>>(Wr1, br1, Wr2, br2, out);
    k_expert1<<<dim3(64, EE), 512, E1_SMEM>>>(be1);
    k_expert2<<<dim3(64, EE), 512, E2_SMEM>>>(be2);
    k_combine<<<(NT * DD / 4) / 256, 256>>>(out);
}

// round 11
// speedup vs baseline: 1.7387x; 1.2428x over previous
#include <cuda_runtime.h>
#include <cuda_fp16.h>
#include <math.h>
#include <stdint.h>

#define NT   8192
#define DD   256
#define FF   8
#define DFE  64
#define DIN  320
#define DR   256
#define EE   8
#define DH   512

// ---------------- device-global scratch ----------------
__device__ __align__(16) float g_x[NT * DIN];
__device__ int                 g_cnt[EE];
__device__ int                 g_tok[EE * NT];
__device__ float               g_w[EE * NT];
__device__ __align__(16) float g_part[2 * NT * DD];
__device__ __align__(16) __half g_xh[NT * DIN];     // fp16 x
__device__ __align__(16) __half g_heh[2 * NT * DH]; // fp16 he
// pre-transposed n-major fp16 weights: B1 [e][kc=5][n=512][k=64], B2 [e][kc=8][n=256][k=64]
__device__ __align__(16) __half g_B1[EE * 5 * 512 * 64];
__device__ __align__(16) __half g_B2[EE * 8 * 256 * 64];

// ---------------- helpers ----------------
__device__ __forceinline__ float gelu_tanh(float v) {
    float u = 0.7978845608028654f * (v + 0.044715f * v * v * v);
    return 0.5f * v * (1.0f + tanhf(u));
}
__device__ __forceinline__ float gelu_fast(float v) {
    float u = 0.7978845608028654f * (v + 0.044715f * v * v * v);
    return v / (1.0f + __expf(-2.0f * u));
}
__device__ __forceinline__ uint32_t smem_u32(const void* p) {
    uint32_t a;
    asm("{ .reg .u64 t; cvta.to.shared.u64 t, %1; cvt.u32.u64 %0, t; }" : "=r"(a) : "l"(p));
    return a;
}
__device__ __forceinline__ void mma_f16(float* d, const uint32_t* a, const uint32_t* b) {
    asm volatile(
        "mma.sync.aligned.m16n8k16.row.col.f32.f16.f16.f32 "
        "{%0,%1,%2,%3}, {%4,%5,%6,%7}, {%8,%9}, {%0,%1,%2,%3};"
        : "+f"(d[0]), "+f"(d[1]), "+f"(d[2]), "+f"(d[3])
        : "r"(a[0]), "r"(a[1]), "r"(a[2]), "r"(a[3]), "r"(b[0]), "r"(b[1]));
}
__device__ __forceinline__ void ldsm_x4(uint32_t* r, uint32_t a) {
    asm volatile("ldmatrix.sync.aligned.m8n8.x4.shared.b16 {%0,%1,%2,%3}, [%4];"
        : "=r"(r[0]), "=r"(r[1]), "=r"(r[2]), "=r"(r[3]) : "r"(a));
}
__device__ __forceinline__ void cp16(uint32_t dst, const void* src) {
    asm volatile("cp.async.cg.shared.global [%0], [%1], 16;" :: "r"(dst), "l"(src));
}
__device__ __forceinline__ void cp_commit() {
    asm volatile("cp.async.commit_group;" ::: "memory");
}
__device__ __forceinline__ void cp_wait1() {
    asm volatile("cp.async.wait_group 1;" ::: "memory");
}

// ---------------- K1: build x + fp16 cast (+ counter reset in block 0) ----------------
__global__ void k_build_x(const float* __restrict__ hidden,
                          const float* __restrict__ feat,
                          const float* __restrict__ Wf,
                          const float* __restrict__ bf) {
    int tok = blockIdx.x;
    int t = threadIdx.x;
    if (blockIdx.x == 0 && t < EE) g_cnt[t] = 0;
    float v;
    if (t < DD) {
        v = hidden[tok * DD + t];
    } else {
        int j = t - DD;
        float acc = bf[j];
#pragma unroll
        for (int k = 0; k < FF; k++) acc += feat[tok * FF + k] * Wf[k * DFE + j];
        v = acc;
    }
    g_x[tok * DIN + t] = v;
    g_xh[tok * DIN + t] = __float2half_rn(v);
}

// ---------------- K2: merged weight prep (transpose to n-major fp16) ----------------
__global__ void k_prep(const float* __restrict__ We1, const float* __restrict__ We2) {
    __shared__ float tile[64][65];
    int bx = blockIdx.x;
    int tid = threadIdx.x;
    if (bx < 320) {
        int hb = bx & 7, kc = (bx >> 3) % 5, e = bx / 40;
#pragma unroll
        for (int i = 0; i < 16; i++) {
            int li = i * 256 + tid;
            int ki = li >> 6, hi = li & 63;
            tile[ki][hi] = We1[((size_t)e * DIN + kc * 64 + ki) * DH + hb * 64 + hi];
        }
        __syncthreads();
#pragma unroll
        for (int i = 0; i < 16; i++) {
            int li = i * 256 + tid;
            int kk = li & 63, hr = li >> 6;
            size_t dst = (((size_t)(e * 5 + kc) * 512) + hb * 64 + hr) * 64 + kk;
            g_B1[dst] = __float2half_rn(tile[kk][hr]);
        }
    } else {
        int b2 = bx - 320;
        int ob = b2 & 3, kc = (b2 >> 2) & 7, e = b2 >> 5;
#pragma unroll
        for (int i = 0; i < 16; i++) {
            int li = i * 256 + tid;
            int ki = li >> 6, oi = li & 63;
            tile[ki][oi] = We2[((size_t)e * DH + kc * 64 + ki) * DD + ob * 64 + oi];
        }
        __syncthreads();
#pragma unroll
        for (int i = 0; i < 16; i++) {
            int li = i * 256 + tid;
            int kk = li & 63, orr = li >> 6;
            size_t dst = (((size_t)(e * 8 + kc) * 256) + ob * 64 + orr) * 64 + kk;
            g_B2[dst] = __float2half_rn(tile[kk][orr]);
        }
    }
}

// ---------------- K3: router (logit-exact fp32 SIMT) ----------------
#define R_SMEM_FLOATS (320 * 33 + 32 * 256)
__global__ __launch_bounds__(256, 2) void k_router(
    const float* __restrict__ Wr1, const float* __restrict__ br1,
    const float* __restrict__ Wr2, const float* __restrict__ br2,
    float* __restrict__ out) {
    extern __shared__ float sm[];
    float* xT  = sm;
    float* wch = sm + 320 * 33;
    float* hrT = sm;
    float* ws2 = wch;
    float* lg  = wch + 2048;

    int tid  = threadIdx.x;
    int base = blockIdx.x * 32;

    for (int idx = tid; idx < 32 * DIN; idx += 256) {
        int r = idx / DIN;
        int k = idx - r * DIN;
        xT[k * 33 + r] = g_x[(base + r) * DIN + k];
    }

    int tg = tid >> 5;
    int cg = tid & 31;

    float acc[2][4][4];
#pragma unroll
    for (int m = 0; m < 2; m++)
#pragma unroll
        for (int tt = 0; tt < 4; tt++)
#pragma unroll
            for (int j = 0; j < 4; j++) acc[m][tt][j] = 0.f;

    for (int kc = 0; kc < DIN; kc += 32) {
#pragma unroll
        for (int i = 0; i < 32; i++) {
            int idx = tid + i * 256;
            int kk = idx >> 8;
            int c  = idx & 255;
            wch[kk * 256 + c] = Wr1[(kc + kk) * DR + c];
        }
        __syncthreads();
#pragma unroll 2
        for (int k = 0; k < 32; k++) {
            float xv[4];
#pragma unroll
            for (int tt = 0; tt < 4; tt++) xv[tt] = xT[(kc + k) * 33 + 4 * tg + tt];
#pragma unroll
            for (int m = 0; m < 2; m++) {
                float4 wq = *(const float4*)&wch[k * 256 + 128 * m + 4 * cg];
#pragma unroll
                for (int tt = 0; tt < 4; tt++) {
                    acc[m][tt][0] += xv[tt] * wq.x;
                    acc[m][tt][1] += xv[tt] * wq.y;
                    acc[m][tt][2] += xv[tt] * wq.z;
                    acc[m][tt][3] += xv[tt] * wq.w;
                }
            }
        }
        __syncthreads();
    }

#pragma unroll
    for (int m = 0; m < 2; m++)
#pragma unroll
        for (int j = 0; j < 4; j++) {
            int col = 4 * cg + 128 * m + j;
            float b = br1[col];
#pragma unroll
            for (int tt = 0; tt < 4; tt++)
                hrT[col * 33 + 4 * tg + tt] = gelu_tanh(acc[m][tt][j] + b);
        }
    for (int idx = tid; idx < DR * EE; idx += 256) ws2[idx] = Wr2[idx];
    __syncthreads();

    {
        int e = tid >> 5;
        int r = tid & 31;
        float lacc = br2[e];
#pragma unroll 4
        for (int k = 0; k < DR; k++) lacc += hrT[k * 33 + r] * ws2[k * EE + e];
        lg[r * EE + e] = lacc;
        out[(size_t)NT * DD + (size_t)NT * EE + (size_t)(base + r) * EE + e] = lacc;
    }
    __syncthreads();

    if (tid < 32) {
        int r = tid;
        int gtok = base + r;
        float v[EE];
#pragma unroll
        for (int e = 0; e < EE; e++) v[e] = lg[r * EE + e];
        int i0 = 0;
#pragma unroll
        for (int e = 1; e < EE; e++)
            if (v[e] > v[i0]) i0 = e;
        int i1 = (i0 == 0) ? 1 : 0;
#pragma unroll
        for (int e = 0; e < EE; e++) {
            if (e == i0) continue;
            if (v[e] > v[i1]) i1 = e;
        }
        float t  = expf(v[i1] - v[i0]);
        float s  = 1.0f + t;
        float w0 = 1.0f / s;
        float w1 = t / s;
        float* gw = out + (size_t)NT * DD + (size_t)gtok * EE;
#pragma unroll
        for (int e = 0; e < EE; e++)
            gw[e] = (e == i0) ? w0 : ((e == i1) ? w1 : 0.0f);
        int p0 = atomicAdd(&g_cnt[i0], 1);
        g_tok[i0 * NT + p0] = gtok;
        g_w[i0 * NT + p0]   = w0;
        int p1 = atomicAdd(&g_cnt[i1], 1);
        g_tok[i1 * NT + p1] = gtok | (1 << 31);
        g_w[i1 * NT + p1]   = w1;
    }
}

// ---------------- expert layer 1: 512 threads, single fp16 term, A resident --------
#define E1_A    0
#define E1_B    83968
#define E1_SMEM 139264

__global__ __launch_bounds__(512, 1) void k_expert1(const float* __restrict__ be1) {
    int e = blockIdx.y;
    int cnt = g_cnt[e];
    int base = blockIdx.x * 128;
    if (base >= cnt) return;
    int nrows = min(128, cnt - base);

    extern __shared__ char smraw[];
    uint32_t smb = smem_u32(smraw);

    __shared__ int s_tok[128];
    __shared__ int s_dst[128];

    int tid = threadIdx.x, wid = tid >> 5, lane = tid & 31;
    if (tid < 128) {
        int r = tid;
        int rr = (r < nrows) ? r : 0;
        int ent = g_tok[e * NT + base + rr];
        int tok = ent & 0x7FFFFFFF;
        s_tok[r] = tok;
        s_dst[r] = (r < nrows) ? (int)((((unsigned)ent) >> 31) * NT + tok) : -1;
    }
    __syncthreads();

    int wm = wid & 3, wn = wid >> 2, lq = lane >> 2, lr = lane & 3;

    // prologue: stage full A (fp16 hi only)
    {
        int row = tid >> 2, q = tid & 3;
        const char* srch = (const char*)(g_xh + (size_t)s_tok[row] * DIN);
        uint32_t dh = smb + E1_A + (uint32_t)(row * 656);
#pragma unroll
        for (int j = 0; j < 10; j++) {
            int g = q * 10 + j;
            cp16(dh + g * 16, srch + g * 16);
        }
        cp_commit();
    }
    auto stageB = [&](int c) {
        int nc = c / 5, kc = c - nc * 5;
        uint32_t b = smb + E1_B + (uint32_t)(c % 3) * 18432;
        const char* B1 = (const char*)(g_B1 + (((size_t)(e * 5 + kc) * 512) + nc * 128) * 64);
#pragma unroll
        for (int i4 = 0; i4 < 2; i4++) {
            int idx = tid + i4 * 512;
            int r = idx >> 3, su = idx & 7;
            cp16(b + (uint32_t)(r * 144 + su * 16), B1 + r * 128 + su * 16);
        }
        cp_commit();
    };
    stageB(0);
    stageB(1);

    uint32_t abase = smb + E1_A + (uint32_t)((wm * 32 + (lane & 15)) * 656 + ((lane >> 4) << 4));
    uint32_t bbase = (uint32_t)((wn * 32 + (lane & 15)) * 144 + ((lane >> 4) << 4));

    float acc[2][4][4];
    for (int c = 0; c < 20; c++) {
        int nc = c / 5, kc = c - nc * 5;
        cp_wait1();
        __syncthreads();
        if (c + 2 < 20) stageB(c + 2); else cp_commit();

        if (kc == 0) {
#pragma unroll
            for (int mt = 0; mt < 2; mt++)
#pragma unroll
                for (int nt = 0; nt < 4; nt++)
#pragma unroll
                    for (int j = 0; j < 4; j++) acc[mt][nt][j] = 0.f;
        }
        uint32_t bb = smb + E1_B + (uint32_t)(c % 3) * 18432 + bbase;
        uint32_t ab = abase + (uint32_t)(kc * 128);
#pragma unroll
        for (int s = 0; s < 4; s++) {
            uint32_t ah[2][4], bq[2][4];
#pragma unroll
            for (int mt = 0; mt < 2; mt++)
                ldsm_x4(ah[mt], ab + (uint32_t)(mt * 10496 + s * 32));
#pragma unroll
            for (int g = 0; g < 2; g++)
                ldsm_x4(bq[g], bb + (uint32_t)(g * 2304 + s * 32));
#pragma unroll
            for (int g = 0; g < 2; g++) {
                uint32_t bhe[2] = {bq[g][0], bq[g][2]}, bho[2] = {bq[g][1], bq[g][3]};
#pragma unroll
                for (int mt = 0; mt < 2; mt++) {
                    mma_f16(acc[mt][2 * g],     ah[mt], bhe);
                    mma_f16(acc[mt][2 * g + 1], ah[mt], bho);
                }
            }
        }

        if (kc == 4) {
            const float* b1 = be1 + e * DH + nc * 128;
#pragma unroll
            for (int mt = 0; mt < 2; mt++)
#pragma unroll
                for (int nt = 0; nt < 4; nt++) {
                    int col = wn * 32 + nt * 8 + lr * 2;
                    float bb0 = b1[col], bb1 = b1[col + 1];
#pragma unroll
                    for (int h = 0; h < 2; h++) {
                        int row = wm * 32 + mt * 16 + lq + h * 8;
                        int dst = s_dst[row];
                        if (dst >= 0) {
                            float v0 = gelu_fast(acc[mt][nt][2 * h]     + bb0);
                            float v1 = gelu_fast(acc[mt][nt][2 * h + 1] + bb1);
                            __half h0 = __float2half_rn(v0), h1 = __float2half_rn(v1);
                            uint32_t ph = (uint32_t)__half_as_ushort(h0) | ((uint32_t)__half_as_ushort(h1) << 16);
                            size_t widx = ((size_t)dst * DH + nc * 128 + col) >> 1;
                            ((uint32_t*)g_heh)[widx] = ph;
                        }
                    }
                }
        }
    }
}

// ---------------- expert layer 2: 512 threads, single fp16 term, dual-nc acc -------
#define E2_A    0
#define E2_B    67584
#define E2_SMEM 122880

__global__ __launch_bounds__(512, 1) void k_expert2(const float* __restrict__ be2) {
    int e = blockIdx.y;
    int cnt = g_cnt[e];
    int base = blockIdx.x * 128;
    if (base >= cnt) return;
    int nrows = min(128, cnt - base);

    extern __shared__ char smraw[];
    uint32_t smb = smem_u32(smraw);

    __shared__ int   s_row[128];
    __shared__ int   s_dst[128];
    __shared__ float s_w[128];

    int tid = threadIdx.x, wid = tid >> 5, lane = tid & 31;
    if (tid < 128) {
        int r = tid;
        int rr = (r < nrows) ? r : 0;
        int ent = g_tok[e * NT + base + rr];
        int tok = ent & 0x7FFFFFFF;
        int herow = (int)((((unsigned)ent) >> 31) * NT + tok);
        s_row[r] = herow;
        s_dst[r] = (r < nrows) ? herow : -1;
        s_w[r]   = g_w[e * NT + base + rr];
    }
    __syncthreads();

    int wm = wid & 3, wn = wid >> 2, lq = lane >> 2, lr = lane & 3;

    uint32_t abase = smb + E2_A + (uint32_t)((wm * 32 + (lane & 15)) * 528 + ((lane >> 4) << 4));
    uint32_t bbase = (uint32_t)((wn * 32 + (lane & 15)) * 144 + ((lane >> 4) << 4));

    auto stageB = [&](int cgl) {
        int j = cgl & 7, kh = cgl >> 3;
        int nc = j >> 2, kcl = j & 3;
        int kc = kh * 4 + kcl;
        uint32_t b = smb + E2_B + (uint32_t)(cgl % 3) * 18432;
        const char* B2 = (const char*)(g_B2 + (((size_t)(e * 8 + kc) * 256) + nc * 128) * 64);
#pragma unroll
        for (int i4 = 0; i4 < 2; i4++) {
            int idx = tid + i4 * 512;
            int r = idx >> 3, su = idx & 7;
            cp16(b + (uint32_t)(r * 144 + su * 16), B2 + r * 128 + su * 16);
        }
        cp_commit();
    };

    float acc[2][2][4][4];
#pragma unroll
    for (int nc = 0; nc < 2; nc++)
#pragma unroll
        for (int mt = 0; mt < 2; mt++)
#pragma unroll
            for (int nt = 0; nt < 4; nt++)
#pragma unroll
                for (int j = 0; j < 4; j++) acc[nc][mt][nt][j] = 0.f;

    for (int kh = 0; kh < 2; kh++) {
        __syncthreads();
        {
            int row = tid >> 2, q = tid & 3;
            const char* srch = (const char*)(g_heh + (size_t)s_row[row] * DH + kh * 256);
            uint32_t dh = smb + E2_A + (uint32_t)(row * 528);
#pragma unroll
            for (int j = 0; j < 8; j++) {
                int g = q * 8 + j;
                cp16(dh + g * 16, srch + g * 16);
            }
            cp_commit();
        }
        stageB(kh * 8);
        stageB(kh * 8 + 1);

        for (int j = 0; j < 8; j++) {
            int cgl = kh * 8 + j;
            int nc = j >> 2, kcl = j & 3;
            cp_wait1();
            __syncthreads();
            if (j + 2 < 8) stageB(cgl + 2); else cp_commit();

            uint32_t bb = smb + E2_B + (uint32_t)(cgl % 3) * 18432 + bbase;
            uint32_t ab = abase + (uint32_t)(kcl * 128);
#pragma unroll
            for (int s = 0; s < 4; s++) {
                uint32_t ah[2][4], bq[2][4];
#pragma unroll
                for (int mt = 0; mt < 2; mt++)
                    ldsm_x4(ah[mt], ab + (uint32_t)(mt * 8448 + s * 32));
#pragma unroll
                for (int g = 0; g < 2; g++)
                    ldsm_x4(bq[g], bb + (uint32_t)(g * 2304 + s * 32));
#pragma unroll
                for (int g = 0; g < 2; g++) {
                    uint32_t bhe[2] = {bq[g][0], bq[g][2]}, bho[2] = {bq[g][1], bq[g][3]};
#pragma unroll
                    for (int mt = 0; mt < 2; mt++) {
                        mma_f16(acc[nc][mt][2 * g],     ah[mt], bhe);
                        mma_f16(acc[nc][mt][2 * g + 1], ah[mt], bho);
                    }
                }
            }
        }
    }

    // epilogue: gate-scaled bias add -> g_part
#pragma unroll
    for (int nc = 0; nc < 2; nc++) {
        const float* b2 = be2 + e * DD + nc * 128;
#pragma unroll
        for (int mt = 0; mt < 2; mt++)
#pragma unroll
            for (int nt = 0; nt < 4; nt++) {
                int col = wn * 32 + nt * 8 + lr * 2;
                float bb0 = b2[col], bb1 = b2[col + 1];
#pragma unroll
                for (int h = 0; h < 2; h++) {
                    int row = wm * 32 + mt * 16 + lq + h * 8;
                    int dst = s_dst[row];
                    if (dst >= 0) {
                        float wgt = s_w[row];
                        float2 o;
                        o.x = wgt * (acc[nc][mt][nt][2 * h]     + bb0);
                        o.y = wgt * (acc[nc][mt][nt][2 * h + 1] + bb1);
                        *(float2*)&g_part[(size_t)dst * DD + nc * 128 + col] = o;
                    }
                }
            }
    }
}

// ---------------- K4: combine slot partials ----------------
__global__ void k_combine(float* __restrict__ out) {
    int i = blockIdx.x * blockDim.x + threadIdx.x;
    const float4* p0 = (const float4*)g_part;
    const float4* p1 = (const float4*)(g_part + (size_t)NT * DD);
    float4 a = p0[i], b = p1[i];
    float4 r;
    r.x = a.x + b.x; r.y = a.y + b.y; r.z = a.z + b.z; r.w = a.w + b.w;
    ((float4*)out)[i] = r;
}

// ---------------- launch ----------------
extern "C" void kernel_launch(void* const* d_in, const int* in_sizes, int n_in,
                              void* d_out, int out_size) {
    const float* hidden = (const float*)d_in[0];
    const float* feat   = (const float*)d_in[1];
    const float* Wf     = (const float*)d_in[2];
    const float* bf     = (const float*)d_in[3];
    const float* Wr1    = (const float*)d_in[4];
    const float* br1    = (const float*)d_in[5];
    const float* Wr2    = (const float*)d_in[6];
    const float* br2    = (const float*)d_in[7];
    const float* We1    = (const float*)d_in[8];
    const float* be1    = (const float*)d_in[9];
    const float* We2    = (const float*)d_in[10];
    const float* be2    = (const float*)d_in[11];
    float* out = (float*)d_out;

    const int r_smem = R_SMEM_FLOATS * 4;
    cudaFuncSetAttribute(k_router,  cudaFuncAttributeMaxDynamicSharedMemorySize, r_smem);
    cudaFuncSetAttribute(k_expert1, cudaFuncAttributeMaxDynamicSharedMemorySize, E1_SMEM);
    cudaFuncSetAttribute(k_expert2, cudaFuncAttributeMaxDynamicSharedMemorySize, E2_SMEM);

    k_build_x<<<NT, DIN>>>(hidden, feat, Wf, bf);
    k_prep<<<576, 256>>>(We1, We2);
    k_router<<<NT / 32, 256, r_smem>>>(Wr1, br1, Wr2, br2, out);
    k_expert1<<<dim3(64, EE), 512, E1_SMEM>>>(be1);
    k_expert2<<<dim3(64, EE), 512, E2_SMEM>>>(be2);
    k_combine<<<(NT * DD / 4) / 256, 256>>>(out);
}

// round 12
// speedup vs baseline: 1.7966x; 1.0333x over previous
#include <cuda_runtime.h>
#include <cuda_fp16.h>
#include <math.h>
#include <stdint.h>

#define NT   8192
#define DD   256
#define FF   8
#define DFE  64
#define DIN  320
#define DR   256
#define EE   8
#define DH   512

// ---------------- device-global scratch ----------------
__device__ __align__(16) float g_x[NT * DIN];
__device__ int                 g_cnt[EE];
__device__ int                 g_tok[EE * NT];
__device__ float               g_w[EE * NT];
__device__ __align__(16) __half g_xh[NT * DIN];     // fp16 x
__device__ __align__(16) __half g_heh[2 * NT * DH]; // fp16 he
// pre-transposed n-major fp16 weights: B1 [e][kc=5][n=512][k=64], B2 [e][kc=8][n=256][k=64]
__device__ __align__(16) __half g_B1[EE * 5 * 512 * 64];
__device__ __align__(16) __half g_B2[EE * 8 * 256 * 64];

// ---------------- helpers ----------------
__device__ __forceinline__ float gelu_tanh(float v) {
    float u = 0.7978845608028654f * (v + 0.044715f * v * v * v);
    return 0.5f * v * (1.0f + tanhf(u));
}
__device__ __forceinline__ float gelu_fast(float v) {
    float u = 0.7978845608028654f * (v + 0.044715f * v * v * v);
    return v / (1.0f + __expf(-2.0f * u));
}
__device__ __forceinline__ uint32_t smem_u32(const void* p) {
    uint32_t a;
    asm("{ .reg .u64 t; cvta.to.shared.u64 t, %1; cvt.u32.u64 %0, t; }" : "=r"(a) : "l"(p));
    return a;
}
__device__ __forceinline__ void mma_f16(float* d, const uint32_t* a, const uint32_t* b) {
    asm volatile(
        "mma.sync.aligned.m16n8k16.row.col.f32.f16.f16.f32 "
        "{%0,%1,%2,%3}, {%4,%5,%6,%7}, {%8,%9}, {%0,%1,%2,%3};"
        : "+f"(d[0]), "+f"(d[1]), "+f"(d[2]), "+f"(d[3])
        : "r"(a[0]), "r"(a[1]), "r"(a[2]), "r"(a[3]), "r"(b[0]), "r"(b[1]));
}
__device__ __forceinline__ void ldsm_x4(uint32_t* r, uint32_t a) {
    asm volatile("ldmatrix.sync.aligned.m8n8.x4.shared.b16 {%0,%1,%2,%3}, [%4];"
        : "=r"(r[0]), "=r"(r[1]), "=r"(r[2]), "=r"(r[3]) : "r"(a));
}
__device__ __forceinline__ void cp16(uint32_t dst, const void* src) {
    asm volatile("cp.async.cg.shared.global [%0], [%1], 16;" :: "r"(dst), "l"(src));
}
__device__ __forceinline__ void cp_commit() {
    asm volatile("cp.async.commit_group;" ::: "memory");
}
__device__ __forceinline__ void cp_wait1() {
    asm volatile("cp.async.wait_group 1;" ::: "memory");
}

// ---------------- K0: zero the stage_delta region of out ----------------
__global__ void k_zero(float* __restrict__ out) {
    int i = blockIdx.x * blockDim.x + threadIdx.x;
    ((float4*)out)[i] = make_float4(0.f, 0.f, 0.f, 0.f);
}

// ---------------- K1: build x + fp16 cast (+ counter reset in block 0) ----------------
__global__ void k_build_x(const float* __restrict__ hidden,
                          const float* __restrict__ feat,
                          const float* __restrict__ Wf,
                          const float* __restrict__ bf) {
    int tok = blockIdx.x;
    int t = threadIdx.x;
    if (blockIdx.x == 0 && t < EE) g_cnt[t] = 0;
    float v;
    if (t < DD) {
        v = hidden[tok * DD + t];
    } else {
        int j = t - DD;
        float acc = bf[j];
#pragma unroll
        for (int k = 0; k < FF; k++) acc += feat[tok * FF + k] * Wf[k * DFE + j];
        v = acc;
    }
    g_x[tok * DIN + t] = v;
    g_xh[tok * DIN + t] = __float2half_rn(v);
}

// ---------------- K2: merged weight prep (transpose to n-major fp16) ----------------
__global__ void k_prep(const float* __restrict__ We1, const float* __restrict__ We2) {
    __shared__ float tile[64][65];
    int bx = blockIdx.x;
    int tid = threadIdx.x;
    if (bx < 320) {
        int hb = bx & 7, kc = (bx >> 3) % 5, e = bx / 40;
#pragma unroll
        for (int i = 0; i < 16; i++) {
            int li = i * 256 + tid;
            int ki = li >> 6, hi = li & 63;
            tile[ki][hi] = We1[((size_t)e * DIN + kc * 64 + ki) * DH + hb * 64 + hi];
        }
        __syncthreads();
#pragma unroll
        for (int i = 0; i < 16; i++) {
            int li = i * 256 + tid;
            int kk = li & 63, hr = li >> 6;
            size_t dst = (((size_t)(e * 5 + kc) * 512) + hb * 64 + hr) * 64 + kk;
            g_B1[dst] = __float2half_rn(tile[kk][hr]);
        }
    } else {
        int b2 = bx - 320;
        int ob = b2 & 3, kc = (b2 >> 2) & 7, e = b2 >> 5;
#pragma unroll
        for (int i = 0; i < 16; i++) {
            int li = i * 256 + tid;
            int ki = li >> 6, oi = li & 63;
            tile[ki][oi] = We2[((size_t)e * DH + kc * 64 + ki) * DD + ob * 64 + oi];
        }
        __syncthreads();
#pragma unroll
        for (int i = 0; i < 16; i++) {
            int li = i * 256 + tid;
            int kk = li & 63, orr = li >> 6;
            size_t dst = (((size_t)(e * 8 + kc) * 256) + ob * 64 + orr) * 64 + kk;
            g_B2[dst] = __float2half_rn(tile[kk][orr]);
        }
    }
}

// ---------------- K3: router (logit-exact fp32 SIMT) ----------------
#define R_SMEM_FLOATS (320 * 33 + 32 * 256)
__global__ __launch_bounds__(256, 2) void k_router(
    const float* __restrict__ Wr1, const float* __restrict__ br1,
    const float* __restrict__ Wr2, const float* __restrict__ br2,
    float* __restrict__ out) {
    extern __shared__ float sm[];
    float* xT  = sm;
    float* wch = sm + 320 * 33;
    float* hrT = sm;
    float* ws2 = wch;
    float* lg  = wch + 2048;

    int tid  = threadIdx.x;
    int base = blockIdx.x * 32;

    for (int idx = tid; idx < 32 * DIN; idx += 256) {
        int r = idx / DIN;
        int k = idx - r * DIN;
        xT[k * 33 + r] = g_x[(base + r) * DIN + k];
    }

    int tg = tid >> 5;
    int cg = tid & 31;

    float acc[2][4][4];
#pragma unroll
    for (int m = 0; m < 2; m++)
#pragma unroll
        for (int tt = 0; tt < 4; tt++)
#pragma unroll
            for (int j = 0; j < 4; j++) acc[m][tt][j] = 0.f;

    for (int kc = 0; kc < DIN; kc += 32) {
#pragma unroll
        for (int i = 0; i < 32; i++) {
            int idx = tid + i * 256;
            int kk = idx >> 8;
            int c  = idx & 255;
            wch[kk * 256 + c] = Wr1[(kc + kk) * DR + c];
        }
        __syncthreads();
#pragma unroll 2
        for (int k = 0; k < 32; k++) {
            float xv[4];
#pragma unroll
            for (int tt = 0; tt < 4; tt++) xv[tt] = xT[(kc + k) * 33 + 4 * tg + tt];
#pragma unroll
            for (int m = 0; m < 2; m++) {
                float4 wq = *(const float4*)&wch[k * 256 + 128 * m + 4 * cg];
#pragma unroll
                for (int tt = 0; tt < 4; tt++) {
                    acc[m][tt][0] += xv[tt] * wq.x;
                    acc[m][tt][1] += xv[tt] * wq.y;
                    acc[m][tt][2] += xv[tt] * wq.z;
                    acc[m][tt][3] += xv[tt] * wq.w;
                }
            }
        }
        __syncthreads();
    }

#pragma unroll
    for (int m = 0; m < 2; m++)
#pragma unroll
        for (int j = 0; j < 4; j++) {
            int col = 4 * cg + 128 * m + j;
            float b = br1[col];
#pragma unroll
            for (int tt = 0; tt < 4; tt++)
                hrT[col * 33 + 4 * tg + tt] = gelu_tanh(acc[m][tt][j] + b);
        }
    for (int idx = tid; idx < DR * EE; idx += 256) ws2[idx] = Wr2[idx];
    __syncthreads();

    {
        int e = tid >> 5;
        int r = tid & 31;
        float lacc = br2[e];
#pragma unroll 4
        for (int k = 0; k < DR; k++) lacc += hrT[k * 33 + r] * ws2[k * EE + e];
        lg[r * EE + e] = lacc;
        out[(size_t)NT * DD + (size_t)NT * EE + (size_t)(base + r) * EE + e] = lacc;
    }
    __syncthreads();

    if (tid < 32) {
        int r = tid;
        int gtok = base + r;
        float v[EE];
#pragma unroll
        for (int e = 0; e < EE; e++) v[e] = lg[r * EE + e];
        int i0 = 0;
#pragma unroll
        for (int e = 1; e < EE; e++)
            if (v[e] > v[i0]) i0 = e;
        int i1 = (i0 == 0) ? 1 : 0;
#pragma unroll
        for (int e = 0; e < EE; e++) {
            if (e == i0) continue;
            if (v[e] > v[i1]) i1 = e;
        }
        float t  = expf(v[i1] - v[i0]);
        float s  = 1.0f + t;
        float w0 = 1.0f / s;
        float w1 = t / s;
        float* gw = out + (size_t)NT * DD + (size_t)gtok * EE;
#pragma unroll
        for (int e = 0; e < EE; e++)
            gw[e] = (e == i0) ? w0 : ((e == i1) ? w1 : 0.0f);
        int p0 = atomicAdd(&g_cnt[i0], 1);
        g_tok[i0 * NT + p0] = gtok;
        g_w[i0 * NT + p0]   = w0;
        int p1 = atomicAdd(&g_cnt[i1], 1);
        g_tok[i1 * NT + p1] = gtok | (1 << 31);
        g_w[i1 * NT + p1]   = w1;
    }
}

// ---------------- expert layer 1: M=64, 256 thr, 2 CTA/SM, A resident ---------------
#define E1_A    0
#define E1_B    41984
#define E1_SMEM 97280

__global__ __launch_bounds__(256, 2) void k_expert1(const float* __restrict__ be1) {
    int e = blockIdx.y;
    int cnt = g_cnt[e];
    int base = blockIdx.x * 64;
    if (base >= cnt) return;
    int nrows = min(64, cnt - base);

    extern __shared__ char smraw[];
    uint32_t smb = smem_u32(smraw);

    __shared__ int s_tok[64];
    __shared__ int s_dst[64];

    int tid = threadIdx.x, wid = tid >> 5, lane = tid & 31;
    if (tid < 64) {
        int r = tid;
        int rr = (r < nrows) ? r : 0;
        int ent = g_tok[e * NT + base + rr];
        int tok = ent & 0x7FFFFFFF;
        s_tok[r] = tok;
        s_dst[r] = (r < nrows) ? (int)((((unsigned)ent) >> 31) * NT + tok) : -1;
    }
    __syncthreads();

    int wm = wid & 1, wn = wid >> 1, lq = lane >> 2, lr = lane & 3;

    // prologue: stage full A (64 rows x 640B data, row stride 656B)
    {
        int row = tid >> 2, q = tid & 3;
        const char* srch = (const char*)(g_xh + (size_t)s_tok[row] * DIN);
        uint32_t dh = smb + E1_A + (uint32_t)(row * 656);
#pragma unroll
        for (int j = 0; j < 10; j++) {
            int g = q * 10 + j;
            cp16(dh + g * 16, srch + g * 16);
        }
        cp_commit();
    }
    auto stageB = [&](int c) {
        int nc = c / 5, kc = c - nc * 5;
        uint32_t b = smb + E1_B + (uint32_t)(c % 3) * 18432;
        const char* B1 = (const char*)(g_B1 + (((size_t)(e * 5 + kc) * 512) + nc * 128) * 64);
#pragma unroll
        for (int i4 = 0; i4 < 4; i4++) {
            int idx = tid + i4 * 256;
            int r = idx >> 3, su = idx & 7;
            cp16(b + (uint32_t)(r * 144 + su * 16), B1 + r * 128 + su * 16);
        }
        cp_commit();
    };
    stageB(0);
    stageB(1);

    uint32_t abase = smb + E1_A + (uint32_t)((wm * 32 + (lane & 15)) * 656 + ((lane >> 4) << 4));
    uint32_t bbase = (uint32_t)((wn * 32 + (lane & 15)) * 144 + ((lane >> 4) << 4));

    float acc[2][4][4];
    for (int c = 0; c < 20; c++) {
        int nc = c / 5, kc = c - nc * 5;
        cp_wait1();
        __syncthreads();
        if (c + 2 < 20) stageB(c + 2); else cp_commit();

        if (kc == 0) {
#pragma unroll
            for (int mt = 0; mt < 2; mt++)
#pragma unroll
                for (int nt = 0; nt < 4; nt++)
#pragma unroll
                    for (int j = 0; j < 4; j++) acc[mt][nt][j] = 0.f;
        }
        uint32_t bb = smb + E1_B + (uint32_t)(c % 3) * 18432 + bbase;
        uint32_t ab = abase + (uint32_t)(kc * 128);
#pragma unroll
        for (int s = 0; s < 4; s++) {
            uint32_t ah[2][4], bq[2][4];
#pragma unroll
            for (int mt = 0; mt < 2; mt++)
                ldsm_x4(ah[mt], ab + (uint32_t)(mt * 10496 + s * 32));
#pragma unroll
            for (int g = 0; g < 2; g++)
                ldsm_x4(bq[g], bb + (uint32_t)(g * 2304 + s * 32));
#pragma unroll
            for (int g = 0; g < 2; g++) {
                uint32_t bhe[2] = {bq[g][0], bq[g][2]}, bho[2] = {bq[g][1], bq[g][3]};
#pragma unroll
                for (int mt = 0; mt < 2; mt++) {
                    mma_f16(acc[mt][2 * g],     ah[mt], bhe);
                    mma_f16(acc[mt][2 * g + 1], ah[mt], bho);
                }
            }
        }

        if (kc == 4) {
            const float* b1 = be1 + e * DH + nc * 128;
#pragma unroll
            for (int mt = 0; mt < 2; mt++)
#pragma unroll
                for (int nt = 0; nt < 4; nt++) {
                    int col = wn * 32 + nt * 8 + lr * 2;
                    float bb0 = b1[col], bb1 = b1[col + 1];
#pragma unroll
                    for (int h = 0; h < 2; h++) {
                        int row = wm * 32 + mt * 16 + lq + h * 8;
                        int dst = s_dst[row];
                        if (dst >= 0) {
                            float v0 = gelu_fast(acc[mt][nt][2 * h]     + bb0);
                            float v1 = gelu_fast(acc[mt][nt][2 * h + 1] + bb1);
                            __half h0 = __float2half_rn(v0), h1 = __float2half_rn(v1);
                            uint32_t ph = (uint32_t)__half_as_ushort(h0) | ((uint32_t)__half_as_ushort(h1) << 16);
                            size_t widx = ((size_t)dst * DH + nc * 128 + col) >> 1;
                            ((uint32_t*)g_heh)[widx] = ph;
                        }
                    }
                }
        }
    }
}

// ---------------- expert layer 2: M=64, 256 thr, 2 CTA/SM, atomic epilogue ---------
#define E2_A    0
#define E2_B    33792
#define E2_SMEM 89088

__global__ __launch_bounds__(256, 2) void k_expert2(const float* __restrict__ be2,
                                                    float* __restrict__ out) {
    int e = blockIdx.y;
    int cnt = g_cnt[e];
    int base = blockIdx.x * 64;
    if (base >= cnt) return;
    int nrows = min(64, cnt - base);

    extern __shared__ char smraw[];
    uint32_t smb = smem_u32(smraw);

    __shared__ int   s_row[64];
    __shared__ int   s_tk[64];
    __shared__ float s_w[64];

    int tid = threadIdx.x, wid = tid >> 5, lane = tid & 31;
    if (tid < 64) {
        int r = tid;
        int rr = (r < nrows) ? r : 0;
        int ent = g_tok[e * NT + base + rr];
        int tok = ent & 0x7FFFFFFF;
        s_row[r] = (int)((((unsigned)ent) >> 31) * NT + tok);
        s_tk[r]  = (r < nrows) ? tok : -1;
        s_w[r]   = g_w[e * NT + base + rr];
    }
    __syncthreads();

    int wm = wid & 1, wn = wid >> 1, lq = lane >> 2, lr = lane & 3;

    uint32_t abase = smb + E2_A + (uint32_t)((wm * 32 + (lane & 15)) * 528 + ((lane >> 4) << 4));
    uint32_t bbase = (uint32_t)((wn * 32 + (lane & 15)) * 144 + ((lane >> 4) << 4));

    auto stageB = [&](int cgl) {
        int j = cgl & 7, kh = cgl >> 3;
        int nc = j >> 2, kcl = j & 3;
        int kc = kh * 4 + kcl;
        uint32_t b = smb + E2_B + (uint32_t)(cgl % 3) * 18432;
        const char* B2 = (const char*)(g_B2 + (((size_t)(e * 8 + kc) * 256) + nc * 128) * 64);
#pragma unroll
        for (int i4 = 0; i4 < 4; i4++) {
            int idx = tid + i4 * 256;
            int r = idx >> 3, su = idx & 7;
            cp16(b + (uint32_t)(r * 144 + su * 16), B2 + r * 128 + su * 16);
        }
        cp_commit();
    };

    float acc[2][2][4][4];
#pragma unroll
    for (int nc = 0; nc < 2; nc++)
#pragma unroll
        for (int mt = 0; mt < 2; mt++)
#pragma unroll
            for (int nt = 0; nt < 4; nt++)
#pragma unroll
                for (int j = 0; j < 4; j++) acc[nc][mt][nt][j] = 0.f;

    for (int kh = 0; kh < 2; kh++) {
        __syncthreads();
        {
            int row = tid >> 2, q = tid & 3;
            const char* srch = (const char*)(g_heh + (size_t)s_row[row] * DH + kh * 256);
            uint32_t dh = smb + E2_A + (uint32_t)(row * 528);
#pragma unroll
            for (int j = 0; j < 8; j++) {
                int g = q * 8 + j;
                cp16(dh + g * 16, srch + g * 16);
            }
            cp_commit();
        }
        stageB(kh * 8);
        stageB(kh * 8 + 1);

        for (int j = 0; j < 8; j++) {
            int cgl = kh * 8 + j;
            int nc = j >> 2, kcl = j & 3;
            cp_wait1();
            __syncthreads();
            if (j + 2 < 8) stageB(cgl + 2); else cp_commit();

            uint32_t bb = smb + E2_B + (uint32_t)(cgl % 3) * 18432 + bbase;
            uint32_t ab = abase + (uint32_t)(kcl * 128);
#pragma unroll
            for (int s = 0; s < 4; s++) {
                uint32_t ah[2][4], bq[2][4];
#pragma unroll
                for (int mt = 0; mt < 2; mt++)
                    ldsm_x4(ah[mt], ab + (uint32_t)(mt * 8448 + s * 32));
#pragma unroll
                for (int g = 0; g < 2; g++)
                    ldsm_x4(bq[g], bb + (uint32_t)(g * 2304 + s * 32));
#pragma unroll
                for (int g = 0; g < 2; g++) {
                    uint32_t bhe[2] = {bq[g][0], bq[g][2]}, bho[2] = {bq[g][1], bq[g][3]};
#pragma unroll
                    for (int mt = 0; mt < 2; mt++) {
                        mma_f16(acc[nc][mt][2 * g],     ah[mt], bhe);
                        mma_f16(acc[nc][mt][2 * g + 1], ah[mt], bho);
                    }
                }
            }
        }
    }

    // epilogue: gate-scaled bias add, atomicAdd into out (exactly 2 adds/elem, commutative)
#pragma unroll
    for (int nc = 0; nc < 2; nc++) {
        const float* b2 = be2 + e * DD + nc * 128;
#pragma unroll
        for (int mt = 0; mt < 2; mt++)
#pragma unroll
            for (int nt = 0; nt < 4; nt++) {
                int col = wn * 32 + nt * 8 + lr * 2;
                float bb0 = b2[col], bb1 = b2[col + 1];
#pragma unroll
                for (int h = 0; h < 2; h++) {
                    int row = wm * 32 + mt * 16 + lq + h * 8;
                    int tk = s_tk[row];
                    if (tk >= 0) {
                        float wgt = s_w[row];
                        float* dst = out + (size_t)tk * DD + nc * 128 + col;
                        atomicAdd(dst,     wgt * (acc[nc][mt][nt][2 * h]     + bb0));
                        atomicAdd(dst + 1, wgt * (acc[nc][mt][nt][2 * h + 1] + bb1));
                    }
                }
            }
    }
}

// ---------------- launch ----------------
extern "C" void kernel_launch(void* const* d_in, const int* in_sizes, int n_in,
                              void* d_out, int out_size) {
    const float* hidden = (const float*)d_in[0];
    const float* feat   = (const float*)d_in[1];
    const float* Wf     = (const float*)d_in[2];
    const float* bf     = (const float*)d_in[3];
    const float* Wr1    = (const float*)d_in[4];
    const float* br1    = (const float*)d_in[5];
    const float* Wr2    = (const float*)d_in[6];
    const float* br2    = (const float*)d_in[7];
    const float* We1    = (const float*)d_in[8];
    const float* be1    = (const float*)d_in[9];
    const float* We2    = (const float*)d_in[10];
    const float* be2    = (const float*)d_in[11];
    float* out = (float*)d_out;

    const int r_smem = R_SMEM_FLOATS * 4;
    cudaFuncSetAttribute(k_router,  cudaFuncAttributeMaxDynamicSharedMemorySize, r_smem);
    cudaFuncSetAttribute(k_expert1, cudaFuncAttributeMaxDynamicSharedMemorySize, E1_SMEM);
    cudaFuncSetAttribute(k_expert2, cudaFuncAttributeMaxDynamicSharedMemorySize, E2_SMEM);

    k_zero<<<(NT * DD / 4) / 256, 256>>>(out);
    k_build_x<<<NT, DIN>>>(hidden, feat, Wf, bf);
    k_prep<<<576, 256>>>(We1, We2);
    k_router<<<NT / 32, 256, r_smem>>>(Wr1, br1, Wr2, br2, out);
    k_expert1<<<dim3(128, EE), 256, E1_SMEM>>>(be1);
    k_expert2<<<dim3(128, EE), 256, E2_SMEM>>>(be2, out);
}

// round 13
// speedup vs baseline: 2.2559x; 1.2556x over previous
#include <cuda_runtime.h>
#include <cuda_fp16.h>
#include <math.h>
#include <stdint.h>

#define NT   8192
#define DD   256
#define FF   8
#define DFE  64
#define DIN  320
#define DR   256
#define EE   8
#define DH   512

// ---------------- device-global scratch ----------------
__device__ int                 g_cnt[EE];
__device__ int                 g_tok[EE * NT];
__device__ float               g_w[EE * NT];
__device__ __align__(16) __half g_xh[NT * DIN];     // fp16 hi of x
__device__ __align__(16) __half g_xl[NT * DIN];     // fp16 lo of x
__device__ __align__(16) __half g_heh[2 * NT * DH]; // fp16 he
// pre-transposed n-major fp16 weights
__device__ __align__(16) __half g_B1[EE * 5 * 512 * 64];   // [e][kc=5][n=512][k=64]
__device__ __align__(16) __half g_B2[EE * 8 * 256 * 64];   // [e][kc=8][n=256][k=64]
__device__ __align__(16) __half g_R1h[5 * 256 * 64];       // Wr1 hi [kc=5][n=256][k=64]
__device__ __align__(16) __half g_R1l[5 * 256 * 64];       // Wr1 lo

// ---------------- helpers ----------------
__device__ __forceinline__ float gelu_tanh(float v) {
    float u = 0.7978845608028654f * (v + 0.044715f * v * v * v);
    return 0.5f * v * (1.0f + tanhf(u));
}
__device__ __forceinline__ float gelu_fast(float v) {
    float u = 0.7978845608028654f * (v + 0.044715f * v * v * v);
    return v / (1.0f + __expf(-2.0f * u));
}
__device__ __forceinline__ uint32_t smem_u32(const void* p) {
    uint32_t a;
    asm("{ .reg .u64 t; cvta.to.shared.u64 t, %1; cvt.u32.u64 %0, t; }" : "=r"(a) : "l"(p));
    return a;
}
__device__ __forceinline__ void mma_f16(float* d, const uint32_t* a, const uint32_t* b) {
    asm volatile(
        "mma.sync.aligned.m16n8k16.row.col.f32.f16.f16.f32 "
        "{%0,%1,%2,%3}, {%4,%5,%6,%7}, {%8,%9}, {%0,%1,%2,%3};"
        : "+f"(d[0]), "+f"(d[1]), "+f"(d[2]), "+f"(d[3])
        : "r"(a[0]), "r"(a[1]), "r"(a[2]), "r"(a[3]), "r"(b[0]), "r"(b[1]));
}
__device__ __forceinline__ void ldsm_x4(uint32_t* r, uint32_t a) {
    asm volatile("ldmatrix.sync.aligned.m8n8.x4.shared.b16 {%0,%1,%2,%3}, [%4];"
        : "=r"(r[0]), "=r"(r[1]), "=r"(r[2]), "=r"(r[3]) : "r"(a));
}
__device__ __forceinline__ void cp16(uint32_t dst, const void* src) {
    asm volatile("cp.async.cg.shared.global [%0], [%1], 16;" :: "r"(dst), "l"(src));
}
__device__ __forceinline__ void cp_commit() {
    asm volatile("cp.async.commit_group;" ::: "memory");
}
__device__ __forceinline__ void cp_wait1() {
    asm volatile("cp.async.wait_group 1;" ::: "memory");
}

// ---------------- K0: zero the stage_delta region of out ----------------
__global__ void k_zero(float* __restrict__ out) {
    int i = blockIdx.x * blockDim.x + threadIdx.x;
    ((float4*)out)[i] = make_float4(0.f, 0.f, 0.f, 0.f);
}

// ---------------- K1: build x (fp16 hi/lo) + counter reset ----------------
__global__ void k_build_x(const float* __restrict__ hidden,
                          const float* __restrict__ feat,
                          const float* __restrict__ Wf,
                          const float* __restrict__ bf) {
    int tok = blockIdx.x;
    int t = threadIdx.x;
    if (blockIdx.x == 0 && t < EE) g_cnt[t] = 0;
    float v;
    if (t < DD) {
        v = hidden[tok * DD + t];
    } else {
        int j = t - DD;
        float acc = bf[j];
#pragma unroll
        for (int k = 0; k < FF; k++) acc += feat[tok * FF + k] * Wf[k * DFE + j];
        v = acc;
    }
    __half h = __float2half_rn(v);
    g_xh[tok * DIN + t] = h;
    g_xl[tok * DIN + t] = __float2half_rn(v - __half2float(h));
}

// ---------------- K2: weight prep (transpose to n-major fp16; Wr1 hi/lo) ------------
__global__ void k_prep(const float* __restrict__ We1, const float* __restrict__ We2,
                       const float* __restrict__ Wr1) {
    __shared__ float tile[64][65];
    int bx = blockIdx.x;
    int tid = threadIdx.x;
    if (bx < 320) {
        int hb = bx & 7, kc = (bx >> 3) % 5, e = bx / 40;
#pragma unroll
        for (int i = 0; i < 16; i++) {
            int li = i * 256 + tid;
            int ki = li >> 6, hi = li & 63;
            tile[ki][hi] = We1[((size_t)e * DIN + kc * 64 + ki) * DH + hb * 64 + hi];
        }
        __syncthreads();
#pragma unroll
        for (int i = 0; i < 16; i++) {
            int li = i * 256 + tid;
            int kk = li & 63, hr = li >> 6;
            size_t dst = (((size_t)(e * 5 + kc) * 512) + hb * 64 + hr) * 64 + kk;
            g_B1[dst] = __float2half_rn(tile[kk][hr]);
        }
    } else if (bx < 576) {
        int b2 = bx - 320;
        int ob = b2 & 3, kc = (b2 >> 2) & 7, e = b2 >> 5;
#pragma unroll
        for (int i = 0; i < 16; i++) {
            int li = i * 256 + tid;
            int ki = li >> 6, oi = li & 63;
            tile[ki][oi] = We2[((size_t)e * DH + kc * 64 + ki) * DD + ob * 64 + oi];
        }
        __syncthreads();
#pragma unroll
        for (int i = 0; i < 16; i++) {
            int li = i * 256 + tid;
            int kk = li & 63, orr = li >> 6;
            size_t dst = (((size_t)(e * 8 + kc) * 256) + ob * 64 + orr) * 64 + kk;
            g_B2[dst] = __float2half_rn(tile[kk][orr]);
        }
    } else {
        int b3 = bx - 576;          // 20 blocks: nb(4) x kc(5)
        int nb = b3 & 3, kc = b3 >> 2;
#pragma unroll
        for (int i = 0; i < 16; i++) {
            int li = i * 256 + tid;
            int ki = li >> 6, ni = li & 63;
            tile[ki][ni] = Wr1[(kc * 64 + ki) * DR + nb * 64 + ni];
        }
        __syncthreads();
#pragma unroll
        for (int i = 0; i < 16; i++) {
            int li = i * 256 + tid;
            int kk = li & 63, nr = li >> 6;
            float v = tile[kk][nr];
            __half h = __float2half_rn(v);
            __half l = __float2half_rn(v - __half2float(h));
            size_t dst = ((size_t)kc * 256 + nb * 64 + nr) * 64 + kk;
            g_R1h[dst] = h;
            g_R1l[dst] = l;
        }
    }
}

// ---------------- K3: router — HMMA 3-term GEMM1, fp32 GEMM2, top-2 gating ----------
// smem: Ah [0,41984) 64x656B ; Al [41984,83968) ; B 3 x 36864 (hi 18432 + lo 18432)
// post-GEMM1 overlay on A region: hr 64x264 fp32 [0,67584); lg [67584,69632);
// ws2T 8x260 fp32 [69632,77952)
#define RT_AL   41984
#define RT_B    83968
#define RT_SMEM (83968 + 3 * 36864)

__global__ __launch_bounds__(256, 1) void k_router_mma(
    const float* __restrict__ br1,
    const float* __restrict__ Wr2, const float* __restrict__ br2,
    float* __restrict__ out) {
    extern __shared__ char smraw[];
    uint32_t smb = smem_u32(smraw);
    float* smf = (float*)smraw;

    int tid = threadIdx.x, wid = tid >> 5, lane = tid & 31;
    int base = blockIdx.x * 64;
    int wm = wid & 1, wn = wid >> 1, lq = lane >> 2, lr = lane & 3;

    // stage A: x hi/lo for 64 tokens (contiguous token block)
    {
        int row = tid >> 2, q = tid & 3;
        const char* sh = (const char*)(g_xh + (size_t)(base + row) * DIN);
        const char* sl = (const char*)(g_xl + (size_t)(base + row) * DIN);
        uint32_t dh = smb + (uint32_t)(row * 656);
        uint32_t dl = smb + RT_AL + (uint32_t)(row * 656);
#pragma unroll
        for (int j = 0; j < 10; j++) {
            int g = q * 10 + j;
            cp16(dh + g * 16, sh + g * 16);
            cp16(dl + g * 16, sl + g * 16);
        }
        cp_commit();
    }
    auto stageB = [&](int c) {
        int kc = c >> 1, nc = c & 1;
        uint32_t b = smb + RT_B + (uint32_t)(c % 3) * 36864;
        const char* Bh = (const char*)(g_R1h + ((size_t)kc * 256 + nc * 128) * 64);
        const char* Bl = (const char*)(g_R1l + ((size_t)kc * 256 + nc * 128) * 64);
#pragma unroll
        for (int i4 = 0; i4 < 4; i4++) {
            int idx = tid + i4 * 256;
            int r = idx >> 3, su = idx & 7;
            cp16(b + (uint32_t)(r * 144 + su * 16), Bh + r * 128 + su * 16);
            cp16(b + 18432 + (uint32_t)(r * 144 + su * 16), Bl + r * 128 + su * 16);
        }
        cp_commit();
    };
    stageB(0);
    stageB(1);

    uint32_t abase = smb + (uint32_t)((wm * 32 + (lane & 15)) * 656 + ((lane >> 4) << 4));
    uint32_t bbase = (uint32_t)((wn * 32 + (lane & 15)) * 144 + ((lane >> 4) << 4));

    float acc[2][2][4][4];   // [nc][mt][nt][j]
#pragma unroll
    for (int nc = 0; nc < 2; nc++)
#pragma unroll
        for (int mt = 0; mt < 2; mt++)
#pragma unroll
            for (int nt = 0; nt < 4; nt++)
#pragma unroll
                for (int j = 0; j < 4; j++) acc[nc][mt][nt][j] = 0.f;

    for (int c = 0; c < 10; c++) {
        int kc = c >> 1, nc = c & 1;
        cp_wait1();
        __syncthreads();
        if (c + 2 < 10) stageB(c + 2); else cp_commit();

        uint32_t bb = smb + RT_B + (uint32_t)(c % 3) * 36864 + bbase;
        uint32_t ab = abase + (uint32_t)(kc * 128);
#pragma unroll
        for (int s = 0; s < 4; s++) {
            uint32_t ah[2][4], al[2][4], bh[2][4], bl[2][4];
#pragma unroll
            for (int mt = 0; mt < 2; mt++) {
                uint32_t a = ab + (uint32_t)(mt * 10496 + s * 32);
                ldsm_x4(ah[mt], a);
                ldsm_x4(al[mt], a + RT_AL);
            }
#pragma unroll
            for (int g = 0; g < 2; g++) {
                uint32_t bo = bb + (uint32_t)(g * 2304 + s * 32);
                ldsm_x4(bh[g], bo);
                ldsm_x4(bl[g], bo + 18432);
            }
#pragma unroll
            for (int g = 0; g < 2; g++) {
                uint32_t bhe[2] = {bh[g][0], bh[g][2]}, bho[2] = {bh[g][1], bh[g][3]};
                uint32_t ble[2] = {bl[g][0], bl[g][2]}, blo[2] = {bl[g][1], bl[g][3]};
#pragma unroll
                for (int mt = 0; mt < 2; mt++) {
                    mma_f16(acc[nc][mt][2 * g],     ah[mt], bhe);
                    mma_f16(acc[nc][mt][2 * g],     ah[mt], ble);
                    mma_f16(acc[nc][mt][2 * g],     al[mt], bhe);
                    mma_f16(acc[nc][mt][2 * g + 1], ah[mt], bho);
                    mma_f16(acc[nc][mt][2 * g + 1], ah[mt], blo);
                    mma_f16(acc[nc][mt][2 * g + 1], al[mt], bho);
                }
            }
        }
    }
    __syncthreads();   // all MMAs done; A region reusable

    // GEMM1 epilogue: hr = gelu(acc + br1) -> smem hr[64][264]
#pragma unroll
    for (int nc = 0; nc < 2; nc++)
#pragma unroll
        for (int mt = 0; mt < 2; mt++)
#pragma unroll
            for (int nt = 0; nt < 4; nt++) {
                int col = nc * 128 + wn * 32 + nt * 8 + lr * 2;
                float b0 = br1[col], b1 = br1[col + 1];
#pragma unroll
                for (int h = 0; h < 2; h++) {
                    int row = wm * 32 + mt * 16 + lq + h * 8;
                    smf[row * 264 + col]     = gelu_tanh(acc[nc][mt][nt][2 * h]     + b0);
                    smf[row * 264 + col + 1] = gelu_tanh(acc[nc][mt][nt][2 * h + 1] + b1);
                }
            }
    // stage Wr2 transposed: ws2T[e][k] at float offset 17408, row stride 260
#pragma unroll
    for (int i = 0; i < 8; i++) {
        int idx = tid + i * 256;
        int k = idx >> 3, e = idx & 7;
        smf[17408 + e * 260 + k] = Wr2[k * EE + e];
    }
    __syncthreads();

    // GEMM2: logits (fp32, exact)
    {
        int e = tid & 7, t0 = tid >> 3;
        float a0 = br2[e], a1 = br2[e];
        const float* hr0 = smf + t0 * 264;
        const float* hr1 = smf + (t0 + 32) * 264;
        const float* w2  = smf + 17408 + e * 260;
#pragma unroll 8
        for (int k = 0; k < DR; k += 4) {
            float4 w  = *(const float4*)(w2 + k);
            float4 h0 = *(const float4*)(hr0 + k);
            float4 h1 = *(const float4*)(hr1 + k);
            a0 += h0.x * w.x + h0.y * w.y + h0.z * w.z + h0.w * w.w;
            a1 += h1.x * w.x + h1.y * w.y + h1.z * w.z + h1.w * w.w;
        }
        smf[16896 + t0 * 8 + e] = a0;
        smf[16896 + (t0 + 32) * 8 + e] = a1;
        float* lo = out + (size_t)NT * DD + (size_t)NT * EE;
        lo[(size_t)(base + t0) * EE + e] = a0;
        lo[(size_t)(base + t0 + 32) * EE + e] = a1;
    }
    __syncthreads();

    // top-2 gating (64 tokens)
    if (tid < 64) {
        int gtok = base + tid;
        float v[EE];
#pragma unroll
        for (int e = 0; e < EE; e++) v[e] = smf[16896 + tid * 8 + e];
        int i0 = 0;
#pragma unroll
        for (int e = 1; e < EE; e++)
            if (v[e] > v[i0]) i0 = e;
        int i1 = (i0 == 0) ? 1 : 0;
#pragma unroll
        for (int e = 0; e < EE; e++) {
            if (e == i0) continue;
            if (v[e] > v[i1]) i1 = e;
        }
        float t  = expf(v[i1] - v[i0]);
        float s  = 1.0f + t;
        float w0 = 1.0f / s;
        float w1 = t / s;
        float* gw = out + (size_t)NT * DD + (size_t)gtok * EE;
#pragma unroll
        for (int e = 0; e < EE; e++)
            gw[e] = (e == i0) ? w0 : ((e == i1) ? w1 : 0.0f);
        int p0 = atomicAdd(&g_cnt[i0], 1);
        g_tok[i0 * NT + p0] = gtok;
        g_w[i0 * NT + p0]   = w0;
        int p1 = atomicAdd(&g_cnt[i1], 1);
        g_tok[i1 * NT + p1] = gtok | (1 << 31);
        g_w[i1 * NT + p1]   = w1;
    }
}

// ---------------- expert layer 1: M=64, 256 thr, 2 CTA/SM, A resident ---------------
#define E1_A    0
#define E1_B    41984
#define E1_SMEM 97280

__global__ __launch_bounds__(256, 2) void k_expert1(const float* __restrict__ be1) {
    int e = blockIdx.y;
    int cnt = g_cnt[e];
    int base = blockIdx.x * 64;
    if (base >= cnt) return;
    int nrows = min(64, cnt - base);

    extern __shared__ char smraw[];
    uint32_t smb = smem_u32(smraw);

    __shared__ int s_tok[64];
    __shared__ int s_dst[64];

    int tid = threadIdx.x, wid = tid >> 5, lane = tid & 31;
    if (tid < 64) {
        int r = tid;
        int rr = (r < nrows) ? r : 0;
        int ent = g_tok[e * NT + base + rr];
        int tok = ent & 0x7FFFFFFF;
        s_tok[r] = tok;
        s_dst[r] = (r < nrows) ? (int)((((unsigned)ent) >> 31) * NT + tok) : -1;
    }
    __syncthreads();

    int wm = wid & 1, wn = wid >> 1, lq = lane >> 2, lr = lane & 3;

    {
        int row = tid >> 2, q = tid & 3;
        const char* srch = (const char*)(g_xh + (size_t)s_tok[row] * DIN);
        uint32_t dh = smb + E1_A + (uint32_t)(row * 656);
#pragma unroll
        for (int j = 0; j < 10; j++) {
            int g = q * 10 + j;
            cp16(dh + g * 16, srch + g * 16);
        }
        cp_commit();
    }
    auto stageB = [&](int c) {
        int nc = c / 5, kc = c - nc * 5;
        uint32_t b = smb + E1_B + (uint32_t)(c % 3) * 18432;
        const char* B1 = (const char*)(g_B1 + (((size_t)(e * 5 + kc) * 512) + nc * 128) * 64);
#pragma unroll
        for (int i4 = 0; i4 < 4; i4++) {
            int idx = tid + i4 * 256;
            int r = idx >> 3, su = idx & 7;
            cp16(b + (uint32_t)(r * 144 + su * 16), B1 + r * 128 + su * 16);
        }
        cp_commit();
    };
    stageB(0);
    stageB(1);

    uint32_t abase = smb + E1_A + (uint32_t)((wm * 32 + (lane & 15)) * 656 + ((lane >> 4) << 4));
    uint32_t bbase = (uint32_t)((wn * 32 + (lane & 15)) * 144 + ((lane >> 4) << 4));

    float acc[2][4][4];
    for (int c = 0; c < 20; c++) {
        int nc = c / 5, kc = c - nc * 5;
        cp_wait1();
        __syncthreads();
        if (c + 2 < 20) stageB(c + 2); else cp_commit();

        if (kc == 0) {
#pragma unroll
            for (int mt = 0; mt < 2; mt++)
#pragma unroll
                for (int nt = 0; nt < 4; nt++)
#pragma unroll
                    for (int j = 0; j < 4; j++) acc[mt][nt][j] = 0.f;
        }
        uint32_t bb = smb + E1_B + (uint32_t)(c % 3) * 18432 + bbase;
        uint32_t ab = abase + (uint32_t)(kc * 128);
#pragma unroll
        for (int s = 0; s < 4; s++) {
            uint32_t ah[2][4], bq[2][4];
#pragma unroll
            for (int mt = 0; mt < 2; mt++)
                ldsm_x4(ah[mt], ab + (uint32_t)(mt * 10496 + s * 32));
#pragma unroll
            for (int g = 0; g < 2; g++)
                ldsm_x4(bq[g], bb + (uint32_t)(g * 2304 + s * 32));
#pragma unroll
            for (int g = 0; g < 2; g++) {
                uint32_t bhe[2] = {bq[g][0], bq[g][2]}, bho[2] = {bq[g][1], bq[g][3]};
#pragma unroll
                for (int mt = 0; mt < 2; mt++) {
                    mma_f16(acc[mt][2 * g],     ah[mt], bhe);
                    mma_f16(acc[mt][2 * g + 1], ah[mt], bho);
                }
            }
        }

        if (kc == 4) {
            const float* b1 = be1 + e * DH + nc * 128;
#pragma unroll
            for (int mt = 0; mt < 2; mt++)
#pragma unroll
                for (int nt = 0; nt < 4; nt++) {
                    int col = wn * 32 + nt * 8 + lr * 2;
                    float bb0 = b1[col], bb1 = b1[col + 1];
#pragma unroll
                    for (int h = 0; h < 2; h++) {
                        int row = wm * 32 + mt * 16 + lq + h * 8;
                        int dst = s_dst[row];
                        if (dst >= 0) {
                            float v0 = gelu_fast(acc[mt][nt][2 * h]     + bb0);
                            float v1 = gelu_fast(acc[mt][nt][2 * h + 1] + bb1);
                            __half h0 = __float2half_rn(v0), h1 = __float2half_rn(v1);
                            uint32_t ph = (uint32_t)__half_as_ushort(h0) | ((uint32_t)__half_as_ushort(h1) << 16);
                            size_t widx = ((size_t)dst * DH + nc * 128 + col) >> 1;
                            ((uint32_t*)g_heh)[widx] = ph;
                        }
                    }
                }
        }
    }
}

// ---------------- expert layer 2: M=64, 256 thr, 2 CTA/SM, atomic epilogue ---------
#define E2_A    0
#define E2_B    33792
#define E2_SMEM 89088

__global__ __launch_bounds__(256, 2) void k_expert2(const float* __restrict__ be2,
                                                    float* __restrict__ out) {
    int e = blockIdx.y;
    int cnt = g_cnt[e];
    int base = blockIdx.x * 64;
    if (base >= cnt) return;
    int nrows = min(64, cnt - base);

    extern __shared__ char smraw[];
    uint32_t smb = smem_u32(smraw);

    __shared__ int   s_row[64];
    __shared__ int   s_tk[64];
    __shared__ float s_w[64];

    int tid = threadIdx.x, wid = tid >> 5, lane = tid & 31;
    if (tid < 64) {
        int r = tid;
        int rr = (r < nrows) ? r : 0;
        int ent = g_tok[e * NT + base + rr];
        int tok = ent & 0x7FFFFFFF;
        s_row[r] = (int)((((unsigned)ent) >> 31) * NT + tok);
        s_tk[r]  = (r < nrows) ? tok : -1;
        s_w[r]   = g_w[e * NT + base + rr];
    }
    __syncthreads();

    int wm = wid & 1, wn = wid >> 1, lq = lane >> 2, lr = lane & 3;

    uint32_t abase = smb + E2_A + (uint32_t)((wm * 32 + (lane & 15)) * 528 + ((lane >> 4) << 4));
    uint32_t bbase = (uint32_t)((wn * 32 + (lane & 15)) * 144 + ((lane >> 4) << 4));

    auto stageB = [&](int cgl) {
        int j = cgl & 7, kh = cgl >> 3;
        int nc = j >> 2, kcl = j & 3;
        int kc = kh * 4 + kcl;
        uint32_t b = smb + E2_B + (uint32_t)(cgl % 3) * 18432;
        const char* B2 = (const char*)(g_B2 + (((size_t)(e * 8 + kc) * 256) + nc * 128) * 64);
#pragma unroll
        for (int i4 = 0; i4 < 4; i4++) {
            int idx = tid + i4 * 256;
            int r = idx >> 3, su = idx & 7;
            cp16(b + (uint32_t)(r * 144 + su * 16), B2 + r * 128 + su * 16);
        }
        cp_commit();
    };

    float acc[2][2][4][4];
#pragma unroll
    for (int nc = 0; nc < 2; nc++)
#pragma unroll
        for (int mt = 0; mt < 2; mt++)
#pragma unroll
            for (int nt = 0; nt < 4; nt++)
#pragma unroll
                for (int j = 0; j < 4; j++) acc[nc][mt][nt][j] = 0.f;

    for (int kh = 0; kh < 2; kh++) {
        __syncthreads();
        {
            int row = tid >> 2, q = tid & 3;
            const char* srch = (const char*)(g_heh + (size_t)s_row[row] * DH + kh * 256);
            uint32_t dh = smb + E2_A + (uint32_t)(row * 528);
#pragma unroll
            for (int j = 0; j < 8; j++) {
                int g = q * 8 + j;
                cp16(dh + g * 16, srch + g * 16);
            }
            cp_commit();
        }
        stageB(kh * 8);
        stageB(kh * 8 + 1);

        for (int j = 0; j < 8; j++) {
            int cgl = kh * 8 + j;
            int nc = j >> 2, kcl = j & 3;
            cp_wait1();
            __syncthreads();
            if (j + 2 < 8) stageB(cgl + 2); else cp_commit();

            uint32_t bb = smb + E2_B + (uint32_t)(cgl % 3) * 18432 + bbase;
            uint32_t ab = abase + (uint32_t)(kcl * 128);
#pragma unroll
            for (int s = 0; s < 4; s++) {
                uint32_t ah[2][4], bq[2][4];
#pragma unroll
                for (int mt = 0; mt < 2; mt++)
                    ldsm_x4(ah[mt], ab + (uint32_t)(mt * 8448 + s * 32));
#pragma unroll
                for (int g = 0; g < 2; g++)
                    ldsm_x4(bq[g], bb + (uint32_t)(g * 2304 + s * 32));
#pragma unroll
                for (int g = 0; g < 2; g++) {
                    uint32_t bhe[2] = {bq[g][0], bq[g][2]}, bho[2] = {bq[g][1], bq[g][3]};
#pragma unroll
                    for (int mt = 0; mt < 2; mt++) {
                        mma_f16(acc[nc][mt][2 * g],     ah[mt], bhe);
                        mma_f16(acc[nc][mt][2 * g + 1], ah[mt], bho);
                    }
                }
            }
        }
    }

    // epilogue: gate-scaled bias add, atomicAdd into out (exactly 2 adds/elem)
#pragma unroll
    for (int nc = 0; nc < 2; nc++) {
        const float* b2 = be2 + e * DD + nc * 128;
#pragma unroll
        for (int mt = 0; mt < 2; mt++)
#pragma unroll
            for (int nt = 0; nt < 4; nt++) {
                int col = wn * 32 + nt * 8 + lr * 2;
                float bb0 = b2[col], bb1 = b2[col + 1];
#pragma unroll
                for (int h = 0; h < 2; h++) {
                    int row = wm * 32 + mt * 16 + lq + h * 8;
                    int tk = s_tk[row];
                    if (tk >= 0) {
                        float wgt = s_w[row];
                        float* dst = out + (size_t)tk * DD + nc * 128 + col;
                        atomicAdd(dst,     wgt * (acc[nc][mt][nt][2 * h]     + bb0));
                        atomicAdd(dst + 1, wgt * (acc[nc][mt][nt][2 * h + 1] + bb1));
                    }
                }
            }
    }
}

// ---------------- launch ----------------
extern "C" void kernel_launch(void* const* d_in, const int* in_sizes, int n_in,
                              void* d_out, int out_size) {
    const float* hidden = (const float*)d_in[0];
    const float* feat   = (const float*)d_in[1];
    const float* Wf     = (const float*)d_in[2];
    const float* bf     = (const float*)d_in[3];
    const float* Wr1    = (const float*)d_in[4];
    const float* br1    = (const float*)d_in[5];
    const float* Wr2    = (const float*)d_in[6];
    const float* br2    = (const float*)d_in[7];
    const float* We1    = (const float*)d_in[8];
    const float* be1    = (const float*)d_in[9];
    const float* We2    = (const float*)d_in[10];
    const float* be2    = (const float*)d_in[11];
    float* out = (float*)d_out;

    cudaFuncSetAttribute(k_router_mma, cudaFuncAttributeMaxDynamicSharedMemorySize, RT_SMEM);
    cudaFuncSetAttribute(k_expert1, cudaFuncAttributeMaxDynamicSharedMemorySize, E1_SMEM);
    cudaFuncSetAttribute(k_expert2, cudaFuncAttributeMaxDynamicSharedMemorySize, E2_SMEM);

    k_zero<<<(NT * DD / 4) / 256, 256>>>(out);
    k_build_x<<<NT, DIN>>>(hidden, feat, Wf, bf);
    k_prep<<<596, 256>>>(We1, We2, Wr1);
    k_router_mma<<<NT / 64, 256, RT_SMEM>>>(br1, Wr2, br2, out);
    k_expert1<<<dim3(128, EE), 256, E1_SMEM>>>(be1);
    k_expert2<<<dim3(128, EE), 256, E2_SMEM>>>(be2, out);
}

// round 14
// speedup vs baseline: 2.3481x; 1.0408x over previous
#include <cuda_runtime.h>
#include <cuda_fp16.h>
#include <math.h>
#include <stdint.h>

#define NT   8192
#define DD   256
#define FF   8
#define DFE  64
#define DIN  320
#define DR   256
#define EE   8
#define DH   512

// ---------------- device-global scratch ----------------
__device__ int                 g_cnt[EE];
__device__ int                 g_tok[EE * NT];
__device__ float               g_w[EE * NT];
__device__ __align__(16) __half g_xh[NT * DIN];     // fp16 hi of x
__device__ __align__(16) __half g_xl[NT * DIN];     // fp16 lo of x
__device__ __align__(16) __half g_heh[2 * NT * DH]; // fp16 he
// pre-transposed n-major fp16 weights
__device__ __align__(16) __half g_B1[EE * 5 * 512 * 64];   // [e][kc=5][n=512][k=64]
__device__ __align__(16) __half g_B2[EE * 8 * 256 * 64];   // [e][kc=8][n=256][k=64]
__device__ __align__(16) __half g_R1h[5 * 256 * 64];       // Wr1 hi [kc=5][n=256][k=64]
__device__ __align__(16) __half g_R1l[5 * 256 * 64];       // Wr1 lo

// ---------------- helpers ----------------
__device__ __forceinline__ float gelu_tanh(float v) {
    float u = 0.7978845608028654f * (v + 0.044715f * v * v * v);
    return 0.5f * v * (1.0f + tanhf(u));
}
__device__ __forceinline__ float gelu_fast(float v) {
    float u = 0.7978845608028654f * (v + 0.044715f * v * v * v);
    return v / (1.0f + __expf(-2.0f * u));
}
__device__ __forceinline__ uint32_t smem_u32(const void* p) {
    uint32_t a;
    asm("{ .reg .u64 t; cvta.to.shared.u64 t, %1; cvt.u32.u64 %0, t; }" : "=r"(a) : "l"(p));
    return a;
}
__device__ __forceinline__ void mma_f16(float* d, const uint32_t* a, const uint32_t* b) {
    asm volatile(
        "mma.sync.aligned.m16n8k16.row.col.f32.f16.f16.f32 "
        "{%0,%1,%2,%3}, {%4,%5,%6,%7}, {%8,%9}, {%0,%1,%2,%3};"
        : "+f"(d[0]), "+f"(d[1]), "+f"(d[2]), "+f"(d[3])
        : "r"(a[0]), "r"(a[1]), "r"(a[2]), "r"(a[3]), "r"(b[0]), "r"(b[1]));
}
__device__ __forceinline__ void ldsm_x4(uint32_t* r, uint32_t a) {
    asm volatile("ldmatrix.sync.aligned.m8n8.x4.shared.b16 {%0,%1,%2,%3}, [%4];"
        : "=r"(r[0]), "=r"(r[1]), "=r"(r[2]), "=r"(r[3]) : "r"(a));
}
__device__ __forceinline__ void cp16(uint32_t dst, const void* src) {
    asm volatile("cp.async.cg.shared.global [%0], [%1], 16;" :: "r"(dst), "l"(src));
}
__device__ __forceinline__ void cp_commit() {
    asm volatile("cp.async.commit_group;" ::: "memory");
}
__device__ __forceinline__ void cp_wait1() {
    asm volatile("cp.async.wait_group 1;" ::: "memory");
}

// ---------------- K1: build x (fp16 hi/lo) + zero out + counter reset ----------------
__global__ void k_build_x(const float* __restrict__ hidden,
                          const float* __restrict__ feat,
                          const float* __restrict__ Wf,
                          const float* __restrict__ bf,
                          float* __restrict__ out) {
    int tok = blockIdx.x;
    int t = threadIdx.x;
    if (blockIdx.x == 0 && t < EE) g_cnt[t] = 0;
    float v;
    if (t < DD) {
        v = hidden[tok * DD + t];
        out[(size_t)tok * DD + t] = 0.f;   // zero stage_delta region
    } else {
        int j = t - DD;
        float acc = bf[j];
#pragma unroll
        for (int k = 0; k < FF; k++) acc += feat[tok * FF + k] * Wf[k * DFE + j];
        v = acc;
    }
    __half h = __float2half_rn(v);
    g_xh[tok * DIN + t] = h;
    g_xl[tok * DIN + t] = __float2half_rn(v - __half2float(h));
}

// ---------------- K2: weight prep (transpose to n-major fp16; Wr1 hi/lo) ------------
__global__ void k_prep(const float* __restrict__ We1, const float* __restrict__ We2,
                       const float* __restrict__ Wr1) {
    __shared__ float tile[64][65];
    int bx = blockIdx.x;
    int tid = threadIdx.x;
    if (bx < 320) {
        int hb = bx & 7, kc = (bx >> 3) % 5, e = bx / 40;
#pragma unroll
        for (int i = 0; i < 16; i++) {
            int li = i * 256 + tid;
            int ki = li >> 6, hi = li & 63;
            tile[ki][hi] = We1[((size_t)e * DIN + kc * 64 + ki) * DH + hb * 64 + hi];
        }
        __syncthreads();
#pragma unroll
        for (int i = 0; i < 16; i++) {
            int li = i * 256 + tid;
            int kk = li & 63, hr = li >> 6;
            size_t dst = (((size_t)(e * 5 + kc) * 512) + hb * 64 + hr) * 64 + kk;
            g_B1[dst] = __float2half_rn(tile[kk][hr]);
        }
    } else if (bx < 576) {
        int b2 = bx - 320;
        int ob = b2 & 3, kc = (b2 >> 2) & 7, e = b2 >> 5;
#pragma unroll
        for (int i = 0; i < 16; i++) {
            int li = i * 256 + tid;
            int ki = li >> 6, oi = li & 63;
            tile[ki][oi] = We2[((size_t)e * DH + kc * 64 + ki) * DD + ob * 64 + oi];
        }
        __syncthreads();
#pragma unroll
        for (int i = 0; i < 16; i++) {
            int li = i * 256 + tid;
            int kk = li & 63, orr = li >> 6;
            size_t dst = (((size_t)(e * 8 + kc) * 256) + ob * 64 + orr) * 64 + kk;
            g_B2[dst] = __float2half_rn(tile[kk][orr]);
        }
    } else {
        int b3 = bx - 576;          // 20 blocks: nb(4) x kc(5)
        int nb = b3 & 3, kc = b3 >> 2;
#pragma unroll
        for (int i = 0; i < 16; i++) {
            int li = i * 256 + tid;
            int ki = li >> 6, ni = li & 63;
            tile[ki][ni] = Wr1[(kc * 64 + ki) * DR + nb * 64 + ni];
        }
        __syncthreads();
#pragma unroll
        for (int i = 0; i < 16; i++) {
            int li = i * 256 + tid;
            int kk = li & 63, nr = li >> 6;
            float v = tile[kk][nr];
            __half h = __float2half_rn(v);
            __half l = __float2half_rn(v - __half2float(h));
            size_t dst = ((size_t)kc * 256 + nb * 64 + nr) * 64 + kk;
            g_R1h[dst] = h;
            g_R1l[dst] = l;
        }
    }
}

// ---------------- K3: router — 512 threads, HMMA 3-term GEMM1, fp32 GEMM2 ----------
// smem: Ah [0,41984) 64x656B ; Al [41984,83968) ; B 3 x 36864 (hi + lo) at 83968
// overlay after GEMM1: hr 64x264 f32 [0,67584); lg @f16896; ws2T @f17408 (8x260)
#define RT_AL   41984
#define RT_B    83968
#define RT_SMEM (83968 + 3 * 36864)

__global__ __launch_bounds__(512, 1) void k_router_mma(
    const float* __restrict__ br1,
    const float* __restrict__ Wr2, const float* __restrict__ br2,
    float* __restrict__ out) {
    extern __shared__ char smraw[];
    uint32_t smb = smem_u32(smraw);
    float* smf = (float*)smraw;

    int tid = threadIdx.x, wid = tid >> 5, lane = tid & 31;
    int base = blockIdx.x * 64;
    int wm = wid & 1, wn = wid >> 1, lq = lane >> 2, lr = lane & 3;

    // stage A: x hi/lo for 64 tokens
    {
        int row = tid >> 3, oct = tid & 7;
        const char* sh = (const char*)(g_xh + (size_t)(base + row) * DIN);
        const char* sl = (const char*)(g_xl + (size_t)(base + row) * DIN);
        uint32_t dh = smb + (uint32_t)(row * 656);
        uint32_t dl = smb + RT_AL + (uint32_t)(row * 656);
#pragma unroll
        for (int j = 0; j < 5; j++) {
            int g = oct * 5 + j;
            cp16(dh + g * 16, sh + g * 16);
            cp16(dl + g * 16, sl + g * 16);
        }
        cp_commit();
    }
    auto stageB = [&](int c) {
        int kc = c >> 1, nc = c & 1;
        uint32_t b = smb + RT_B + (uint32_t)(c % 3) * 36864;
        const char* Bh = (const char*)(g_R1h + ((size_t)kc * 256 + nc * 128) * 64);
        const char* Bl = (const char*)(g_R1l + ((size_t)kc * 256 + nc * 128) * 64);
#pragma unroll
        for (int i4 = 0; i4 < 2; i4++) {
            int idx = tid + i4 * 512;
            int r = idx >> 3, su = idx & 7;
            cp16(b + (uint32_t)(r * 144 + su * 16), Bh + r * 128 + su * 16);
            cp16(b + 18432 + (uint32_t)(r * 144 + su * 16), Bl + r * 128 + su * 16);
        }
        cp_commit();
    };
    stageB(0);
    stageB(1);

    uint32_t abase = smb + (uint32_t)((wm * 32 + (lane & 15)) * 656 + ((lane >> 4) << 4));
    uint32_t bbase = (uint32_t)((wn * 16 + (lane & 15)) * 144 + ((lane >> 4) << 4));

    float acc[2][2][2][4];   // [nc][mt][nh][j]
#pragma unroll
    for (int nc = 0; nc < 2; nc++)
#pragma unroll
        for (int mt = 0; mt < 2; mt++)
#pragma unroll
            for (int nh = 0; nh < 2; nh++)
#pragma unroll
                for (int j = 0; j < 4; j++) acc[nc][mt][nh][j] = 0.f;

    for (int c = 0; c < 10; c++) {
        int kc = c >> 1, nc = c & 1;
        cp_wait1();
        __syncthreads();
        if (c + 2 < 10) stageB(c + 2); else cp_commit();

        uint32_t bb = smb + RT_B + (uint32_t)(c % 3) * 36864 + bbase;
        uint32_t ab = abase + (uint32_t)(kc * 128);
#pragma unroll
        for (int s = 0; s < 4; s++) {
            uint32_t ah[2][4], al[2][4], bh[4], bl[4];
#pragma unroll
            for (int mt = 0; mt < 2; mt++) {
                uint32_t a = ab + (uint32_t)(mt * 10496 + s * 32);
                ldsm_x4(ah[mt], a);
                ldsm_x4(al[mt], a + RT_AL);
            }
            {
                uint32_t bo = bb + (uint32_t)(s * 32);
                ldsm_x4(bh, bo);
                ldsm_x4(bl, bo + 18432);
            }
            uint32_t bhe[2] = {bh[0], bh[2]}, bho[2] = {bh[1], bh[3]};
            uint32_t ble[2] = {bl[0], bl[2]}, blo[2] = {bl[1], bl[3]};
#pragma unroll
            for (int mt = 0; mt < 2; mt++) {
                mma_f16(acc[nc][mt][0], ah[mt], bhe);
                mma_f16(acc[nc][mt][0], ah[mt], ble);
                mma_f16(acc[nc][mt][0], al[mt], bhe);
                mma_f16(acc[nc][mt][1], ah[mt], bho);
                mma_f16(acc[nc][mt][1], ah[mt], blo);
                mma_f16(acc[nc][mt][1], al[mt], bho);
            }
        }
    }
    __syncthreads();   // all MMAs done; A region reusable

    // GEMM1 epilogue: hr = gelu(acc + br1) -> smem hr[64][264]
#pragma unroll
    for (int nc = 0; nc < 2; nc++)
#pragma unroll
        for (int mt = 0; mt < 2; mt++)
#pragma unroll
            for (int nh = 0; nh < 2; nh++) {
                int col = nc * 128 + wn * 16 + nh * 8 + lr * 2;
                float b0 = br1[col], b1 = br1[col + 1];
#pragma unroll
                for (int h = 0; h < 2; h++) {
                    int row = wm * 32 + mt * 16 + lq + h * 8;
                    smf[row * 264 + col]     = gelu_tanh(acc[nc][mt][nh][2 * h]     + b0);
                    smf[row * 264 + col + 1] = gelu_tanh(acc[nc][mt][nh][2 * h + 1] + b1);
                }
            }
    // stage Wr2 transposed: ws2T[e][k] at float offset 17408, row stride 260
#pragma unroll
    for (int i = 0; i < 4; i++) {
        int idx = tid + i * 512;
        int k = idx >> 3, e = idx & 7;
        smf[17408 + e * 260 + k] = Wr2[k * EE + e];
    }
    __syncthreads();

    // GEMM2: logits (fp32, exact) — one (token, expert) pair per thread
    {
        int e = tid & 7, t0 = tid >> 3;
        float a0 = br2[e];
        const float* hr0 = smf + t0 * 264;
        const float* w2  = smf + 17408 + e * 260;
#pragma unroll 8
        for (int k = 0; k < DR; k += 4) {
            float4 w  = *(const float4*)(w2 + k);
            float4 h0 = *(const float4*)(hr0 + k);
            a0 += h0.x * w.x + h0.y * w.y + h0.z * w.z + h0.w * w.w;
        }
        smf[16896 + t0 * 8 + e] = a0;
        float* lo = out + (size_t)NT * DD + (size_t)NT * EE;
        lo[(size_t)(base + t0) * EE + e] = a0;
    }
    __syncthreads();

    // top-2 gating (64 tokens)
    if (tid < 64) {
        int gtok = base + tid;
        float v[EE];
#pragma unroll
        for (int e = 0; e < EE; e++) v[e] = smf[16896 + tid * 8 + e];
        int i0 = 0;
#pragma unroll
        for (int e = 1; e < EE; e++)
            if (v[e] > v[i0]) i0 = e;
        int i1 = (i0 == 0) ? 1 : 0;
#pragma unroll
        for (int e = 0; e < EE; e++) {
            if (e == i0) continue;
            if (v[e] > v[i1]) i1 = e;
        }
        float t  = expf(v[i1] - v[i0]);
        float s  = 1.0f + t;
        float w0 = 1.0f / s;
        float w1 = t / s;
        float* gw = out + (size_t)NT * DD + (size_t)gtok * EE;
#pragma unroll
        for (int e = 0; e < EE; e++)
            gw[e] = (e == i0) ? w0 : ((e == i1) ? w1 : 0.0f);
        int p0 = atomicAdd(&g_cnt[i0], 1);
        g_tok[i0 * NT + p0] = gtok;
        g_w[i0 * NT + p0]   = w0;
        int p1 = atomicAdd(&g_cnt[i1], 1);
        g_tok[i1 * NT + p1] = gtok | (1 << 31);
        g_w[i1 * NT + p1]   = w1;
    }
}

// ---------------- expert layer 1: M=64, 256 thr, 2 CTA/SM, A resident ---------------
#define E1_A    0
#define E1_B    41984
#define E1_SMEM 97280

__global__ __launch_bounds__(256, 2) void k_expert1(const float* __restrict__ be1) {
    int e = blockIdx.y;
    int cnt = g_cnt[e];
    int base = blockIdx.x * 64;
    if (base >= cnt) return;
    int nrows = min(64, cnt - base);

    extern __shared__ char smraw[];
    uint32_t smb = smem_u32(smraw);

    __shared__ int s_tok[64];
    __shared__ int s_dst[64];

    int tid = threadIdx.x, wid = tid >> 5, lane = tid & 31;
    if (tid < 64) {
        int r = tid;
        int rr = (r < nrows) ? r : 0;
        int ent = g_tok[e * NT + base + rr];
        int tok = ent & 0x7FFFFFFF;
        s_tok[r] = tok;
        s_dst[r] = (r < nrows) ? (int)((((unsigned)ent) >> 31) * NT + tok) : -1;
    }
    __syncthreads();

    int wm = wid & 1, wn = wid >> 1, lq = lane >> 2, lr = lane & 3;

    {
        int row = tid >> 2, q = tid & 3;
        const char* srch = (const char*)(g_xh + (size_t)s_tok[row] * DIN);
        uint32_t dh = smb + E1_A + (uint32_t)(row * 656);
#pragma unroll
        for (int j = 0; j < 10; j++) {
            int g = q * 10 + j;
            cp16(dh + g * 16, srch + g * 16);
        }
        cp_commit();
    }
    auto stageB = [&](int c) {
        int nc = c / 5, kc = c - nc * 5;
        uint32_t b = smb + E1_B + (uint32_t)(c % 3) * 18432;
        const char* B1 = (const char*)(g_B1 + (((size_t)(e * 5 + kc) * 512) + nc * 128) * 64);
#pragma unroll
        for (int i4 = 0; i4 < 4; i4++) {
            int idx = tid + i4 * 256;
            int r = idx >> 3, su = idx & 7;
            cp16(b + (uint32_t)(r * 144 + su * 16), B1 + r * 128 + su * 16);
        }
        cp_commit();
    };
    stageB(0);
    stageB(1);

    uint32_t abase = smb + E1_A + (uint32_t)((wm * 32 + (lane & 15)) * 656 + ((lane >> 4) << 4));
    uint32_t bbase = (uint32_t)((wn * 32 + (lane & 15)) * 144 + ((lane >> 4) << 4));

    float acc[2][4][4];
    for (int c = 0; c < 20; c++) {
        int nc = c / 5, kc = c - nc * 5;
        cp_wait1();
        __syncthreads();
        if (c + 2 < 20) stageB(c + 2); else cp_commit();

        if (kc == 0) {
#pragma unroll
            for (int mt = 0; mt < 2; mt++)
#pragma unroll
                for (int nt = 0; nt < 4; nt++)
#pragma unroll
                    for (int j = 0; j < 4; j++) acc[mt][nt][j] = 0.f;
        }
        uint32_t bb = smb + E1_B + (uint32_t)(c % 3) * 18432 + bbase;
        uint32_t ab = abase + (uint32_t)(kc * 128);
#pragma unroll
        for (int s = 0; s < 4; s++) {
            uint32_t ah[2][4], bq[2][4];
#pragma unroll
            for (int mt = 0; mt < 2; mt++)
                ldsm_x4(ah[mt], ab + (uint32_t)(mt * 10496 + s * 32));
#pragma unroll
            for (int g = 0; g < 2; g++)
                ldsm_x4(bq[g], bb + (uint32_t)(g * 2304 + s * 32));
#pragma unroll
            for (int g = 0; g < 2; g++) {
                uint32_t bhe[2] = {bq[g][0], bq[g][2]}, bho[2] = {bq[g][1], bq[g][3]};
#pragma unroll
                for (int mt = 0; mt < 2; mt++) {
                    mma_f16(acc[mt][2 * g],     ah[mt], bhe);
                    mma_f16(acc[mt][2 * g + 1], ah[mt], bho);
                }
            }
        }

        if (kc == 4) {
            const float* b1 = be1 + e * DH + nc * 128;
#pragma unroll
            for (int mt = 0; mt < 2; mt++)
#pragma unroll
                for (int nt = 0; nt < 4; nt++) {
                    int col = wn * 32 + nt * 8 + lr * 2;
                    float bb0 = b1[col], bb1 = b1[col + 1];
#pragma unroll
                    for (int h = 0; h < 2; h++) {
                        int row = wm * 32 + mt * 16 + lq + h * 8;
                        int dst = s_dst[row];
                        if (dst >= 0) {
                            float v0 = gelu_fast(acc[mt][nt][2 * h]     + bb0);
                            float v1 = gelu_fast(acc[mt][nt][2 * h + 1] + bb1);
                            __half h0 = __float2half_rn(v0), h1 = __float2half_rn(v1);
                            uint32_t ph = (uint32_t)__half_as_ushort(h0) | ((uint32_t)__half_as_ushort(h1) << 16);
                            size_t widx = ((size_t)dst * DH + nc * 128 + col) >> 1;
                            ((uint32_t*)g_heh)[widx] = ph;
                        }
                    }
                }
        }
    }
}

// ---------------- expert layer 2: M=64, 256 thr, 2 CTA/SM, atomic epilogue ---------
#define E2_A    0
#define E2_B    33792
#define E2_SMEM 89088

__global__ __launch_bounds__(256, 2) void k_expert2(const float* __restrict__ be2,
                                                    float* __restrict__ out) {
    int e = blockIdx.y;
    int cnt = g_cnt[e];
    int base = blockIdx.x * 64;
    if (base >= cnt) return;
    int nrows = min(64, cnt - base);

    extern __shared__ char smraw[];
    uint32_t smb = smem_u32(smraw);

    __shared__ int   s_row[64];
    __shared__ int   s_tk[64];
    __shared__ float s_w[64];

    int tid = threadIdx.x, wid = tid >> 5, lane = tid & 31;
    if (tid < 64) {
        int r = tid;
        int rr = (r < nrows) ? r : 0;
        int ent = g_tok[e * NT + base + rr];
        int tok = ent & 0x7FFFFFFF;
        s_row[r] = (int)((((unsigned)ent) >> 31) * NT + tok);
        s_tk[r]  = (r < nrows) ? tok : -1;
        s_w[r]   = g_w[e * NT + base + rr];
    }
    __syncthreads();

    int wm = wid & 1, wn = wid >> 1, lq = lane >> 2, lr = lane & 3;

    uint32_t abase = smb + E2_A + (uint32_t)((wm * 32 + (lane & 15)) * 528 + ((lane >> 4) << 4));
    uint32_t bbase = (uint32_t)((wn * 32 + (lane & 15)) * 144 + ((lane >> 4) << 4));

    auto stageB = [&](int cgl) {
        int j = cgl & 7, kh = cgl >> 3;
        int nc = j >> 2, kcl = j & 3;
        int kc = kh * 4 + kcl;
        uint32_t b = smb + E2_B + (uint32_t)(cgl % 3) * 18432;
        const char* B2 = (const char*)(g_B2 + (((size_t)(e * 8 + kc) * 256) + nc * 128) * 64);
#pragma unroll
        for (int i4 = 0; i4 < 4; i4++) {
            int idx = tid + i4 * 256;
            int r = idx >> 3, su = idx & 7;
            cp16(b + (uint32_t)(r * 144 + su * 16), B2 + r * 128 + su * 16);
        }
        cp_commit();
    };

    float acc[2][2][4][4];
#pragma unroll
    for (int nc = 0; nc < 2; nc++)
#pragma unroll
        for (int mt = 0; mt < 2; mt++)
#pragma unroll
            for (int nt = 0; nt < 4; nt++)
#pragma unroll
                for (int j = 0; j < 4; j++) acc[nc][mt][nt][j] = 0.f;

    for (int kh = 0; kh < 2; kh++) {
        __syncthreads();
        {
            int row = tid >> 2, q = tid & 3;
            const char* srch = (const char*)(g_heh + (size_t)s_row[row] * DH + kh * 256);
            uint32_t dh = smb + E2_A + (uint32_t)(row * 528);
#pragma unroll
            for (int j = 0; j < 8; j++) {
                int g = q * 8 + j;
                cp16(dh + g * 16, srch + g * 16);
            }
            cp_commit();
        }
        stageB(kh * 8);
        stageB(kh * 8 + 1);

        for (int j = 0; j < 8; j++) {
            int cgl = kh * 8 + j;
            int nc = j >> 2, kcl = j & 3;
            cp_wait1();
            __syncthreads();
            if (j + 2 < 8) stageB(cgl + 2); else cp_commit();

            uint32_t bb = smb + E2_B + (uint32_t)(cgl % 3) * 18432 + bbase;
            uint32_t ab = abase + (uint32_t)(kcl * 128);
#pragma unroll
            for (int s = 0; s < 4; s++) {
                uint32_t ah[2][4], bq[2][4];
#pragma unroll
                for (int mt = 0; mt < 2; mt++)
                    ldsm_x4(ah[mt], ab + (uint32_t)(mt * 8448 + s * 32));
#pragma unroll
                for (int g = 0; g < 2; g++)
                    ldsm_x4(bq[g], bb + (uint32_t)(g * 2304 + s * 32));
#pragma unroll
                for (int g = 0; g < 2; g++) {
                    uint32_t bhe[2] = {bq[g][0], bq[g][2]}, bho[2] = {bq[g][1], bq[g][3]};
#pragma unroll
                    for (int mt = 0; mt < 2; mt++) {
                        mma_f16(acc[nc][mt][2 * g],     ah[mt], bhe);
                        mma_f16(acc[nc][mt][2 * g + 1], ah[mt], bho);
                    }
                }
            }
        }
    }

    // epilogue: gate-scaled bias add, atomicAdd into out (exactly 2 adds/elem)
#pragma unroll
    for (int nc = 0; nc < 2; nc++) {
        const float* b2 = be2 + e * DD + nc * 128;
#pragma unroll
        for (int mt = 0; mt < 2; mt++)
#pragma unroll
            for (int nt = 0; nt < 4; nt++) {
                int col = wn * 32 + nt * 8 + lr * 2;
                float bb0 = b2[col], bb1 = b2[col + 1];
#pragma unroll
                for (int h = 0; h < 2; h++) {
                    int row = wm * 32 + mt * 16 + lq + h * 8;
                    int tk = s_tk[row];
                    if (tk >= 0) {
                        float wgt = s_w[row];
                        float* dst = out + (size_t)tk * DD + nc * 128 + col;
                        atomicAdd(dst,     wgt * (acc[nc][mt][nt][2 * h]     + bb0));
                        atomicAdd(dst + 1, wgt * (acc[nc][mt][nt][2 * h + 1] + bb1));
                    }
                }
            }
    }
}

// ---------------- launch ----------------
extern "C" void kernel_launch(void* const* d_in, const int* in_sizes, int n_in,
                              void* d_out, int out_size) {
    const float* hidden = (const float*)d_in[0];
    const float* feat   = (const float*)d_in[1];
    const float* Wf     = (const float*)d_in[2];
    const float* bf     = (const float*)d_in[3];
    const float* Wr1    = (const float*)d_in[4];
    const float* br1    = (const float*)d_in[5];
    const float* Wr2    = (const float*)d_in[6];
    const float* br2    = (const float*)d_in[7];
    const float* We1    = (const float*)d_in[8];
    const float* be1    = (const float*)d_in[9];
    const float* We2    = (const float*)d_in[10];
    const float* be2    = (const float*)d_in[11];
    float* out = (float*)d_out;

    cudaFuncSetAttribute(k_router_mma, cudaFuncAttributeMaxDynamicSharedMemorySize, RT_SMEM);
    cudaFuncSetAttribute(k_expert1, cudaFuncAttributeMaxDynamicSharedMemorySize, E1_SMEM);
    cudaFuncSetAttribute(k_expert2, cudaFuncAttributeMaxDynamicSharedMemorySize, E2_SMEM);

    k_build_x<<<NT, DIN>>>(hidden, feat, Wf, bf, out);
    k_prep<<<596, 256>>>(We1, We2, Wr1);
    k_router_mma<<<NT / 64, 512, RT_SMEM>>>(br1, Wr2, br2, out);
    k_expert1<<<dim3(128, EE), 256, E1_SMEM>>>(be1);
    k_expert2<<<dim3(128, EE), 256, E2_SMEM>>>(be2, out);
}